// round 2
// baseline (speedup 1.0000x reference)
#include <cuda_runtime.h>
#include <math.h>

#define NNODES 1024
#define BATCH 32
#define HID 64
#define OUTD 2
#define STEPS 12
#define NROWS (BATCH*NNODES)   // 32768

// ---------------- scratch (static device allocations; no cudaMalloc) ------
__device__ float g_M[2*NNODES*NNODES];          // M_s = 2*S_s@S_s - I
__device__ float g_state0[NROWS*HID];
__device__ float g_state1[NROWS*HID];
__device__ float g_decin [NROWS*OUTD];
__device__ float g_u     [NROWS*HID];
__device__ float g_rstate[NROWS*HID];
__device__ float g_Fru[NROWS*5*128];            // features [b,n,m,c], Ctot<=128
__device__ float g_Fh [NROWS*5*128];

// ---------------- init: states <- encoder_state, decin <- 0 ---------------
__global__ void initK(const float* __restrict__ enc) {
    int idx = blockIdx.x*blockDim.x + threadIdx.x;
    const int SZ = NROWS*HID;
    if (idx < SZ) { g_state0[idx] = enc[idx]; g_state1[idx] = enc[SZ+idx]; }
    if (idx < NROWS*OUTD) g_decin[idx] = 0.f;
}

// ---------------- M_s = 2*S_s@S_s - I  (1024^3 GEMM, z = s) ----------------
__global__ void precomputeM(const float* __restrict__ supports) {
    const int s = blockIdx.z;
    const float* __restrict__ S = supports + s*NNODES*NNODES;
    float* __restrict__ Mo = g_M + s*NNODES*NNODES;
    __shared__ float As[16][64];
    __shared__ float Bs[16][64];
    const int tid = threadIdx.x;
    const int tx = tid & 15, ty = tid >> 4;
    const int n0 = blockIdx.y * 64;
    const int j0 = blockIdx.x * 64;
    const int arow = tid >> 2, aq = (tid & 3) * 4;
    const int brow = tid >> 4, bq = (tid & 15) * 4;
    float acc[4][4] = {};
    for (int kt = 0; kt < NNODES; kt += 16) {
        float4 av = *(const float4*)(S + (size_t)(n0+arow)*NNODES + kt + aq);
        As[aq+0][arow] = av.x; As[aq+1][arow] = av.y;
        As[aq+2][arow] = av.z; As[aq+3][arow] = av.w;
        float4 bv = *(const float4*)(S + (size_t)(kt+brow)*NNODES + j0 + bq);
        *(float4*)&Bs[brow][bq] = bv;
        __syncthreads();
        #pragma unroll
        for (int k = 0; k < 16; k++) {
            float4 a = *(float4*)&As[k][ty*4];
            float4 b = *(float4*)&Bs[k][tx*4];
            float ar[4] = {a.x,a.y,a.z,a.w};
            float br[4] = {b.x,b.y,b.z,b.w};
            #pragma unroll
            for (int i = 0; i < 4; i++)
                #pragma unroll
                for (int j = 0; j < 4; j++) acc[i][j] += ar[i]*br[j];
        }
        __syncthreads();
    }
    #pragma unroll
    for (int i = 0; i < 4; i++) {
        int n = n0 + ty*4 + i;
        #pragma unroll
        for (int j = 0; j < 4; j++) {
            int jc = j0 + tx*4 + j;
            Mo[(size_t)n*NNODES + jc] = 2.f*acc[i][j] - (n == jc ? 1.f : 0.f);
        }
    }
}

// ---------------- diffusion: Y_f = Op_f @ Xmat, f in {S0,M0,S1,M1} ---------
// Xmat[k, j] = X[b(j), k, c(j)], j in [0, B*C). Writes F[b,n,f+1, colOff+c].
template<int C>
__global__ void diffuseK(const float* __restrict__ X, float* __restrict__ F,
                         int Ctot, int colOff, const float* __restrict__ supports) {
    const int f = blockIdx.z;
    const float* __restrict__ Op =
        (f == 0) ? supports :
        (f == 1) ? g_M :
        (f == 2) ? supports + NNODES*NNODES : g_M + NNODES*NNODES;
    const int NC = BATCH * C;
    __shared__ float As[16][64];
    __shared__ float Bs[16][64];
    const int tid = threadIdx.x;
    const int tx = tid & 15, ty = tid >> 4;
    const int n0 = blockIdx.y * 64;
    const int j0 = blockIdx.x * 64;
    const int arow = tid >> 2, aq = (tid & 3) * 4;
    const int brow = tid >> 4, bq = (tid & 15) * 4;
    float acc[4][4] = {};
    for (int kt = 0; kt < NNODES; kt += 16) {
        float4 av = *(const float4*)(Op + (size_t)(n0+arow)*NNODES + kt + aq);
        As[aq+0][arow] = av.x; As[aq+1][arow] = av.y;
        As[aq+2][arow] = av.z; As[aq+3][arow] = av.w;
        if ((C & 3) == 0) {
            int j = j0 + bq;
            if (j < NC) {
                int b = j / C, c = j % C;   // C=64: b constant across the 4
                *(float4*)&Bs[brow][bq] =
                    *(const float4*)(X + ((size_t)(b*NNODES + kt + brow))*C + c);
            } else {
                Bs[brow][bq+0]=0.f; Bs[brow][bq+1]=0.f; Bs[brow][bq+2]=0.f; Bs[brow][bq+3]=0.f;
            }
        } else {
            #pragma unroll
            for (int q = 0; q < 4; q++) {
                int j = j0 + bq + q;
                float v = 0.f;
                if (j < NC) {
                    int b = j / C, c = j % C;
                    v = X[((size_t)(b*NNODES + kt + brow))*C + c];
                }
                Bs[brow][bq+q] = v;
            }
        }
        __syncthreads();
        #pragma unroll
        for (int k = 0; k < 16; k++) {
            float4 a = *(float4*)&As[k][ty*4];
            float4 b = *(float4*)&Bs[k][tx*4];
            float ar[4] = {a.x,a.y,a.z,a.w};
            float br[4] = {b.x,b.y,b.z,b.w};
            #pragma unroll
            for (int i = 0; i < 4; i++)
                #pragma unroll
                for (int j = 0; j < 4; j++) acc[i][j] += ar[i]*br[j];
        }
        __syncthreads();
    }
    const int m = f + 1;
    #pragma unroll
    for (int i = 0; i < 4; i++) {
        int n = n0 + ty*4 + i;
        #pragma unroll
        for (int j = 0; j < 4; j++) {
            int jc = j0 + tx*4 + j;
            if (jc < NC) {
                int b = jc / C, c = jc % C;
                F[((size_t)(b*NNODES + n)*5 + m)*Ctot + colOff + c] = acc[i][j];
            }
        }
    }
}

// ---------------- copy m=0 slice: F[.,.,0,:] = [inp | st] ------------------
__global__ void copyM0(const float* __restrict__ inp, int Cin,
                       const float* __restrict__ st,
                       float* __restrict__ F, int Ctot) {
    int idx = blockIdx.x*blockDim.x + threadIdx.x;
    int total = NROWS * Ctot;
    if (idx >= total) return;
    int c = idx % Ctot, row = idx / Ctot;
    float v = (c < Cin) ? inp[row*Cin + c] : st[row*HID + (c - Cin)];
    F[((size_t)row*5)*Ctot + c] = v;
}

// ------- copy shared inputs-diffusion feats (m=1..4, c<Cin) Fru -> Fh ------
__global__ void copyInFeats(const float* __restrict__ Fsrc, float* __restrict__ Fdst,
                            int Cin, int Ctot) {
    int idx = blockIdx.x*blockDim.x + threadIdx.x;
    int total = NROWS * 4 * Cin;
    if (idx >= total) return;
    int c = idx % Cin; int t = idx / Cin;
    int m = (t & 3) + 1; int row = t >> 2;
    size_t off = ((size_t)row*5 + m)*Ctot + c;
    Fdst[off] = Fsrc[off];
}

// ------------- mixing GEMM + fused GRU epilogues ---------------------------
// out[row,o] = sum_k F[row,k] * W[k,o] + bias[o];  F row-major ld = Kdim.
__global__ void mixRU(const float* __restrict__ F, int Kdim,
                      const float* __restrict__ W, const float* __restrict__ bias,
                      const float* __restrict__ state, int O) {
    __shared__ float As[16][64];
    __shared__ float Bs[16][64];
    const int tid = threadIdx.x;
    const int tx = tid & 15, ty = tid >> 4;
    const int r0 = blockIdx.y * 64;
    const int o0 = blockIdx.x * 64;
    const int arow = tid >> 2, ak = (tid & 3) * 4;
    const int brow = tid >> 4, bq = (tid & 15) * 4;
    float acc[4][4] = {};
    for (int kt = 0; kt < Kdim; kt += 16) {
        #pragma unroll
        for (int q = 0; q < 4; q++) {
            int kk = kt + ak + q;
            As[ak+q][arow] = (kk < Kdim) ? F[(size_t)(r0+arow)*Kdim + kk] : 0.f;
        }
        int kk = kt + brow;
        if (kk < Kdim) *(float4*)&Bs[brow][bq] = *(const float4*)(W + (size_t)kk*O + o0 + bq);
        else { Bs[brow][bq]=0.f; Bs[brow][bq+1]=0.f; Bs[brow][bq+2]=0.f; Bs[brow][bq+3]=0.f; }
        __syncthreads();
        #pragma unroll
        for (int k = 0; k < 16; k++) {
            float4 a = *(float4*)&As[k][ty*4];
            float4 b = *(float4*)&Bs[k][tx*4];
            float ar[4] = {a.x,a.y,a.z,a.w};
            float br[4] = {b.x,b.y,b.z,b.w};
            #pragma unroll
            for (int i = 0; i < 4; i++)
                #pragma unroll
                for (int j = 0; j < 4; j++) acc[i][j] += ar[i]*br[j];
        }
        __syncthreads();
    }
    #pragma unroll
    for (int i = 0; i < 4; i++) {
        int row = r0 + ty*4 + i;
        #pragma unroll
        for (int j = 0; j < 4; j++) {
            int o = o0 + tx*4 + j;
            float g = 1.f / (1.f + expf(-(acc[i][j] + bias[o])));
            if (o < HID) g_rstate[row*HID + o] = g * state[row*HID + o];
            else         g_u[row*HID + (o - HID)] = g;
        }
    }
}

__global__ void mixH(const float* __restrict__ F, int Kdim,
                     const float* __restrict__ W, const float* __restrict__ bias,
                     float* __restrict__ state, int O) {
    __shared__ float As[16][64];
    __shared__ float Bs[16][64];
    const int tid = threadIdx.x;
    const int tx = tid & 15, ty = tid >> 4;
    const int r0 = blockIdx.y * 64;
    const int o0 = blockIdx.x * 64;
    const int arow = tid >> 2, ak = (tid & 3) * 4;
    const int brow = tid >> 4, bq = (tid & 15) * 4;
    float acc[4][4] = {};
    for (int kt = 0; kt < Kdim; kt += 16) {
        #pragma unroll
        for (int q = 0; q < 4; q++) {
            int kk = kt + ak + q;
            As[ak+q][arow] = (kk < Kdim) ? F[(size_t)(r0+arow)*Kdim + kk] : 0.f;
        }
        int kk = kt + brow;
        if (kk < Kdim) *(float4*)&Bs[brow][bq] = *(const float4*)(W + (size_t)kk*O + o0 + bq);
        else { Bs[brow][bq]=0.f; Bs[brow][bq+1]=0.f; Bs[brow][bq+2]=0.f; Bs[brow][bq+3]=0.f; }
        __syncthreads();
        #pragma unroll
        for (int k = 0; k < 16; k++) {
            float4 a = *(float4*)&As[k][ty*4];
            float4 b = *(float4*)&Bs[k][tx*4];
            float ar[4] = {a.x,a.y,a.z,a.w};
            float br[4] = {b.x,b.y,b.z,b.w};
            #pragma unroll
            for (int i = 0; i < 4; i++)
                #pragma unroll
                for (int j = 0; j < 4; j++) acc[i][j] += ar[i]*br[j];
        }
        __syncthreads();
    }
    #pragma unroll
    for (int i = 0; i < 4; i++) {
        int row = r0 + ty*4 + i;
        #pragma unroll
        for (int j = 0; j < 4; j++) {
            int o = o0 + tx*4 + j;
            float h = tanhf(acc[i][j] + bias[o]);
            float u = g_u[row*HID + o];
            float s = state[row*HID + o];
            state[row*HID + o] = u*s + (1.f - u)*h;
        }
    }
}

// ---------------- projection: out = state1 @ W_p + b_p --------------------
__global__ void projK(const float* __restrict__ Wp, const float* __restrict__ bp,
                      float* __restrict__ out_t) {
    int row = blockIdx.x*blockDim.x + threadIdx.x;
    if (row >= NROWS) return;
    const float* s = g_state1 + (size_t)row*HID;
    float a0 = bp[0], a1 = bp[1];
    #pragma unroll
    for (int h = 0; h < HID; h++) {
        float sv = s[h];
        a0 += sv * Wp[h*2 + 0];
        a1 += sv * Wp[h*2 + 1];
    }
    out_t[row*2 + 0] = a0;  out_t[row*2 + 1] = a1;
    g_decin[row*2 + 0] = a0; g_decin[row*2 + 1] = a1;
}

// --------------------------------------------------------------------------
extern "C" void kernel_launch(void* const* d_in, const int* in_sizes, int n_in,
                              void* d_out, int out_size) {
    const float* enc  = (const float*)d_in[0];
    const float* sup  = (const float*)d_in[1];
    const float* Wru0 = (const float*)d_in[2];
    const float* bru0 = (const float*)d_in[3];
    const float* Wh0  = (const float*)d_in[4];
    const float* bh0  = (const float*)d_in[5];
    const float* Wru1 = (const float*)d_in[6];
    const float* bru1 = (const float*)d_in[7];
    const float* Wh1  = (const float*)d_in[8];
    const float* bh1  = (const float*)d_in[9];
    const float* Wp   = (const float*)d_in[10];
    const float* bp   = (const float*)d_in[11];
    float* out = (float*)d_out;

    void *pFruV, *pFhV, *pS0V, *pS1V, *pDecV, *pRstV;
    cudaGetSymbolAddress(&pFruV, g_Fru);
    cudaGetSymbolAddress(&pFhV,  g_Fh);
    cudaGetSymbolAddress(&pS0V,  g_state0);
    cudaGetSymbolAddress(&pS1V,  g_state1);
    cudaGetSymbolAddress(&pDecV, g_decin);
    cudaGetSymbolAddress(&pRstV, g_rstate);
    float* pFru = (float*)pFruV; float* pFh  = (float*)pFhV;
    float* pS0  = (float*)pS0V;  float* pS1  = (float*)pS1V;
    float* pDec = (float*)pDecV; float* pRst = (float*)pRstV;

    initK<<<(NROWS*HID + 255)/256, 256>>>(enc);
    precomputeM<<<dim3(16,16,2), 256>>>(sup);

    for (int t = 0; t < STEPS; t++) {
        // ---- layer 0: in = decin (Cin=2), state = state0, Ctot=66, Kdim=330
        copyM0<<<(NROWS*66 + 255)/256, 256>>>(pDec, 2, pS0, pFru, 66);
        diffuseK<2> <<<dim3(1, 16, 4), 256>>>(pDec, pFru, 66, 0, sup);
        diffuseK<64><<<dim3(32,16, 4), 256>>>(pS0,  pFru, 66, 2, sup);
        mixRU<<<dim3(2,512), 256>>>(pFru, 330, Wru0, bru0, pS0, 128);
        copyM0<<<(NROWS*66 + 255)/256, 256>>>(pDec, 2, pRst, pFh, 66);
        copyInFeats<<<(NROWS*8 + 255)/256, 256>>>(pFru, pFh, 2, 66);
        diffuseK<64><<<dim3(32,16,4), 256>>>(pRst, pFh, 66, 2, sup);
        mixH<<<dim3(1,512), 256>>>(pFh, 330, Wh0, bh0, pS0, 64);

        // ---- layer 1: in = state0 (Cin=64), state = state1, Ctot=128, Kdim=640
        copyM0<<<(NROWS*128 + 255)/256, 256>>>(pS0, 64, pS1, pFru, 128);
        diffuseK<64><<<dim3(32,16,4), 256>>>(pS0, pFru, 128, 0,  sup);
        diffuseK<64><<<dim3(32,16,4), 256>>>(pS1, pFru, 128, 64, sup);
        mixRU<<<dim3(2,512), 256>>>(pFru, 640, Wru1, bru1, pS1, 128);
        copyM0<<<(NROWS*128 + 255)/256, 256>>>(pS0, 64, pRst, pFh, 128);
        copyInFeats<<<(NROWS*256 + 255)/256, 256>>>(pFru, pFh, 64, 128);
        diffuseK<64><<<dim3(32,16,4), 256>>>(pRst, pFh, 128, 64, sup);
        mixH<<<dim3(1,512), 256>>>(pFh, 640, Wh1, bh1, pS1, 64);

        // ---- projection
        projK<<<(NROWS + 255)/256, 256>>>(Wp, bp, out + (size_t)t*NROWS*OUTD);
    }
}

// round 3
// speedup vs baseline: 1.0011x; 1.0011x over previous
#include <cuda_runtime.h>
#include <math.h>

#define NNODES 1024
#define BATCH 32
#define HID 64
#define OUTD 2
#define STEPS 12
#define NROWS (BATCH*NNODES)   // 32768

// ---------------- scratch (static device allocations; no cudaMalloc) ------
__device__ float g_M[2*NNODES*NNODES];          // M_s = 2*S_s@S_s - I
__device__ float g_state0[NROWS*HID];
__device__ float g_state1[NROWS*HID];
__device__ float g_decin [NROWS*OUTD];
__device__ float g_u     [NROWS*HID];
__device__ float g_rstate[NROWS*HID];
__device__ float g_Fru[NROWS*5*128];            // features [b,n,m,c], Ctot<=128
__device__ float g_Fh [NROWS*5*128];

// ---------------- init: states <- encoder_state, decin <- 0 ---------------
__global__ void initK(const float* __restrict__ enc) {
    int idx = blockIdx.x*blockDim.x + threadIdx.x;
    const int SZ = NROWS*HID;
    if (idx < SZ) { g_state0[idx] = enc[idx]; g_state1[idx] = enc[SZ+idx]; }
    if (idx < NROWS*OUTD) g_decin[idx] = 0.f;
}

// ---------------- M_s = 2*S_s@S_s - I  (1024^3 GEMM, z = s) ----------------
__global__ void precomputeM(const float* __restrict__ supports) {
    const int s = blockIdx.z;
    const float* __restrict__ S = supports + s*NNODES*NNODES;
    float* __restrict__ Mo = g_M + s*NNODES*NNODES;
    __shared__ float As[16][64];
    __shared__ float Bs[16][64];
    const int tid = threadIdx.x;
    const int tx = tid & 15, ty = tid >> 4;
    const int n0 = blockIdx.y * 64;
    const int j0 = blockIdx.x * 64;
    const int arow = tid >> 2, aq = (tid & 3) * 4;
    const int brow = tid >> 4, bq = (tid & 15) * 4;
    float acc[4][4] = {};
    for (int kt = 0; kt < NNODES; kt += 16) {
        float4 av = *(const float4*)(S + (size_t)(n0+arow)*NNODES + kt + aq);
        As[aq+0][arow] = av.x; As[aq+1][arow] = av.y;
        As[aq+2][arow] = av.z; As[aq+3][arow] = av.w;
        float4 bv = *(const float4*)(S + (size_t)(kt+brow)*NNODES + j0 + bq);
        *(float4*)&Bs[brow][bq] = bv;
        __syncthreads();
        #pragma unroll
        for (int k = 0; k < 16; k++) {
            float4 a = *(float4*)&As[k][ty*4];
            float4 b = *(float4*)&Bs[k][tx*4];
            float ar[4] = {a.x,a.y,a.z,a.w};
            float br[4] = {b.x,b.y,b.z,b.w};
            #pragma unroll
            for (int i = 0; i < 4; i++)
                #pragma unroll
                for (int j = 0; j < 4; j++) acc[i][j] += ar[i]*br[j];
        }
        __syncthreads();
    }
    #pragma unroll
    for (int i = 0; i < 4; i++) {
        int n = n0 + ty*4 + i;
        #pragma unroll
        for (int j = 0; j < 4; j++) {
            int jc = j0 + tx*4 + j;
            Mo[(size_t)n*NNODES + jc] = 2.f*acc[i][j] - (n == jc ? 1.f : 0.f);
        }
    }
}

// ---------------- diffusion: Y_f = Op_f @ Xmat, f in {S0,M0,S1,M1} ---------
// Xmat[k, j] = X[b(j), k, c(j)], j in [0, B*C). Writes F[b,n,f+1, colOff+c].
template<int C>
__global__ void diffuseK(const float* __restrict__ X, float* __restrict__ F,
                         int Ctot, int colOff, const float* __restrict__ supports) {
    const int f = blockIdx.z;
    const float* __restrict__ Op =
        (f == 0) ? supports :
        (f == 1) ? g_M :
        (f == 2) ? supports + NNODES*NNODES : g_M + NNODES*NNODES;
    const int NC = BATCH * C;
    __shared__ float As[16][64];
    __shared__ float Bs[16][64];
    const int tid = threadIdx.x;
    const int tx = tid & 15, ty = tid >> 4;
    const int n0 = blockIdx.y * 64;
    const int j0 = blockIdx.x * 64;
    const int arow = tid >> 2, aq = (tid & 3) * 4;
    const int brow = tid >> 4, bq = (tid & 15) * 4;
    float acc[4][4] = {};
    for (int kt = 0; kt < NNODES; kt += 16) {
        float4 av = *(const float4*)(Op + (size_t)(n0+arow)*NNODES + kt + aq);
        As[aq+0][arow] = av.x; As[aq+1][arow] = av.y;
        As[aq+2][arow] = av.z; As[aq+3][arow] = av.w;
        if ((C & 3) == 0) {
            int j = j0 + bq;
            if (j < NC) {
                int b = j / C, c = j % C;   // C=64: b constant across the 4
                *(float4*)&Bs[brow][bq] =
                    *(const float4*)(X + ((size_t)(b*NNODES + kt + brow))*C + c);
            } else {
                Bs[brow][bq+0]=0.f; Bs[brow][bq+1]=0.f; Bs[brow][bq+2]=0.f; Bs[brow][bq+3]=0.f;
            }
        } else {
            #pragma unroll
            for (int q = 0; q < 4; q++) {
                int j = j0 + bq + q;
                float v = 0.f;
                if (j < NC) {
                    int b = j / C, c = j % C;
                    v = X[((size_t)(b*NNODES + kt + brow))*C + c];
                }
                Bs[brow][bq+q] = v;
            }
        }
        __syncthreads();
        #pragma unroll
        for (int k = 0; k < 16; k++) {
            float4 a = *(float4*)&As[k][ty*4];
            float4 b = *(float4*)&Bs[k][tx*4];
            float ar[4] = {a.x,a.y,a.z,a.w};
            float br[4] = {b.x,b.y,b.z,b.w};
            #pragma unroll
            for (int i = 0; i < 4; i++)
                #pragma unroll
                for (int j = 0; j < 4; j++) acc[i][j] += ar[i]*br[j];
        }
        __syncthreads();
    }
    const int m = f + 1;
    #pragma unroll
    for (int i = 0; i < 4; i++) {
        int n = n0 + ty*4 + i;
        #pragma unroll
        for (int j = 0; j < 4; j++) {
            int jc = j0 + tx*4 + j;
            if (jc < NC) {
                int b = jc / C, c = jc % C;
                F[((size_t)(b*NNODES + n)*5 + m)*Ctot + colOff + c] = acc[i][j];
            }
        }
    }
}

// ---------------- copy m=0 slice: F[.,.,0,:] = [inp | st] ------------------
__global__ void copyM0(const float* __restrict__ inp, int Cin,
                       const float* __restrict__ st,
                       float* __restrict__ F, int Ctot) {
    int idx = blockIdx.x*blockDim.x + threadIdx.x;
    int total = NROWS * Ctot;
    if (idx >= total) return;
    int c = idx % Ctot, row = idx / Ctot;
    float v = (c < Cin) ? inp[row*Cin + c] : st[row*HID + (c - Cin)];
    F[((size_t)row*5)*Ctot + c] = v;
}

// ------- copy shared inputs-diffusion feats (m=1..4, c<Cin) Fru -> Fh ------
__global__ void copyInFeats(const float* __restrict__ Fsrc, float* __restrict__ Fdst,
                            int Cin, int Ctot) {
    int idx = blockIdx.x*blockDim.x + threadIdx.x;
    int total = NROWS * 4 * Cin;
    if (idx >= total) return;
    int c = idx % Cin; int t = idx / Cin;
    int m = (t & 3) + 1; int row = t >> 2;
    size_t off = ((size_t)row*5 + m)*Ctot + c;
    Fdst[off] = Fsrc[off];
}

// ------------- mixing GEMM + fused GRU epilogues ---------------------------
// out[row,o] = sum_k F[row,k] * W[k,o] + bias[o];  F row-major ld = Kdim.
__global__ void mixRU(const float* __restrict__ F, int Kdim,
                      const float* __restrict__ W, const float* __restrict__ bias,
                      const float* __restrict__ state, int O) {
    __shared__ float As[16][64];
    __shared__ float Bs[16][64];
    const int tid = threadIdx.x;
    const int tx = tid & 15, ty = tid >> 4;
    const int r0 = blockIdx.y * 64;
    const int o0 = blockIdx.x * 64;
    const int arow = tid >> 2, ak = (tid & 3) * 4;
    const int brow = tid >> 4, bq = (tid & 15) * 4;
    float acc[4][4] = {};
    for (int kt = 0; kt < Kdim; kt += 16) {
        #pragma unroll
        for (int q = 0; q < 4; q++) {
            int kk = kt + ak + q;
            As[ak+q][arow] = (kk < Kdim) ? F[(size_t)(r0+arow)*Kdim + kk] : 0.f;
        }
        int kk = kt + brow;
        if (kk < Kdim) *(float4*)&Bs[brow][bq] = *(const float4*)(W + (size_t)kk*O + o0 + bq);
        else { Bs[brow][bq]=0.f; Bs[brow][bq+1]=0.f; Bs[brow][bq+2]=0.f; Bs[brow][bq+3]=0.f; }
        __syncthreads();
        #pragma unroll
        for (int k = 0; k < 16; k++) {
            float4 a = *(float4*)&As[k][ty*4];
            float4 b = *(float4*)&Bs[k][tx*4];
            float ar[4] = {a.x,a.y,a.z,a.w};
            float br[4] = {b.x,b.y,b.z,b.w};
            #pragma unroll
            for (int i = 0; i < 4; i++)
                #pragma unroll
                for (int j = 0; j < 4; j++) acc[i][j] += ar[i]*br[j];
        }
        __syncthreads();
    }
    #pragma unroll
    for (int i = 0; i < 4; i++) {
        int row = r0 + ty*4 + i;
        #pragma unroll
        for (int j = 0; j < 4; j++) {
            int o = o0 + tx*4 + j;
            float g = 1.f / (1.f + expf(-(acc[i][j] + bias[o])));
            if (o < HID) g_rstate[row*HID + o] = g * state[row*HID + o];
            else         g_u[row*HID + (o - HID)] = g;
        }
    }
}

__global__ void mixH(const float* __restrict__ F, int Kdim,
                     const float* __restrict__ W, const float* __restrict__ bias,
                     float* __restrict__ state, int O) {
    __shared__ float As[16][64];
    __shared__ float Bs[16][64];
    const int tid = threadIdx.x;
    const int tx = tid & 15, ty = tid >> 4;
    const int r0 = blockIdx.y * 64;
    const int o0 = blockIdx.x * 64;
    const int arow = tid >> 2, ak = (tid & 3) * 4;
    const int brow = tid >> 4, bq = (tid & 15) * 4;
    float acc[4][4] = {};
    for (int kt = 0; kt < Kdim; kt += 16) {
        #pragma unroll
        for (int q = 0; q < 4; q++) {
            int kk = kt + ak + q;
            As[ak+q][arow] = (kk < Kdim) ? F[(size_t)(r0+arow)*Kdim + kk] : 0.f;
        }
        int kk = kt + brow;
        if (kk < Kdim) *(float4*)&Bs[brow][bq] = *(const float4*)(W + (size_t)kk*O + o0 + bq);
        else { Bs[brow][bq]=0.f; Bs[brow][bq+1]=0.f; Bs[brow][bq+2]=0.f; Bs[brow][bq+3]=0.f; }
        __syncthreads();
        #pragma unroll
        for (int k = 0; k < 16; k++) {
            float4 a = *(float4*)&As[k][ty*4];
            float4 b = *(float4*)&Bs[k][tx*4];
            float ar[4] = {a.x,a.y,a.z,a.w};
            float br[4] = {b.x,b.y,b.z,b.w};
            #pragma unroll
            for (int i = 0; i < 4; i++)
                #pragma unroll
                for (int j = 0; j < 4; j++) acc[i][j] += ar[i]*br[j];
        }
        __syncthreads();
    }
    #pragma unroll
    for (int i = 0; i < 4; i++) {
        int row = r0 + ty*4 + i;
        #pragma unroll
        for (int j = 0; j < 4; j++) {
            int o = o0 + tx*4 + j;
            float h = tanhf(acc[i][j] + bias[o]);
            float u = g_u[row*HID + o];
            float s = state[row*HID + o];
            state[row*HID + o] = u*s + (1.f - u)*h;
        }
    }
}

// ---------------- projection: out = state1 @ W_p + b_p --------------------
__global__ void projK(const float* __restrict__ Wp, const float* __restrict__ bp,
                      float* __restrict__ out_t) {
    int row = blockIdx.x*blockDim.x + threadIdx.x;
    if (row >= NROWS) return;
    const float* s = g_state1 + (size_t)row*HID;
    float a0 = bp[0], a1 = bp[1];
    #pragma unroll
    for (int h = 0; h < HID; h++) {
        float sv = s[h];
        a0 += sv * Wp[h*2 + 0];
        a1 += sv * Wp[h*2 + 1];
    }
    out_t[row*2 + 0] = a0;  out_t[row*2 + 1] = a1;
    g_decin[row*2 + 0] = a0; g_decin[row*2 + 1] = a1;
}

// --------------------------------------------------------------------------
extern "C" void kernel_launch(void* const* d_in, const int* in_sizes, int n_in,
                              void* d_out, int out_size) {
    const float* enc  = (const float*)d_in[0];
    const float* sup  = (const float*)d_in[1];
    const float* Wru0 = (const float*)d_in[2];
    const float* bru0 = (const float*)d_in[3];
    const float* Wh0  = (const float*)d_in[4];
    const float* bh0  = (const float*)d_in[5];
    const float* Wru1 = (const float*)d_in[6];
    const float* bru1 = (const float*)d_in[7];
    const float* Wh1  = (const float*)d_in[8];
    const float* bh1  = (const float*)d_in[9];
    const float* Wp   = (const float*)d_in[10];
    const float* bp   = (const float*)d_in[11];
    float* out = (float*)d_out;

    void *pFruV, *pFhV, *pS0V, *pS1V, *pDecV, *pRstV;
    cudaGetSymbolAddress(&pFruV, g_Fru);
    cudaGetSymbolAddress(&pFhV,  g_Fh);
    cudaGetSymbolAddress(&pS0V,  g_state0);
    cudaGetSymbolAddress(&pS1V,  g_state1);
    cudaGetSymbolAddress(&pDecV, g_decin);
    cudaGetSymbolAddress(&pRstV, g_rstate);
    float* pFru = (float*)pFruV; float* pFh  = (float*)pFhV;
    float* pS0  = (float*)pS0V;  float* pS1  = (float*)pS1V;
    float* pDec = (float*)pDecV; float* pRst = (float*)pRstV;

    initK<<<(NROWS*HID + 255)/256, 256>>>(enc);
    precomputeM<<<dim3(16,16,2), 256>>>(sup);

    for (int t = 0; t < STEPS; t++) {
        // ---- layer 0: in = decin (Cin=2), state = state0, Ctot=66, Kdim=330
        copyM0<<<(NROWS*66 + 255)/256, 256>>>(pDec, 2, pS0, pFru, 66);
        diffuseK<2> <<<dim3(1, 16, 4), 256>>>(pDec, pFru, 66, 0, sup);
        diffuseK<64><<<dim3(32,16, 4), 256>>>(pS0,  pFru, 66, 2, sup);
        mixRU<<<dim3(2,512), 256>>>(pFru, 330, Wru0, bru0, pS0, 128);
        copyM0<<<(NROWS*66 + 255)/256, 256>>>(pDec, 2, pRst, pFh, 66);
        copyInFeats<<<(NROWS*8 + 255)/256, 256>>>(pFru, pFh, 2, 66);
        diffuseK<64><<<dim3(32,16,4), 256>>>(pRst, pFh, 66, 2, sup);
        mixH<<<dim3(1,512), 256>>>(pFh, 330, Wh0, bh0, pS0, 64);

        // ---- layer 1: in = state0 (Cin=64), state = state1, Ctot=128, Kdim=640
        copyM0<<<(NROWS*128 + 255)/256, 256>>>(pS0, 64, pS1, pFru, 128);
        diffuseK<64><<<dim3(32,16,4), 256>>>(pS0, pFru, 128, 0,  sup);
        diffuseK<64><<<dim3(32,16,4), 256>>>(pS1, pFru, 128, 64, sup);
        mixRU<<<dim3(2,512), 256>>>(pFru, 640, Wru1, bru1, pS1, 128);
        copyM0<<<(NROWS*128 + 255)/256, 256>>>(pS0, 64, pRst, pFh, 128);
        copyInFeats<<<(NROWS*256 + 255)/256, 256>>>(pFru, pFh, 64, 128);
        diffuseK<64><<<dim3(32,16,4), 256>>>(pRst, pFh, 128, 64, sup);
        mixH<<<dim3(1,512), 256>>>(pFh, 640, Wh1, bh1, pS1, 64);

        // ---- projection
        projK<<<(NROWS + 255)/256, 256>>>(Wp, bp, out + (size_t)t*NROWS*OUTD);
    }
}

// round 5
// speedup vs baseline: 2.0160x; 2.0138x over previous
#include <cuda_runtime.h>
#include <cuda_bf16.h>
#include <math.h>
#include <stdint.h>

#define NN 1024
#define BATCH 32
#define HID 64
#define OUTD 2
#define STEPS 12
#define NROWS (BATCH*NN)

// ---------------- PTX helpers (sm_80-era, base-target legal) --------------
__device__ __forceinline__ uint32_t smem_u32(const void* p) {
    uint32_t a;
    asm("{ .reg .u64 t; cvta.to.shared.u64 t, %1; cvt.u32.u64 %0, t; }" : "=r"(a) : "l"(p));
    return a;
}
__device__ __forceinline__ void cp16(uint32_t sa, const void* g) {
    asm volatile("cp.async.cg.shared.global [%0], [%1], 16;" :: "r"(sa), "l"(g) : "memory");
}
#define CP_COMMIT() asm volatile("cp.async.commit_group;" ::: "memory")
#define CP_WAIT(n)  asm volatile("cp.async.wait_group %0;" :: "n"(n) : "memory")
#define LDSM4(r, a) asm volatile( \
    "ldmatrix.sync.aligned.m8n8.x4.shared.b16 {%0,%1,%2,%3}, [%4];" \
    : "=r"((r)[0]), "=r"((r)[1]), "=r"((r)[2]), "=r"((r)[3]) : "r"(a))
#define LDSM2(r, a) asm volatile( \
    "ldmatrix.sync.aligned.m8n8.x2.shared.b16 {%0,%1}, [%2];" \
    : "=r"((r)[0]), "=r"((r)[1]) : "r"(a))
#define MMA16816(d, a, b) asm volatile( \
    "mma.sync.aligned.m16n8k16.row.col.f32.bf16.bf16.f32 " \
    "{%0,%1,%2,%3},{%4,%5,%6,%7},{%8,%9},{%0,%1,%2,%3};" \
    : "+f"((d)[0]), "+f"((d)[1]), "+f"((d)[2]), "+f"((d)[3]) \
    : "r"((a)[0]), "r"((a)[1]), "r"((a)[2]), "r"((a)[3]), "r"((b)[0]), "r"((b)[1]))

// ---------------- scratch -------------------------------------------------
__device__ float g_M[2u*NN*NN];
__device__ float g_state0[NROWS*HID];
__device__ float g_state1[NROWS*HID];
__device__ float g_decin [NROWS*OUTD];
__device__ float g_u     [NROWS*HID];
__device__ float g_rstate[NROWS*HID];
__device__ float g_Fru[(size_t)NROWS*640];
__device__ float g_Fh [(size_t)NROWS*640];
__device__ __nv_bfloat16 g_oph[(size_t)4*NN*NN];
__device__ __nv_bfloat16 g_opl[(size_t)4*NN*NN];
__device__ __nv_bfloat16 g_Xh[(size_t)4096*NN];
__device__ __nv_bfloat16 g_Xl[(size_t)4096*NN];

// ---------------- small kernels ------------------------------------------
__global__ void initK(const float* __restrict__ enc) {
    int i = blockIdx.x*blockDim.x + threadIdx.x;
    const int SZ = NROWS*HID;
    if (i < SZ) { g_state0[i] = enc[i]; g_state1[i] = enc[SZ+i]; }
    if (i < NROWS*OUTD) g_decin[i] = 0.f;
}

__global__ void precomputeM(const float* __restrict__ sup) {
    const int s = blockIdx.z;
    const float* __restrict__ S = sup + (size_t)s*NN*NN;
    float* __restrict__ Mo = g_M + (size_t)s*NN*NN;
    __shared__ float As[16][64], Bs[16][64];
    const int tid = threadIdx.x, tx = tid & 15, ty = tid >> 4;
    const int n0 = blockIdx.y*64, j0 = blockIdx.x*64;
    const int ar = tid >> 2, aq = (tid & 3)*4, br = tid >> 4, bq = (tid & 15)*4;
    float acc[4][4] = {};
    for (int kt = 0; kt < NN; kt += 16) {
        float4 av = *(const float4*)(S + (size_t)(n0+ar)*NN + kt + aq);
        As[aq][ar]=av.x; As[aq+1][ar]=av.y; As[aq+2][ar]=av.z; As[aq+3][ar]=av.w;
        *(float4*)&Bs[br][bq] = *(const float4*)(S + (size_t)(kt+br)*NN + j0 + bq);
        __syncthreads();
        #pragma unroll
        for (int k = 0; k < 16; k++) {
            float4 a = *(float4*)&As[k][ty*4], b = *(float4*)&Bs[k][tx*4];
            float arr[4]={a.x,a.y,a.z,a.w}, brr[4]={b.x,b.y,b.z,b.w};
            #pragma unroll
            for (int i=0;i<4;i++)
                #pragma unroll
                for (int j=0;j<4;j++) acc[i][j] += arr[i]*brr[j];
        }
        __syncthreads();
    }
    #pragma unroll
    for (int i=0;i<4;i++) { int n=n0+ty*4+i;
        #pragma unroll
        for (int j=0;j<4;j++) { int jc=j0+tx*4+j;
            Mo[(size_t)n*NN+jc] = 2.f*acc[i][j] - (n==jc?1.f:0.f); } }
}

__global__ void splitOpsK(const float* __restrict__ sup) {
    size_t i = (size_t)blockIdx.x*blockDim.x + threadIdx.x;
    if (i >= (size_t)4*NN*NN) return;
    int op = (int)(i >> 20); size_t r = i & ((size_t)NN*NN - 1);
    const float* src = (op==0) ? sup : (op==1) ? g_M :
                       (op==2) ? sup + (size_t)NN*NN : g_M + (size_t)NN*NN;
    float v = src[r];
    __nv_bfloat16 h = __float2bfloat16(v);
    g_oph[i] = h; g_opl[i] = __float2bfloat16(v - __bfloat162float(h));
}

// transpose+split: Xc[(b*Ct + c)*NN + n] (bf16 hi/lo) from row-major [b*NN+n, 64]
__global__ void tsplitK(const float* __restrict__ s0, const float* __restrict__ s1, int Ct) {
    __shared__ float t[32][33];
    int b = blockIdx.z, n0 = blockIdx.x*32, c0 = blockIdx.y*32;
    int tx = threadIdx.x, ty = threadIdx.y;
    int c = c0 + tx;
    const float* sp = (c < 64) ? s0 : s1;
    t[ty][tx] = sp[((size_t)(b*NN + n0 + ty))*HID + (c & 63)];
    __syncthreads();
    float v = t[tx][ty];
    int n = n0 + tx, cw = c0 + ty;
    __nv_bfloat16 h = __float2bfloat16(v);
    size_t o = ((size_t)(b*Ct + cw))*NN + n;
    g_Xh[o] = h; g_Xl[o] = __float2bfloat16(v - __bfloat162float(h));
}

// ---------------- mma.sync diffusion kernel ------------------------------
// D[128 x 128] = Op_f[n0.., k] @ Xc[j0.., k]^T, split-bf16 3-pass.
// smem per stage: 4 matrices of 128 rows x 32 bf16, padded to 40 elems/row.
#define LDP 40
#define MATB (128*LDP*2)        // 10240 bytes per matrix
#define STAGEB (4*MATB)         // 40960
#define MMAD_SMEM (2*STAGEB)    // 81920

__device__ __forceinline__ void issueStage(uint32_t sbase, int buf, int kt, int tid,
    const __nv_bfloat16* Ah, const __nv_bfloat16* Al,
    const __nv_bfloat16* Bh, const __nv_bfloat16* Bl) {
    uint32_t so = sbase + buf*STAGEB;
    #pragma unroll
    for (int h = 0; h < 2; h++) {
        int ch = tid + h*256;            // 0..511
        int row = ch >> 2, kq = (ch & 3)*8;
        uint32_t soff = (uint32_t)(row*(LDP*2) + kq*2);
        size_t go = (size_t)row*NN + kt + kq;
        cp16(so + soff,          Ah + go);
        cp16(so + MATB + soff,   Al + go);
        cp16(so + 2*MATB + soff, Bh + go);
        cp16(so + 3*MATB + soff, Bl + go);
    }
    CP_COMMIT();
}

__global__ void __launch_bounds__(256)
mmaDiffuse(int Ctile, float* __restrict__ F, int FCtot, int colOff) {
    extern __shared__ __nv_bfloat16 sm[];
    const int tid = threadIdx.x, wid = tid >> 5, lane = tid & 31;
    const int f = blockIdx.z, n0 = blockIdx.y*128, j0 = blockIdx.x*128;
    const __nv_bfloat16* __restrict__ Ah = g_oph + ((size_t)f*NN + n0)*NN;
    const __nv_bfloat16* __restrict__ Al = g_opl + ((size_t)f*NN + n0)*NN;
    const __nv_bfloat16* __restrict__ Bh = g_Xh + (size_t)j0*NN;
    const __nv_bfloat16* __restrict__ Bl = g_Xl + (size_t)j0*NN;
    uint32_t sbase = smem_u32(sm);

    const int wm = wid >> 2, wn = wid & 3;   // warp tile: 64(m) x 32(n)
    float acc[4][4][4] = {};

    issueStage(sbase, 0, 0, tid, Ah, Al, Bh, Bl);
    for (int ch = 0; ch < 32; ch++) {
        if (ch + 1 < 32) {
            issueStage(sbase, (ch+1)&1, (ch+1)*32, tid, Ah, Al, Bh, Bl);
            CP_WAIT(1);
        } else {
            CP_WAIT(0);
        }
        __syncthreads();
        uint32_t Ab  = sbase + (ch&1)*STAGEB;
        uint32_t Alb = Ab + MATB, Bb = Ab + 2*MATB, Blb = Ab + 3*MATB;
        #pragma unroll
        for (int k16 = 0; k16 < 2; k16++) {
            const int kk = k16*16;
            uint32_t ah[4][4], al[4][4], bh[4][2], bl[4][2];
            #pragma unroll
            for (int im = 0; im < 4; im++) {
                int row = wm*64 + im*16 + (lane & 15);
                int col = kk + ((lane >> 4) << 3);
                uint32_t off = (uint32_t)(row*(LDP*2) + col*2);
                LDSM4(ah[im], Ab + off);
                LDSM4(al[im], Alb + off);
            }
            #pragma unroll
            for (int in = 0; in < 4; in++) {
                int row = wn*32 + in*8 + (lane & 7);
                int col = kk + (((lane >> 3) & 1) << 3);
                uint32_t off = (uint32_t)(row*(LDP*2) + col*2);
                LDSM2(bh[in], Bb + off);
                LDSM2(bl[in], Blb + off);
            }
            #pragma unroll
            for (int im = 0; im < 4; im++)
                #pragma unroll
                for (int in = 0; in < 4; in++) {
                    MMA16816(acc[im][in], ah[im], bh[in]);
                    MMA16816(acc[im][in], ah[im], bl[in]);
                    MMA16816(acc[im][in], al[im], bh[in]);
                }
        }
        __syncthreads();
    }

    // epilogue: write into F[(b*NN+n)*5 + f+1][colOff + c]
    const int m = f + 1;
    const int r = lane >> 2, cp = (lane & 3)*2;
    #pragma unroll
    for (int im = 0; im < 4; im++) {
        #pragma unroll
        for (int in = 0; in < 4; in++) {
            int jG = j0 + wn*32 + in*8 + cp;
            int b = jG / Ctile, c = jG % Ctile;
            int nG = n0 + wm*64 + im*16 + r;
            float* d0 = F + (((size_t)(b*NN + nG))*5 + m)*FCtot + colOff + c;
            d0[0] = acc[im][in][0]; d0[1] = acc[im][in][1];
            float* d1 = F + (((size_t)(b*NN + nG + 8))*5 + m)*FCtot + colOff + c;
            d1[0] = acc[im][in][2]; d1[1] = acc[im][in][3];
        }
    }
}

// ---------------- FFMA diffusion for decin (C=2) -------------------------
__global__ void diffuse2K(const float* __restrict__ X, float* __restrict__ F,
                          int Ctot, const float* __restrict__ sup) {
    const int f = blockIdx.z;
    const float* __restrict__ Op = (f==0) ? sup : (f==1) ? g_M :
        (f==2) ? sup + (size_t)NN*NN : g_M + (size_t)NN*NN;
    const int NC = BATCH*2;
    __shared__ float As[16][64], Bs[16][64];
    const int tid = threadIdx.x, tx = tid & 15, ty = tid >> 4;
    const int n0 = blockIdx.y*64;
    const int ar = tid >> 2, aq = (tid & 3)*4, br = tid >> 4, bq = (tid & 15)*4;
    float acc[4][4] = {};
    for (int kt = 0; kt < NN; kt += 16) {
        float4 av = *(const float4*)(Op + (size_t)(n0+ar)*NN + kt + aq);
        As[aq][ar]=av.x; As[aq+1][ar]=av.y; As[aq+2][ar]=av.z; As[aq+3][ar]=av.w;
        #pragma unroll
        for (int q = 0; q < 4; q++) {
            int j = bq + q; float v = 0.f;
            if (j < NC) v = X[((size_t)((j>>1)*NN + kt + br))*2 + (j & 1)];
            Bs[br][bq+q] = v;
        }
        __syncthreads();
        #pragma unroll
        for (int k = 0; k < 16; k++) {
            float4 a = *(float4*)&As[k][ty*4], b = *(float4*)&Bs[k][tx*4];
            float arr[4]={a.x,a.y,a.z,a.w}, brr[4]={b.x,b.y,b.z,b.w};
            #pragma unroll
            for (int i=0;i<4;i++)
                #pragma unroll
                for (int j=0;j<4;j++) acc[i][j] += arr[i]*brr[j];
        }
        __syncthreads();
    }
    const int m = f + 1;
    #pragma unroll
    for (int i=0;i<4;i++) { int n=n0+ty*4+i;
        #pragma unroll
        for (int j=0;j<4;j++) { int jc=tx*4+j;
            if (jc < NC)
                F[((size_t)((jc>>1)*NN + n)*5 + m)*Ctot + (jc & 1)] = acc[i][j]; } }
}

// ---------------- m0 + feature copies ------------------------------------
__global__ void copyM0(const float* __restrict__ inp, int Cin,
                       const float* __restrict__ st, float* __restrict__ F, int Ctot) {
    int i = blockIdx.x*blockDim.x + threadIdx.x;
    if (i >= NROWS*Ctot) return;
    int c = i % Ctot, row = i / Ctot;
    F[(size_t)row*5*Ctot + c] = (c < Cin) ? inp[row*Cin + c] : st[row*HID + c - Cin];
}
__global__ void copyInFeats(const float* __restrict__ Fs, float* __restrict__ Fd,
                            int Cin, int Ctot) {
    int i = blockIdx.x*blockDim.x + threadIdx.x;
    if (i >= NROWS*4*Cin) return;
    int c = i % Cin; int t = i / Cin;
    int m = (t & 3) + 1; int row = t >> 2;
    size_t o = ((size_t)row*5 + m)*Ctot + c;
    Fd[o] = Fs[o];
}

// ---------------- mixing GEMMs + GRU epilogues ---------------------------
__global__ void mixRU(const float* __restrict__ F, int Kdim,
                      const float* __restrict__ W, const float* __restrict__ bias,
                      const float* __restrict__ state, int O) {
    __shared__ float As[16][64], Bs[16][64];
    const int tid = threadIdx.x, tx = tid & 15, ty = tid >> 4;
    const int r0 = blockIdx.y*64, o0 = blockIdx.x*64;
    const int ar = tid >> 2, ak = (tid & 3)*4, br = tid >> 4, bq = (tid & 15)*4;
    float acc[4][4] = {};
    for (int kt = 0; kt < Kdim; kt += 16) {
        #pragma unroll
        for (int q = 0; q < 4; q++) {
            int kk = kt + ak + q;
            As[ak+q][ar] = (kk < Kdim) ? F[(size_t)(r0+ar)*Kdim + kk] : 0.f;
        }
        int kk = kt + br;
        if (kk < Kdim) *(float4*)&Bs[br][bq] = *(const float4*)(W + (size_t)kk*O + o0 + bq);
        else { Bs[br][bq]=0.f; Bs[br][bq+1]=0.f; Bs[br][bq+2]=0.f; Bs[br][bq+3]=0.f; }
        __syncthreads();
        #pragma unroll
        for (int k = 0; k < 16; k++) {
            float4 a = *(float4*)&As[k][ty*4], b = *(float4*)&Bs[k][tx*4];
            float arr[4]={a.x,a.y,a.z,a.w}, brr[4]={b.x,b.y,b.z,b.w};
            #pragma unroll
            for (int i=0;i<4;i++)
                #pragma unroll
                for (int j=0;j<4;j++) acc[i][j] += arr[i]*brr[j];
        }
        __syncthreads();
    }
    #pragma unroll
    for (int i=0;i<4;i++) { int row=r0+ty*4+i;
        #pragma unroll
        for (int j=0;j<4;j++) { int o=o0+tx*4+j;
            float g = 1.f/(1.f + expf(-(acc[i][j] + bias[o])));
            if (o < HID) g_rstate[row*HID + o] = g * state[row*HID + o];
            else         g_u[row*HID + o - HID] = g; } }
}

__global__ void mixH(const float* __restrict__ F, int Kdim,
                     const float* __restrict__ W, const float* __restrict__ bias,
                     float* __restrict__ state, int O) {
    __shared__ float As[16][64], Bs[16][64];
    const int tid = threadIdx.x, tx = tid & 15, ty = tid >> 4;
    const int r0 = blockIdx.y*64, o0 = blockIdx.x*64;
    const int ar = tid >> 2, ak = (tid & 3)*4, br = tid >> 4, bq = (tid & 15)*4;
    float acc[4][4] = {};
    for (int kt = 0; kt < Kdim; kt += 16) {
        #pragma unroll
        for (int q = 0; q < 4; q++) {
            int kk = kt + ak + q;
            As[ak+q][ar] = (kk < Kdim) ? F[(size_t)(r0+ar)*Kdim + kk] : 0.f;
        }
        int kk = kt + br;
        if (kk < Kdim) *(float4*)&Bs[br][bq] = *(const float4*)(W + (size_t)kk*O + o0 + bq);
        else { Bs[br][bq]=0.f; Bs[br][bq+1]=0.f; Bs[br][bq+2]=0.f; Bs[br][bq+3]=0.f; }
        __syncthreads();
        #pragma unroll
        for (int k = 0; k < 16; k++) {
            float4 a = *(float4*)&As[k][ty*4], b = *(float4*)&Bs[k][tx*4];
            float arr[4]={a.x,a.y,a.z,a.w}, brr[4]={b.x,b.y,b.z,b.w};
            #pragma unroll
            for (int i=0;i<4;i++)
                #pragma unroll
                for (int j=0;j<4;j++) acc[i][j] += arr[i]*brr[j];
        }
        __syncthreads();
    }
    #pragma unroll
    for (int i=0;i<4;i++) { int row=r0+ty*4+i;
        #pragma unroll
        for (int j=0;j<4;j++) { int o=o0+tx*4+j;
            float h = tanhf(acc[i][j] + bias[o]);
            float u = g_u[row*HID + o], s = state[row*HID + o];
            state[row*HID + o] = u*s + (1.f - u)*h; } }
}

__global__ void projK(const float* __restrict__ Wp, const float* __restrict__ bp,
                      float* __restrict__ out_t) {
    int row = blockIdx.x*blockDim.x + threadIdx.x;
    if (row >= NROWS) return;
    const float* s = g_state1 + (size_t)row*HID;
    float a0 = bp[0], a1 = bp[1];
    #pragma unroll
    for (int h = 0; h < HID; h++) { float v = s[h]; a0 += v*Wp[h*2]; a1 += v*Wp[h*2+1]; }
    out_t[row*2] = a0; out_t[row*2+1] = a1;
    g_decin[row*2] = a0; g_decin[row*2+1] = a1;
}

// -------------------------------------------------------------------------
extern "C" void kernel_launch(void* const* d_in, const int* in_sizes, int n_in,
                              void* d_out, int out_size) {
    const float* enc  = (const float*)d_in[0];
    const float* sup  = (const float*)d_in[1];
    const float* Wru0 = (const float*)d_in[2];
    const float* bru0 = (const float*)d_in[3];
    const float* Wh0  = (const float*)d_in[4];
    const float* bh0  = (const float*)d_in[5];
    const float* Wru1 = (const float*)d_in[6];
    const float* bru1 = (const float*)d_in[7];
    const float* Wh1  = (const float*)d_in[8];
    const float* bh1  = (const float*)d_in[9];
    const float* Wp   = (const float*)d_in[10];
    const float* bp   = (const float*)d_in[11];
    float* out = (float*)d_out;

    void *a, *b, *c, *d, *e, *f;
    cudaGetSymbolAddress(&a, g_Fru);   float* pFru = (float*)a;
    cudaGetSymbolAddress(&b, g_Fh);    float* pFh  = (float*)b;
    cudaGetSymbolAddress(&c, g_state0);float* pS0  = (float*)c;
    cudaGetSymbolAddress(&d, g_state1);float* pS1  = (float*)d;
    cudaGetSymbolAddress(&e, g_decin); float* pDec = (float*)e;
    cudaGetSymbolAddress(&f, g_rstate);float* pRst = (float*)f;

    cudaFuncSetAttribute(mmaDiffuse, cudaFuncAttributeMaxDynamicSharedMemorySize, MMAD_SMEM);

    initK<<<(NROWS*HID + 255)/256, 256>>>(enc);
    precomputeM<<<dim3(16,16,2), 256>>>(sup);
    splitOpsK<<<(int)(((size_t)4*NN*NN + 255)/256), 256>>>(sup);

    for (int t = 0; t < STEPS; t++) {
        // layer 0 RU: x=[decin|state0], Ctot=66, Kdim=330
        copyM0<<<(NROWS*66 + 255)/256, 256>>>(pDec, 2, pS0, pFru, 66);
        diffuse2K<<<dim3(1,16,4), 256>>>(pDec, pFru, 66, sup);
        tsplitK<<<dim3(32,2,32), dim3(32,32)>>>(pS0, pS0, 64);
        mmaDiffuse<<<dim3(16,8,4), 256, MMAD_SMEM>>>(64, pFru, 66, 2);
        mixRU<<<dim3(2,512), 256>>>(pFru, 330, Wru0, bru0, pS0, 128);
        // layer 0 H: x2=[decin|r*state0]
        copyM0<<<(NROWS*66 + 255)/256, 256>>>(pDec, 2, pRst, pFh, 66);
        copyInFeats<<<(NROWS*8 + 255)/256, 256>>>(pFru, pFh, 2, 66);
        tsplitK<<<dim3(32,2,32), dim3(32,32)>>>(pRst, pRst, 64);
        mmaDiffuse<<<dim3(16,8,4), 256, MMAD_SMEM>>>(64, pFh, 66, 2);
        mixH<<<dim3(1,512), 256>>>(pFh, 330, Wh0, bh0, pS0, 64);

        // layer 1 RU: x=[state0|state1], Ctot=128, Kdim=640
        copyM0<<<(NROWS*128 + 255)/256, 256>>>(pS0, 64, pS1, pFru, 128);
        tsplitK<<<dim3(32,4,32), dim3(32,32)>>>(pS0, pS1, 128);
        mmaDiffuse<<<dim3(32,8,4), 256, MMAD_SMEM>>>(128, pFru, 128, 0);
        mixRU<<<dim3(2,512), 256>>>(pFru, 640, Wru1, bru1, pS1, 128);
        // layer 1 H: x2=[state0|r*state1]
        copyM0<<<(NROWS*128 + 255)/256, 256>>>(pS0, 64, pRst, pFh, 128);
        copyInFeats<<<(NROWS*256 + 255)/256, 256>>>(pFru, pFh, 64, 128);
        tsplitK<<<dim3(32,2,32), dim3(32,32)>>>(pRst, pRst, 64);
        mmaDiffuse<<<dim3(16,8,4), 256, MMAD_SMEM>>>(64, pFh, 128, 64);
        mixH<<<dim3(1,512), 256>>>(pFh, 640, Wh1, bh1, pS1, 64);

        projK<<<(NROWS + 255)/256, 256>>>(Wp, bp, out + (size_t)t*NROWS*OUTD);
    }
}

// round 6
// speedup vs baseline: 2.2176x; 1.1000x over previous
#include <cuda_runtime.h>
#include <cuda_bf16.h>
#include <math.h>
#include <stdint.h>

#define NN 1024
#define BATCH 32
#define HID 64
#define OUTD 2
#define STEPS 12
#define NROWS (BATCH*NN)
typedef __nv_bfloat16 bf16;

// ---------------- PTX helpers ---------------------------------------------
__device__ __forceinline__ uint32_t smem_u32(const void* p) {
    uint32_t a;
    asm("{ .reg .u64 t; cvta.to.shared.u64 t, %1; cvt.u32.u64 %0, t; }" : "=r"(a) : "l"(p));
    return a;
}
__device__ __forceinline__ void cp16(uint32_t sa, const void* g) {
    asm volatile("cp.async.cg.shared.global [%0], [%1], 16;" :: "r"(sa), "l"(g) : "memory");
}
#define CP_COMMIT() asm volatile("cp.async.commit_group;" ::: "memory")
#define CP_WAIT(n)  asm volatile("cp.async.wait_group %0;" :: "n"(n) : "memory")
#define LDSM4(r, a) asm volatile( \
    "ldmatrix.sync.aligned.m8n8.x4.shared.b16 {%0,%1,%2,%3}, [%4];" \
    : "=r"((r)[0]), "=r"((r)[1]), "=r"((r)[2]), "=r"((r)[3]) : "r"(a))
#define LDSM2(r, a) asm volatile( \
    "ldmatrix.sync.aligned.m8n8.x2.shared.b16 {%0,%1}, [%2];" \
    : "=r"((r)[0]), "=r"((r)[1]) : "r"(a))
#define MMA16816(d, a, b) asm volatile( \
    "mma.sync.aligned.m16n8k16.row.col.f32.bf16.bf16.f32 " \
    "{%0,%1,%2,%3},{%4,%5,%6,%7},{%8,%9},{%0,%1,%2,%3};" \
    : "+f"((d)[0]), "+f"((d)[1]), "+f"((d)[2]), "+f"((d)[3]) \
    : "r"((a)[0]), "r"((a)[1]), "r"((a)[2]), "r"((a)[3]), "r"((b)[0]), "r"((b)[1]))

__device__ __forceinline__ void bsplit(float v, bf16& h, bf16& l) {
    h = __float2bfloat16(v);
    l = __float2bfloat16(v - __bfloat162float(h));
}

// ---------------- scratch -------------------------------------------------
__device__ float g_M[2u*NN*NN];
__device__ float g_state0[NROWS*HID];
__device__ float g_state1[NROWS*HID];
__device__ float g_decin [NROWS*OUTD];
__device__ float g_u     [NROWS*HID];
__device__ float g_rstate[NROWS*HID];
__device__ bf16 g_FAh[(size_t)NROWS*640], g_FAl[(size_t)NROWS*640];
__device__ bf16 g_FBh[(size_t)NROWS*640], g_FBl[(size_t)NROWS*640];
__device__ bf16 g_oph[(size_t)4*NN*NN], g_opl[(size_t)4*NN*NN];
__device__ bf16 g_Xh[(size_t)4096*NN],  g_Xl[(size_t)4096*NN];
__device__ bf16 g_Wru0h[128*352], g_Wru0l[128*352];
__device__ bf16 g_Wh0h [64*352],  g_Wh0l [64*352];
__device__ bf16 g_Wru1h[128*640], g_Wru1l[128*640];
__device__ bf16 g_Wh1h [64*640],  g_Wh1l [64*640];

// ---------------- small kernels ------------------------------------------
__global__ void initK(const float* __restrict__ enc) {
    int i = blockIdx.x*blockDim.x + threadIdx.x;
    const int SZ = NROWS*HID;
    if (i < SZ) { g_state0[i] = enc[i]; g_state1[i] = enc[SZ+i]; }
    if (i < NROWS*OUTD) g_decin[i] = 0.f;
}

__global__ void precomputeM(const float* __restrict__ sup) {
    const int s = blockIdx.z;
    const float* __restrict__ S = sup + (size_t)s*NN*NN;
    float* __restrict__ Mo = g_M + (size_t)s*NN*NN;
    __shared__ float As[16][64], Bs[16][64];
    const int tid = threadIdx.x, tx = tid & 15, ty = tid >> 4;
    const int n0 = blockIdx.y*64, j0 = blockIdx.x*64;
    const int ar = tid >> 2, aq = (tid & 3)*4, br = tid >> 4, bq = (tid & 15)*4;
    float acc[4][4] = {};
    for (int kt = 0; kt < NN; kt += 16) {
        float4 av = *(const float4*)(S + (size_t)(n0+ar)*NN + kt + aq);
        As[aq][ar]=av.x; As[aq+1][ar]=av.y; As[aq+2][ar]=av.z; As[aq+3][ar]=av.w;
        *(float4*)&Bs[br][bq] = *(const float4*)(S + (size_t)(kt+br)*NN + j0 + bq);
        __syncthreads();
        #pragma unroll
        for (int k = 0; k < 16; k++) {
            float4 a = *(float4*)&As[k][ty*4], b = *(float4*)&Bs[k][tx*4];
            float arr[4]={a.x,a.y,a.z,a.w}, brr[4]={b.x,b.y,b.z,b.w};
            #pragma unroll
            for (int i=0;i<4;i++)
                #pragma unroll
                for (int j=0;j<4;j++) acc[i][j] += arr[i]*brr[j];
        }
        __syncthreads();
    }
    #pragma unroll
    for (int i=0;i<4;i++) { int n=n0+ty*4+i;
        #pragma unroll
        for (int j=0;j<4;j++) { int jc=j0+tx*4+j;
            Mo[(size_t)n*NN+jc] = 2.f*acc[i][j] - (n==jc?1.f:0.f); } }
}

__global__ void splitOpsK(const float* __restrict__ sup) {
    size_t i = (size_t)blockIdx.x*blockDim.x + threadIdx.x;
    if (i >= (size_t)4*NN*NN) return;
    int op = (int)(i >> 20); size_t r = i & ((size_t)NN*NN - 1);
    const float* src = (op==0) ? sup : (op==1) ? g_M :
                       (op==2) ? sup + (size_t)NN*NN : g_M + (size_t)NN*NN;
    bf16 h, l; bsplit(src[r], h, l);
    g_oph[i] = h; g_opl[i] = l;
}

// weights: [5][Ct][O] row-major -> transposed/split [O][KP], zero-padded
__global__ void wsplitT(const float* __restrict__ W, bf16* __restrict__ Th,
                        bf16* __restrict__ Tl, int Ct, int O, int KP) {
    int i = blockIdx.x*blockDim.x + threadIdx.x;
    if (i >= O*KP) return;
    int o = i / KP, k = i % KP;
    float v = (k < 5*Ct) ? W[(size_t)k*O + o] : 0.f;
    bf16 h, l; bsplit(v, h, l);
    Th[i] = h; Tl[i] = l;
}

// transpose+split states: Xc[(b*Ct + c)*NN + n]
__global__ void tsplitK(const float* __restrict__ s0, const float* __restrict__ s1, int Ct) {
    __shared__ float t[32][33];
    int b = blockIdx.z, n0 = blockIdx.x*32, c0 = blockIdx.y*32;
    int tx = threadIdx.x, ty = threadIdx.y;
    int c = c0 + tx;
    const float* sp = (c < 64) ? s0 : s1;
    t[ty][tx] = sp[((size_t)(b*NN + n0 + ty))*HID + (c & 63)];
    __syncthreads();
    float v = t[tx][ty];
    int n = n0 + tx, cw = c0 + ty;
    bf16 h, l; bsplit(v, h, l);
    size_t o = ((size_t)(b*Ct + cw))*NN + n;
    g_Xh[o] = h; g_Xl[o] = l;
}

// ---------------- diffusion: mma.sync, 512 threads, 16 warps -------------
#define LDP 40
#define MATB (128*LDP*2)
#define STAGEB (4*MATB)
#define MMAD_SMEM (2*STAGEB)

__device__ __forceinline__ void issueStage(uint32_t sbase, int buf, int kt, int tid,
    const bf16* Ah, const bf16* Al, const bf16* Bh, const bf16* Bl) {
    uint32_t so = sbase + buf*STAGEB;
    int row = tid >> 2, kq = (tid & 3)*8;
    uint32_t soff = (uint32_t)(row*(LDP*2) + kq*2);
    size_t go = (size_t)row*NN + kt + kq;
    cp16(so + soff,          Ah + go);
    cp16(so + MATB + soff,   Al + go);
    cp16(so + 2*MATB + soff, Bh + go);
    cp16(so + 3*MATB + soff, Bl + go);
    CP_COMMIT();
}

__global__ void __launch_bounds__(512)
mmaDiffuse(int Ctile, bf16* __restrict__ Fh, bf16* __restrict__ Fl,
           int Ctot, int KP, int colOff) {
    extern __shared__ bf16 sm[];
    const int tid = threadIdx.x, wid = tid >> 5, lane = tid & 31;
    const int f = blockIdx.z, n0 = blockIdx.y*128, j0 = blockIdx.x*128;
    const bf16* __restrict__ Ah = g_oph + ((size_t)f*NN + n0)*NN;
    const bf16* __restrict__ Al = g_opl + ((size_t)f*NN + n0)*NN;
    const bf16* __restrict__ Bh = g_Xh + (size_t)j0*NN;
    const bf16* __restrict__ Bl = g_Xl + (size_t)j0*NN;
    uint32_t sbase = smem_u32(sm);
    const int wm = wid >> 2, wn = wid & 3;     // 4x4 warps, tile 32x32
    float acc[2][4][4] = {};

    issueStage(sbase, 0, 0, tid, Ah, Al, Bh, Bl);
    for (int ch = 0; ch < 32; ch++) {
        if (ch + 1 < 32) { issueStage(sbase, (ch+1)&1, (ch+1)*32, tid, Ah, Al, Bh, Bl); CP_WAIT(1); }
        else CP_WAIT(0);
        __syncthreads();
        uint32_t Ab  = sbase + (ch&1)*STAGEB;
        uint32_t Alb = Ab + MATB, Bb = Ab + 2*MATB, Blb = Ab + 3*MATB;
        #pragma unroll
        for (int k16 = 0; k16 < 2; k16++) {
            const int kk = k16*16;
            uint32_t ah[2][4], al[2][4], bh[4][2], bl[4][2];
            #pragma unroll
            for (int im = 0; im < 2; im++) {
                int row = wm*32 + im*16 + (lane & 15);
                int col = kk + ((lane >> 4) << 3);
                uint32_t off = (uint32_t)(row*(LDP*2) + col*2);
                LDSM4(ah[im], Ab + off);
                LDSM4(al[im], Alb + off);
            }
            #pragma unroll
            for (int in = 0; in < 4; in++) {
                int row = wn*32 + in*8 + (lane & 7);
                int col = kk + (((lane >> 3) & 1) << 3);
                uint32_t off = (uint32_t)(row*(LDP*2) + col*2);
                LDSM2(bh[in], Bb + off);
                LDSM2(bl[in], Blb + off);
            }
            #pragma unroll
            for (int im = 0; im < 2; im++)
                #pragma unroll
                for (int in = 0; in < 4; in++) {
                    MMA16816(acc[im][in], ah[im], bh[in]);
                    MMA16816(acc[im][in], ah[im], bl[in]);
                    MMA16816(acc[im][in], al[im], bh[in]);
                }
        }
        __syncthreads();
    }
    const int m = f + 1;
    const int r = lane >> 2, cp2 = (lane & 3)*2;
    #pragma unroll
    for (int im = 0; im < 2; im++) {
        #pragma unroll
        for (int in = 0; in < 4; in++) {
            int jG = j0 + wn*32 + in*8 + cp2;
            int b = jG / Ctile, c = jG % Ctile;
            int nG = n0 + wm*32 + im*16 + r;
            size_t base = (size_t)(b*NN + nG)*KP + m*Ctot + colOff + c;
            bf16 h0,l0,h1,l1;
            bsplit(acc[im][in][0], h0, l0); bsplit(acc[im][in][1], h1, l1);
            __nv_bfloat162 hv; hv.x=h0; hv.y=h1;
            __nv_bfloat162 lv; lv.x=l0; lv.y=l1;
            *(__nv_bfloat162*)(Fh + base) = hv;
            *(__nv_bfloat162*)(Fl + base) = lv;
            bsplit(acc[im][in][2], h0, l0); bsplit(acc[im][in][3], h1, l1);
            hv.x=h0; hv.y=h1; lv.x=l0; lv.y=l1;
            *(__nv_bfloat162*)(Fh + base + (size_t)8*KP) = hv;
            *(__nv_bfloat162*)(Fl + base + (size_t)8*KP) = lv;
        }
    }
}

// ---------------- FFMA diffusion for decin (C=2) -------------------------
__global__ void diffuse2K(const float* __restrict__ X, bf16* __restrict__ Fh,
                          bf16* __restrict__ Fl, int KP, const float* __restrict__ sup) {
    const int f = blockIdx.z;
    const float* __restrict__ Op = (f==0) ? sup : (f==1) ? g_M :
        (f==2) ? sup + (size_t)NN*NN : g_M + (size_t)NN*NN;
    const int NC = BATCH*2;
    __shared__ float As[16][64], Bs[16][64];
    const int tid = threadIdx.x, tx = tid & 15, ty = tid >> 4;
    const int n0 = blockIdx.y*64;
    const int ar = tid >> 2, aq = (tid & 3)*4, br = tid >> 4, bq = (tid & 15)*4;
    float acc[4][4] = {};
    for (int kt = 0; kt < NN; kt += 16) {
        float4 av = *(const float4*)(Op + (size_t)(n0+ar)*NN + kt + aq);
        As[aq][ar]=av.x; As[aq+1][ar]=av.y; As[aq+2][ar]=av.z; As[aq+3][ar]=av.w;
        #pragma unroll
        for (int q = 0; q < 4; q++) {
            int j = bq + q; float v = 0.f;
            if (j < NC) v = X[((size_t)((j>>1)*NN + kt + br))*2 + (j & 1)];
            Bs[br][bq+q] = v;
        }
        __syncthreads();
        #pragma unroll
        for (int k = 0; k < 16; k++) {
            float4 a = *(float4*)&As[k][ty*4], b = *(float4*)&Bs[k][tx*4];
            float arr[4]={a.x,a.y,a.z,a.w}, brr[4]={b.x,b.y,b.z,b.w};
            #pragma unroll
            for (int i=0;i<4;i++)
                #pragma unroll
                for (int j=0;j<4;j++) acc[i][j] += arr[i]*brr[j];
        }
        __syncthreads();
    }
    const int m = f + 1;
    #pragma unroll
    for (int i=0;i<4;i++) { int n=n0+ty*4+i;
        #pragma unroll
        for (int j=0;j<4;j++) { int jc=tx*4+j;
            if (jc < NC) {
                size_t o = (size_t)((jc>>1)*NN + n)*KP + m*66 + (jc & 1);
                bf16 h, l; bsplit(acc[i][j], h, l);
                Fh[o] = h; Fl[o] = l; } } }
}

// ---------------- m0 + feature copies ------------------------------------
__global__ void copyM0(const float* __restrict__ inp, int Cin,
                       const float* __restrict__ st,
                       bf16* __restrict__ Fh, bf16* __restrict__ Fl,
                       int Ctot, int KP) {
    int i = blockIdx.x*blockDim.x + threadIdx.x;
    if (i >= NROWS*Ctot) return;
    int c = i % Ctot, row = i / Ctot;
    float v = (c < Cin) ? inp[row*Cin + c] : st[row*HID + c - Cin];
    bf16 h, l; bsplit(v, h, l);
    size_t o = (size_t)row*KP + c;
    Fh[o] = h; Fl[o] = l;
}
__global__ void copyInFeats(const bf16* __restrict__ Fsh, const bf16* __restrict__ Fsl,
                            bf16* __restrict__ Fdh, bf16* __restrict__ Fdl,
                            int Cin, int Ctot, int KP) {
    int i = blockIdx.x*blockDim.x + threadIdx.x;
    if (i >= NROWS*4*Cin) return;
    int c = i % Cin; int t = i / Cin;
    int m = (t & 3) + 1; int row = t >> 2;
    size_t o = (size_t)row*KP + m*Ctot + c;
    Fdh[o] = Fsh[o]; Fdl[o] = Fsl[o];
}

// ---------------- tensor-core mixing + fused GRU -------------------------
#define MLDP 40
#define MA_B (128*MLDP*2)
#define MB_B (64*MLDP*2)
#define MSTAGE (2*MA_B + 2*MB_B)
#define MIX_SMEM (2*MSTAGE)

template<int MODE>   // 0: RU (sigmoid -> rstate/u), 1: H (tanh -> state upd)
__global__ void __launch_bounds__(256)
mixTC(const bf16* __restrict__ Fh, const bf16* __restrict__ Fl, int KP, int nCh,
      const bf16* __restrict__ Wh, const bf16* __restrict__ Wl,
      const float* __restrict__ bias, const float* __restrict__ stateIn,
      float* __restrict__ stateOut) {
    extern __shared__ char smc[];
    uint32_t sb = smem_u32(smc);
    const int tid = threadIdx.x, wid = tid >> 5, lane = tid & 31;
    const int r0 = blockIdx.y*128, o0 = blockIdx.x*64;
    const int wm = wid >> 1, wn = wid & 1;
    float acc[2][4][4] = {};

    #define MIX_ISSUE(buf, kt) do { \
        uint32_t s_ = sb + (buf)*MSTAGE; \
        _Pragma("unroll") \
        for (int it = 0; it < 2; it++) { \
            int v_ = tid + it*256; \
            int row_ = v_ >> 2, kq_ = (v_ & 3)*8; \
            uint32_t off_ = (uint32_t)(row_*(MLDP*2) + kq_*2); \
            size_t g_ = (size_t)(r0+row_)*KP + (kt) + kq_; \
            cp16(s_ + off_, Fh + g_); \
            cp16(s_ + MA_B + off_, Fl + g_); \
        } \
        { int row_ = tid >> 2, kq_ = (tid & 3)*8; \
          uint32_t off_ = (uint32_t)(row_*(MLDP*2) + kq_*2); \
          size_t g_ = (size_t)(o0+row_)*KP + (kt) + kq_; \
          cp16(s_ + 2*MA_B + off_, Wh + g_); \
          cp16(s_ + 2*MA_B + MB_B + off_, Wl + g_); } \
        CP_COMMIT(); \
    } while (0)

    MIX_ISSUE(0, 0);
    for (int ch = 0; ch < nCh; ch++) {
        if (ch + 1 < nCh) { MIX_ISSUE((ch+1)&1, (ch+1)*32); CP_WAIT(1); }
        else CP_WAIT(0);
        __syncthreads();
        uint32_t Ab = sb + (ch&1)*MSTAGE, Alb = Ab + MA_B, Bb = Ab + 2*MA_B, Blb = Bb + MB_B;
        #pragma unroll
        for (int k16 = 0; k16 < 2; k16++) {
            const int kk = k16*16;
            uint32_t ah[2][4], al[2][4], bh[4][2], bl[4][2];
            #pragma unroll
            for (int im = 0; im < 2; im++) {
                int row = wm*32 + im*16 + (lane & 15);
                int col = kk + ((lane >> 4) << 3);
                uint32_t off = (uint32_t)(row*(MLDP*2) + col*2);
                LDSM4(ah[im], Ab + off);
                LDSM4(al[im], Alb + off);
            }
            #pragma unroll
            for (int in = 0; in < 4; in++) {
                int row = wn*32 + in*8 + (lane & 7);
                int col = kk + (((lane >> 3) & 1) << 3);
                uint32_t off = (uint32_t)(row*(MLDP*2) + col*2);
                LDSM2(bh[in], Bb + off);
                LDSM2(bl[in], Blb + off);
            }
            #pragma unroll
            for (int im = 0; im < 2; im++)
                #pragma unroll
                for (int in = 0; in < 4; in++) {
                    MMA16816(acc[im][in], ah[im], bh[in]);
                    MMA16816(acc[im][in], ah[im], bl[in]);
                    MMA16816(acc[im][in], al[im], bh[in]);
                }
        }
        __syncthreads();
    }
    const int r = lane >> 2, cp2 = (lane & 3)*2;
    #pragma unroll
    for (int im = 0; im < 2; im++) {
        #pragma unroll
        for (int in = 0; in < 4; in++) {
            int o = o0 + wn*32 + in*8 + cp2;
            float b0 = bias[o], b1 = bias[o+1];
            #pragma unroll
            for (int hh = 0; hh < 2; hh++) {
                int row = r0 + wm*32 + im*16 + r + hh*8;
                float v0 = acc[im][in][hh*2], v1 = acc[im][in][hh*2+1];
                if (MODE == 0) {
                    float gg0 = 1.f/(1.f + expf(-(v0 + b0)));
                    float gg1 = 1.f/(1.f + expf(-(v1 + b1)));
                    if (o < HID) {
                        g_rstate[row*HID + o]   = gg0 * stateIn[row*HID + o];
                        g_rstate[row*HID + o+1] = gg1 * stateIn[row*HID + o+1];
                    } else {
                        g_u[row*HID + o - HID]     = gg0;
                        g_u[row*HID + o + 1 - HID] = gg1;
                    }
                } else {
                    float hT0 = tanhf(v0 + b0), hT1 = tanhf(v1 + b1);
                    float u0 = g_u[row*HID + o], u1 = g_u[row*HID + o+1];
                    float s0 = stateOut[row*HID + o], s1 = stateOut[row*HID + o+1];
                    stateOut[row*HID + o]   = u0*s0 + (1.f - u0)*hT0;
                    stateOut[row*HID + o+1] = u1*s1 + (1.f - u1)*hT1;
                }
            }
        }
    }
}

__global__ void projK(const float* __restrict__ Wp, const float* __restrict__ bp,
                      float* __restrict__ out_t) {
    int row = blockIdx.x*blockDim.x + threadIdx.x;
    if (row >= NROWS) return;
    const float* s = g_state1 + (size_t)row*HID;
    float a0 = bp[0], a1 = bp[1];
    #pragma unroll
    for (int h = 0; h < HID; h++) { float v = s[h]; a0 += v*Wp[h*2]; a1 += v*Wp[h*2+1]; }
    out_t[row*2] = a0; out_t[row*2+1] = a1;
    g_decin[row*2] = a0; g_decin[row*2+1] = a1;
}

// -------------------------------------------------------------------------
extern "C" void kernel_launch(void* const* d_in, const int* in_sizes, int n_in,
                              void* d_out, int out_size) {
    const float* enc  = (const float*)d_in[0];
    const float* sup  = (const float*)d_in[1];
    const float* Wru0 = (const float*)d_in[2];
    const float* bru0 = (const float*)d_in[3];
    const float* Wh0  = (const float*)d_in[4];
    const float* bh0  = (const float*)d_in[5];
    const float* Wru1 = (const float*)d_in[6];
    const float* bru1 = (const float*)d_in[7];
    const float* Wh1  = (const float*)d_in[8];
    const float* bh1  = (const float*)d_in[9];
    const float* Wp   = (const float*)d_in[10];
    const float* bp   = (const float*)d_in[11];
    float* out = (float*)d_out;

    void *pv;
    cudaGetSymbolAddress(&pv, g_state0); float* pS0  = (float*)pv;
    cudaGetSymbolAddress(&pv, g_state1); float* pS1  = (float*)pv;
    cudaGetSymbolAddress(&pv, g_decin);  float* pDec = (float*)pv;
    cudaGetSymbolAddress(&pv, g_rstate); float* pRst = (float*)pv;
    cudaGetSymbolAddress(&pv, g_FAh); bf16* FAh = (bf16*)pv;
    cudaGetSymbolAddress(&pv, g_FAl); bf16* FAl = (bf16*)pv;
    cudaGetSymbolAddress(&pv, g_FBh); bf16* FBh = (bf16*)pv;
    cudaGetSymbolAddress(&pv, g_FBl); bf16* FBl = (bf16*)pv;
    cudaGetSymbolAddress(&pv, g_Wru0h); bf16* Wru0h = (bf16*)pv;
    cudaGetSymbolAddress(&pv, g_Wru0l); bf16* Wru0l = (bf16*)pv;
    cudaGetSymbolAddress(&pv, g_Wh0h);  bf16* Wh0h  = (bf16*)pv;
    cudaGetSymbolAddress(&pv, g_Wh0l);  bf16* Wh0l  = (bf16*)pv;
    cudaGetSymbolAddress(&pv, g_Wru1h); bf16* Wru1h = (bf16*)pv;
    cudaGetSymbolAddress(&pv, g_Wru1l); bf16* Wru1l = (bf16*)pv;
    cudaGetSymbolAddress(&pv, g_Wh1h);  bf16* Wh1h  = (bf16*)pv;
    cudaGetSymbolAddress(&pv, g_Wh1l);  bf16* Wh1l  = (bf16*)pv;

    cudaFuncSetAttribute(mmaDiffuse, cudaFuncAttributeMaxDynamicSharedMemorySize, MMAD_SMEM);
    cudaFuncSetAttribute(mixTC<0>, cudaFuncAttributeMaxDynamicSharedMemorySize, MIX_SMEM);
    cudaFuncSetAttribute(mixTC<1>, cudaFuncAttributeMaxDynamicSharedMemorySize, MIX_SMEM);

    initK<<<(NROWS*HID + 255)/256, 256>>>(enc);
    precomputeM<<<dim3(16,16,2), 256>>>(sup);
    splitOpsK<<<(int)(((size_t)4*NN*NN + 255)/256), 256>>>(sup);
    wsplitT<<<(128*352 + 255)/256, 256>>>(Wru0, Wru0h, Wru0l, 66, 128, 352);
    wsplitT<<<(64*352 + 255)/256, 256>>>(Wh0, Wh0h, Wh0l, 66, 64, 352);
    wsplitT<<<(128*640 + 255)/256, 256>>>(Wru1, Wru1h, Wru1l, 128, 128, 640);
    wsplitT<<<(64*640 + 255)/256, 256>>>(Wh1, Wh1h, Wh1l, 128, 64, 640);

    for (int t = 0; t < STEPS; t++) {
        // layer 0 RU: x=[decin|state0], Ctot=66, KP=352
        copyM0<<<(NROWS*66 + 255)/256, 256>>>(pDec, 2, pS0, FAh, FAl, 66, 352);
        diffuse2K<<<dim3(1,16,4), 256>>>(pDec, FAh, FAl, 352, sup);
        tsplitK<<<dim3(32,2,32), dim3(32,32)>>>(pS0, pS0, 64);
        mmaDiffuse<<<dim3(16,8,4), 512, MMAD_SMEM>>>(64, FAh, FAl, 66, 352, 2);
        mixTC<0><<<dim3(2,256), 256, MIX_SMEM>>>(FAh, FAl, 352, 11, Wru0h, Wru0l, bru0, pS0, 0);
        // layer 0 H: x2=[decin|r*state0]
        copyM0<<<(NROWS*66 + 255)/256, 256>>>(pDec, 2, pRst, FBh, FBl, 66, 352);
        copyInFeats<<<(NROWS*8 + 255)/256, 256>>>(FAh, FAl, FBh, FBl, 2, 66, 352);
        tsplitK<<<dim3(32,2,32), dim3(32,32)>>>(pRst, pRst, 64);
        mmaDiffuse<<<dim3(16,8,4), 512, MMAD_SMEM>>>(64, FBh, FBl, 66, 352, 2);
        mixTC<1><<<dim3(1,256), 256, MIX_SMEM>>>(FBh, FBl, 352, 11, Wh0h, Wh0l, bh0, 0, pS0);

        // layer 1 RU: x=[state0|state1], Ctot=128, KP=640
        copyM0<<<(NROWS*128 + 255)/256, 256>>>(pS0, 64, pS1, FAh, FAl, 128, 640);
        tsplitK<<<dim3(32,4,32), dim3(32,32)>>>(pS0, pS1, 128);
        mmaDiffuse<<<dim3(32,8,4), 512, MMAD_SMEM>>>(128, FAh, FAl, 128, 640, 0);
        mixTC<0><<<dim3(2,256), 256, MIX_SMEM>>>(FAh, FAl, 640, 20, Wru1h, Wru1l, bru1, pS1, 0);
        // layer 1 H: x2=[state0|r*state1]
        copyM0<<<(NROWS*128 + 255)/256, 256>>>(pS0, 64, pRst, FBh, FBl, 128, 640);
        copyInFeats<<<(NROWS*256 + 255)/256, 256>>>(FAh, FAl, FBh, FBl, 64, 128, 640);
        tsplitK<<<dim3(32,2,32), dim3(32,32)>>>(pRst, pRst, 64);
        mmaDiffuse<<<dim3(16,8,4), 512, MMAD_SMEM>>>(64, FBh, FBl, 128, 640, 64);
        mixTC<1><<<dim3(1,256), 256, MIX_SMEM>>>(FBh, FBl, 640, 20, Wh1h, Wh1l, bh1, 0, pS1);

        projK<<<(NROWS + 255)/256, 256>>>(Wp, bp, out + (size_t)t*NROWS*OUTD);
    }
}

// round 7
// speedup vs baseline: 2.8362x; 1.2790x over previous
#include <cuda_runtime.h>
#include <cuda_bf16.h>
#include <math.h>
#include <stdint.h>

#define NN 1024
#define BATCH 32
#define HID 64
#define OUTD 2
#define STEPS 12
#define NROWS (BATCH*NN)
typedef __nv_bfloat16 bf16;

// ---------------- PTX helpers ---------------------------------------------
__device__ __forceinline__ uint32_t smem_u32(const void* p) {
    uint32_t a;
    asm("{ .reg .u64 t; cvta.to.shared.u64 t, %1; cvt.u32.u64 %0, t; }" : "=r"(a) : "l"(p));
    return a;
}
__device__ __forceinline__ void cp16(uint32_t sa, const void* g) {
    asm volatile("cp.async.cg.shared.global [%0], [%1], 16;" :: "r"(sa), "l"(g) : "memory");
}
#define CP_COMMIT() asm volatile("cp.async.commit_group;" ::: "memory")
#define CP_WAIT(n)  asm volatile("cp.async.wait_group %0;" :: "n"(n) : "memory")
#define LDSM4(r, a) asm volatile( \
    "ldmatrix.sync.aligned.m8n8.x4.shared.b16 {%0,%1,%2,%3}, [%4];" \
    : "=r"((r)[0]), "=r"((r)[1]), "=r"((r)[2]), "=r"((r)[3]) : "r"(a))
#define LDSM2(r, a) asm volatile( \
    "ldmatrix.sync.aligned.m8n8.x2.shared.b16 {%0,%1}, [%2];" \
    : "=r"((r)[0]), "=r"((r)[1]) : "r"(a))
#define MMA16816(d, a, b) asm volatile( \
    "mma.sync.aligned.m16n8k16.row.col.f32.bf16.bf16.f32 " \
    "{%0,%1,%2,%3},{%4,%5,%6,%7},{%8,%9},{%0,%1,%2,%3};" \
    : "+f"((d)[0]), "+f"((d)[1]), "+f"((d)[2]), "+f"((d)[3]) \
    : "r"((a)[0]), "r"((a)[1]), "r"((a)[2]), "r"((a)[3]), "r"((b)[0]), "r"((b)[1]))
#define MMAS8(d, a, b) asm volatile( \
    "mma.sync.aligned.m16n8k32.row.col.s32.s8.s8.s32 " \
    "{%0,%1,%2,%3},{%4,%5,%6,%7},{%8,%9},{%0,%1,%2,%3};" \
    : "+r"((d)[0]), "+r"((d)[1]), "+r"((d)[2]), "+r"((d)[3]) \
    : "r"((a)[0]), "r"((a)[1]), "r"((a)[2]), "r"((a)[3]), "r"((b)[0]), "r"((b)[1]))

__device__ __forceinline__ void bsplit(float v, bf16& h, bf16& l) {
    h = __float2bfloat16(v);
    l = __float2bfloat16(v - __bfloat162float(h));
}

// ---------------- scratch -------------------------------------------------
__device__ float g_M[2u*NN*NN];
__device__ float g_state0[NROWS*HID];
__device__ float g_state1[NROWS*HID];
__device__ float g_decin [NROWS*OUTD];
__device__ float g_u     [NROWS*HID];
__device__ float g_rstate[NROWS*HID];
__device__ bf16 g_FAh[(size_t)NROWS*640], g_FAl[(size_t)NROWS*640];
__device__ bf16 g_FBh[(size_t)NROWS*640], g_FBl[(size_t)NROWS*640];
__device__ int8_t g_Aq1[(size_t)4*NN*NN], g_Aq2[(size_t)4*NN*NN];
__device__ int8_t g_Xq1[(size_t)4096*NN], g_Xq2[(size_t)4096*NN];
__device__ float g_sA[4*NN];
__device__ float g_sB[4096], g_rB[4096];
__device__ bf16 g_Wru0h[128*352], g_Wru0l[128*352];
__device__ bf16 g_Wh0h [64*352],  g_Wh0l [64*352];
__device__ bf16 g_Wru1h[128*640], g_Wru1l[128*640];
__device__ bf16 g_Wh1h [64*640],  g_Wh1l [64*640];

// ---------------- init / precompute ---------------------------------------
__global__ void initK(const float* __restrict__ enc) {
    int i = blockIdx.x*blockDim.x + threadIdx.x;
    const int SZ = NROWS*HID;
    if (i < SZ) { g_state0[i] = enc[i]; g_state1[i] = enc[SZ+i]; }
    if (i < NROWS*OUTD) g_decin[i] = 0.f;
}

__global__ void precomputeM(const float* __restrict__ sup) {
    const int s = blockIdx.z;
    const float* __restrict__ S = sup + (size_t)s*NN*NN;
    float* __restrict__ Mo = g_M + (size_t)s*NN*NN;
    __shared__ float As[16][64], Bs[16][64];
    const int tid = threadIdx.x, tx = tid & 15, ty = tid >> 4;
    const int n0 = blockIdx.y*64, j0 = blockIdx.x*64;
    const int ar = tid >> 2, aq = (tid & 3)*4, br = tid >> 4, bq = (tid & 15)*4;
    float acc[4][4] = {};
    for (int kt = 0; kt < NN; kt += 16) {
        float4 av = *(const float4*)(S + (size_t)(n0+ar)*NN + kt + aq);
        As[aq][ar]=av.x; As[aq+1][ar]=av.y; As[aq+2][ar]=av.z; As[aq+3][ar]=av.w;
        *(float4*)&Bs[br][bq] = *(const float4*)(S + (size_t)(kt+br)*NN + j0 + bq);
        __syncthreads();
        #pragma unroll
        for (int k = 0; k < 16; k++) {
            float4 a = *(float4*)&As[k][ty*4], b = *(float4*)&Bs[k][tx*4];
            float arr[4]={a.x,a.y,a.z,a.w}, brr[4]={b.x,b.y,b.z,b.w};
            #pragma unroll
            for (int i=0;i<4;i++)
                #pragma unroll
                for (int j=0;j<4;j++) acc[i][j] += arr[i]*brr[j];
        }
        __syncthreads();
    }
    #pragma unroll
    for (int i=0;i<4;i++) { int n=n0+ty*4+i;
        #pragma unroll
        for (int j=0;j<4;j++) { int jc=j0+tx*4+j;
            Mo[(size_t)n*NN+jc] = 2.f*acc[i][j] - (n==jc?1.f:0.f); } }
}

// quantize operator rows to 2-limb int8 with per-row scale (once)
__global__ void opQuant(const float* __restrict__ sup) {
    const int n = blockIdx.x, f = blockIdx.y, tid = threadIdx.x;
    const float* src = (f==0) ? sup : (f==1) ? g_M :
                       (f==2) ? sup + (size_t)NN*NN : g_M + (size_t)NN*NN;
    float4 v = *(const float4*)(src + (size_t)n*NN + tid*4);
    float mx = fmaxf(fmaxf(fabsf(v.x),fabsf(v.y)), fmaxf(fabsf(v.z),fabsf(v.w)));
    #pragma unroll
    for (int o = 16; o; o >>= 1) mx = fmaxf(mx, __shfl_xor_sync(0xffffffffu, mx, o));
    __shared__ float w[8]; __shared__ float sInv;
    if ((tid & 31) == 0) w[tid >> 5] = mx;
    __syncthreads();
    if (tid == 0) {
        float m = w[0];
        #pragma unroll
        for (int i = 1; i < 8; i++) m = fmaxf(m, w[i]);
        g_sA[f*NN + n] = (m > 0.f) ? m/127.f : 1.f;
        sInv = (m > 0.f) ? 127.f/m : 0.f;
    }
    __syncthreads();
    float inv = sInv;
    char4 q1, q2;
    float xs[4] = {v.x*inv, v.y*inv, v.z*inv, v.w*inv};
    int a1[4], a2[4];
    #pragma unroll
    for (int i = 0; i < 4; i++) {
        int q = __float2int_rn(xs[i]);
        q = q > 127 ? 127 : (q < -127 ? -127 : q);
        a1[i] = q;
        a2[i] = __float2int_rn((xs[i] - (float)q)*128.f);
    }
    q1.x=a1[0];q1.y=a1[1];q1.z=a1[2];q1.w=a1[3];
    q2.x=a2[0];q2.y=a2[1];q2.z=a2[2];q2.w=a2[3];
    size_t o = ((size_t)f*NN + n)*NN + tid*4;
    *(char4*)(g_Aq1 + o) = q1;
    *(char4*)(g_Aq2 + o) = q2;
}

// per-(b,c) max of conv input -> scale
__global__ void colMaxK(const float* __restrict__ inp, int Cin,
                        const float* __restrict__ st, int Ct) {
    int b = blockIdx.x, c = threadIdx.x, ty = threadIdx.y;
    __shared__ float red[4][128];
    float mx = 0.f;
    if (c < Ct) {
        for (int n = ty; n < NN; n += 4) {
            size_t row = (size_t)b*NN + n;
            float v = (c < Cin) ? inp[row*Cin + c] : st[row*HID + (c - Cin)];
            mx = fmaxf(mx, fabsf(v));
        }
    }
    red[ty][c] = mx;
    __syncthreads();
    if (ty == 0 && c < Ct) {
        mx = fmaxf(fmaxf(red[0][c], red[1][c]), fmaxf(red[2][c], red[3][c]));
        g_sB[b*Ct + c] = (mx > 0.f) ? mx/127.f : 1.f;
        g_rB[b*Ct + c] = (mx > 0.f) ? 127.f/mx : 0.f;
    }
}

// transpose + 2-limb int8 quantize: Xq[(b*Ct+c)*NN + n]
__global__ void tsplitQ(const float* __restrict__ inp, int Cin,
                        const float* __restrict__ st, int Ct) {
    __shared__ float t[32][33];
    int b = blockIdx.z, n0 = blockIdx.x*32, c0 = blockIdx.y*32;
    int tx = threadIdx.x, ty = threadIdx.y;
    int c = c0 + tx;
    float v = 0.f;
    size_t row = (size_t)b*NN + n0 + ty;
    if (c < Ct) v = (c < Cin) ? inp[row*Cin + c] : st[row*HID + (c - Cin)];
    t[ty][tx] = v;
    __syncthreads();
    float val = t[tx][ty];
    int n = n0 + tx, cw = c0 + ty;
    if (cw < Ct) {
        float x = val * g_rB[b*Ct + cw];
        int q1 = __float2int_rn(x);
        q1 = q1 > 127 ? 127 : (q1 < -127 ? -127 : q1);
        int q2 = __float2int_rn((x - (float)q1)*128.f);
        size_t o = ((size_t)(b*Ct + cw))*NN + n;
        g_Xq1[o] = (int8_t)q1; g_Xq2[o] = (int8_t)q2;
    }
}

// ---------------- int8 diffusion ------------------------------------------
#define QLDP 80
#define QMATB (128*QLDP)
#define QSTAGE (4*QMATB)
#define QSMEM (2*QSTAGE)

__global__ void __launch_bounds__(512, 1)
mmaDiffuseQ(int Ct, int NC, bf16* __restrict__ Fh, bf16* __restrict__ Fl,
            int Ctot, int KP, int colOff) {
    extern __shared__ char sm[];
    uint32_t sb = smem_u32(sm);
    const int tid = threadIdx.x, wid = tid >> 5, lane = tid & 31;
    const int f = blockIdx.z, n0 = blockIdx.y*128, j0 = blockIdx.x*128;
    const int8_t* __restrict__ A1 = g_Aq1 + ((size_t)f*NN + n0)*NN;
    const int8_t* __restrict__ A2 = g_Aq2 + ((size_t)f*NN + n0)*NN;
    const int wm = wid >> 2, wn = wid & 3;
    int acch[2][4][4] = {}, accl[2][4][4] = {};

    const int srow = tid >> 2, skq = (tid & 3)*16;
    const uint32_t soff = (uint32_t)(srow*QLDP + skq);
    int jr = j0 + srow; if (jr >= NC) jr = NC - 1;

    #define Q_ISSUE(buf, kt) do { \
        uint32_t s_ = sb + (buf)*QSTAGE; \
        size_t ga_ = (size_t)srow*NN + (kt) + skq; \
        cp16(s_ + soff,          A1 + ga_); \
        cp16(s_ + QMATB + soff,  A2 + ga_); \
        size_t gb_ = (size_t)jr*NN + (kt) + skq; \
        cp16(s_ + 2*QMATB + soff, g_Xq1 + gb_); \
        cp16(s_ + 3*QMATB + soff, g_Xq2 + gb_); \
        CP_COMMIT(); \
    } while (0)

    Q_ISSUE(0, 0);
    for (int ch = 0; ch < 16; ch++) {
        if (ch + 1 < 16) { Q_ISSUE((ch+1)&1, (ch+1)*64); CP_WAIT(1); }
        else CP_WAIT(0);
        __syncthreads();
        uint32_t Ab = sb + (ch&1)*QSTAGE;
        uint32_t A2b = Ab + QMATB, B1b = Ab + 2*QMATB, B2b = Ab + 3*QMATB;
        #pragma unroll
        for (int kb = 0; kb < 64; kb += 32) {
            uint32_t a1[2][4], a2[2][4], b1[4][2], b2[4][2];
            #pragma unroll
            for (int im = 0; im < 2; im++) {
                int row = wm*32 + im*16 + (lane & 15);
                uint32_t off = (uint32_t)(row*QLDP + kb + ((lane >> 4) << 4));
                LDSM4(a1[im], Ab + off);
                LDSM4(a2[im], A2b + off);
            }
            #pragma unroll
            for (int in = 0; in < 4; in++) {
                int row = wn*32 + in*8 + (lane & 7);
                uint32_t off = (uint32_t)(row*QLDP + kb + (((lane >> 3) & 1) << 4));
                LDSM2(b1[in], B1b + off);
                LDSM2(b2[in], B2b + off);
            }
            #pragma unroll
            for (int im = 0; im < 2; im++)
                #pragma unroll
                for (int in = 0; in < 4; in++) {
                    MMAS8(acch[im][in], a1[im], b1[in]);
                    MMAS8(accl[im][in], a1[im], b2[in]);
                    MMAS8(accl[im][in], a2[im], b1[in]);
                }
        }
        __syncthreads();
    }
    // epilogue
    const int m = f + 1, r = lane >> 2, cp2 = (lane & 3)*2;
    #pragma unroll
    for (int in = 0; in < 4; in++) {
        int jG = j0 + wn*32 + in*8 + cp2;
        if (jG >= NC) continue;
        int b = jG / Ct, c = jG % Ct;
        float sb0 = g_sB[jG], sb1 = g_sB[jG + 1];
        #pragma unroll
        for (int im = 0; im < 2; im++) {
            #pragma unroll
            for (int hh = 0; hh < 2; hh++) {
                int nG = n0 + wm*32 + im*16 + r + hh*8;
                float sa = g_sA[f*NN + nG];
                float v0 = sa*sb0*((float)acch[im][in][hh*2]   + (float)accl[im][in][hh*2]  *0.0078125f);
                float v1 = sa*sb1*((float)acch[im][in][hh*2+1] + (float)accl[im][in][hh*2+1]*0.0078125f);
                bf16 h0,l0,h1,l1; bsplit(v0,h0,l0); bsplit(v1,h1,l1);
                __nv_bfloat162 hv; hv.x=h0; hv.y=h1;
                __nv_bfloat162 lv; lv.x=l0; lv.y=l1;
                size_t base = (size_t)(b*NN + nG)*KP + m*Ctot + colOff + c;
                *(__nv_bfloat162*)(Fh + base) = hv;
                *(__nv_bfloat162*)(Fl + base) = lv;
            }
        }
    }
}

// ---------------- m0 slice ------------------------------------------------
__global__ void copyM0(const float* __restrict__ inp, int Cin,
                       const float* __restrict__ st,
                       bf16* __restrict__ Fh, bf16* __restrict__ Fl,
                       int Cw, int colOff, int KP) {
    int i = blockIdx.x*blockDim.x + threadIdx.x;
    if (i >= NROWS*Cw) return;
    int cl = i % Cw, row = i / Cw;
    float v = (cl < Cin) ? inp[row*Cin + cl] : st[row*HID + cl - Cin];
    bf16 h, l; bsplit(v, h, l);
    size_t o = (size_t)row*KP + colOff + cl;
    Fh[o] = h; Fl[o] = l;
}

// ---------------- weight transpose/split (once) ---------------------------
__global__ void wsplitT(const float* __restrict__ W, bf16* __restrict__ Th,
                        bf16* __restrict__ Tl, int Ct, int O, int KP) {
    int i = blockIdx.x*blockDim.x + threadIdx.x;
    if (i >= O*KP) return;
    int o = i / KP, k = i % KP;
    float v = (k < 5*Ct) ? W[(size_t)k*O + o] : 0.f;
    bf16 h, l; bsplit(v, h, l);
    Th[i] = h; Tl[i] = l;
}

// ---------------- tensor-core mixing + fused GRU --------------------------
#define MLDP 40
#define MA_B (128*MLDP*2)
#define MB_B (64*MLDP*2)
#define MSTAGE (2*MA_B + 2*MB_B)
#define MIX_SMEM (2*MSTAGE)

template<int MODE>
__global__ void __launch_bounds__(256)
mixTC(const bf16* __restrict__ FhA, const bf16* __restrict__ FlA,
      const bf16* __restrict__ FhB, const bf16* __restrict__ FlB,
      int KP, int nCh,
      const bf16* __restrict__ Wh, const bf16* __restrict__ Wl,
      const float* __restrict__ bias, const float* __restrict__ stateIn,
      float* __restrict__ stateOut) {
    extern __shared__ char smc[];
    uint32_t sb = smem_u32(smc);
    const int tid = threadIdx.x, wid = tid >> 5, lane = tid & 31;
    const int r0 = blockIdx.y*128, o0 = blockIdx.x*64;
    const int wm = wid >> 1, wn = wid & 1;
    float acc[2][4][4] = {};

    #define MIX_ISSUE(buf, kt) do { \
        const bf16* Sh_ = (((kt) >> 6) & 1) ? FhB : FhA; \
        const bf16* Sl_ = (((kt) >> 6) & 1) ? FlB : FlA; \
        uint32_t s_ = sb + (buf)*MSTAGE; \
        _Pragma("unroll") \
        for (int it = 0; it < 2; it++) { \
            int v_ = tid + it*256; \
            int row_ = v_ >> 2, kq_ = (v_ & 3)*8; \
            uint32_t off_ = (uint32_t)(row_*(MLDP*2) + kq_*2); \
            size_t g_ = (size_t)(r0+row_)*KP + (kt) + kq_; \
            cp16(s_ + off_, Sh_ + g_); \
            cp16(s_ + MA_B + off_, Sl_ + g_); \
        } \
        { int row_ = tid >> 2, kq_ = (tid & 3)*8; \
          uint32_t off_ = (uint32_t)(row_*(MLDP*2) + kq_*2); \
          size_t g_ = (size_t)(o0+row_)*KP + (kt) + kq_; \
          cp16(s_ + 2*MA_B + off_, Wh + g_); \
          cp16(s_ + 2*MA_B + MB_B + off_, Wl + g_); } \
        CP_COMMIT(); \
    } while (0)

    MIX_ISSUE(0, 0);
    for (int ch = 0; ch < nCh; ch++) {
        if (ch + 1 < nCh) { MIX_ISSUE((ch+1)&1, (ch+1)*32); CP_WAIT(1); }
        else CP_WAIT(0);
        __syncthreads();
        uint32_t Ab = sb + (ch&1)*MSTAGE, Alb = Ab + MA_B, Bb = Ab + 2*MA_B, Blb = Bb + MB_B;
        #pragma unroll
        for (int k16 = 0; k16 < 2; k16++) {
            const int kk = k16*16;
            uint32_t ah[2][4], al[2][4], bh[4][2], bl[4][2];
            #pragma unroll
            for (int im = 0; im < 2; im++) {
                int row = wm*32 + im*16 + (lane & 15);
                int col = kk + ((lane >> 4) << 3);
                uint32_t off = (uint32_t)(row*(MLDP*2) + col*2);
                LDSM4(ah[im], Ab + off);
                LDSM4(al[im], Alb + off);
            }
            #pragma unroll
            for (int in = 0; in < 4; in++) {
                int row = wn*32 + in*8 + (lane & 7);
                int col = kk + (((lane >> 3) & 1) << 3);
                uint32_t off = (uint32_t)(row*(MLDP*2) + col*2);
                LDSM2(bh[in], Bb + off);
                LDSM2(bl[in], Blb + off);
            }
            #pragma unroll
            for (int im = 0; im < 2; im++)
                #pragma unroll
                for (int in = 0; in < 4; in++) {
                    MMA16816(acc[im][in], ah[im], bh[in]);
                    MMA16816(acc[im][in], ah[im], bl[in]);
                    MMA16816(acc[im][in], al[im], bh[in]);
                }
        }
        __syncthreads();
    }
    const int r = lane >> 2, cp2 = (lane & 3)*2;
    #pragma unroll
    for (int im = 0; im < 2; im++) {
        #pragma unroll
        for (int in = 0; in < 4; in++) {
            int o = o0 + wn*32 + in*8 + cp2;
            float b0 = bias[o], b1 = bias[o+1];
            #pragma unroll
            for (int hh = 0; hh < 2; hh++) {
                int row = r0 + wm*32 + im*16 + r + hh*8;
                float v0 = acc[im][in][hh*2], v1 = acc[im][in][hh*2+1];
                if (MODE == 0) {
                    float gg0 = 1.f/(1.f + expf(-(v0 + b0)));
                    float gg1 = 1.f/(1.f + expf(-(v1 + b1)));
                    if (o < HID) {
                        g_rstate[row*HID + o]   = gg0 * stateIn[row*HID + o];
                        g_rstate[row*HID + o+1] = gg1 * stateIn[row*HID + o+1];
                    } else {
                        g_u[row*HID + o - HID]     = gg0;
                        g_u[row*HID + o + 1 - HID] = gg1;
                    }
                } else {
                    float hT0 = tanhf(v0 + b0), hT1 = tanhf(v1 + b1);
                    float u0 = g_u[row*HID + o], u1 = g_u[row*HID + o+1];
                    float s0 = stateOut[row*HID + o], s1 = stateOut[row*HID + o+1];
                    stateOut[row*HID + o]   = u0*s0 + (1.f - u0)*hT0;
                    stateOut[row*HID + o+1] = u1*s1 + (1.f - u1)*hT1;
                }
            }
        }
    }
}

__global__ void projK(const float* __restrict__ Wp, const float* __restrict__ bp,
                      float* __restrict__ out_t) {
    int row = blockIdx.x*blockDim.x + threadIdx.x;
    if (row >= NROWS) return;
    const float* s = g_state1 + (size_t)row*HID;
    float a0 = bp[0], a1 = bp[1];
    #pragma unroll
    for (int h = 0; h < HID; h++) { float v = s[h]; a0 += v*Wp[h*2]; a1 += v*Wp[h*2+1]; }
    out_t[row*2] = a0; out_t[row*2+1] = a1;
    g_decin[row*2] = a0; g_decin[row*2+1] = a1;
}

// -------------------------------------------------------------------------
extern "C" void kernel_launch(void* const* d_in, const int* in_sizes, int n_in,
                              void* d_out, int out_size) {
    const float* enc  = (const float*)d_in[0];
    const float* sup  = (const float*)d_in[1];
    const float* Wru0 = (const float*)d_in[2];
    const float* bru0 = (const float*)d_in[3];
    const float* Wh0  = (const float*)d_in[4];
    const float* bh0  = (const float*)d_in[5];
    const float* Wru1 = (const float*)d_in[6];
    const float* bru1 = (const float*)d_in[7];
    const float* Wh1  = (const float*)d_in[8];
    const float* bh1  = (const float*)d_in[9];
    const float* Wp   = (const float*)d_in[10];
    const float* bp   = (const float*)d_in[11];
    float* out = (float*)d_out;

    void *pv;
    cudaGetSymbolAddress(&pv, g_state0); float* pS0  = (float*)pv;
    cudaGetSymbolAddress(&pv, g_state1); float* pS1  = (float*)pv;
    cudaGetSymbolAddress(&pv, g_decin);  float* pDec = (float*)pv;
    cudaGetSymbolAddress(&pv, g_rstate); float* pRst = (float*)pv;
    cudaGetSymbolAddress(&pv, g_FAh); bf16* FAh = (bf16*)pv;
    cudaGetSymbolAddress(&pv, g_FAl); bf16* FAl = (bf16*)pv;
    cudaGetSymbolAddress(&pv, g_FBh); bf16* FBh = (bf16*)pv;
    cudaGetSymbolAddress(&pv, g_FBl); bf16* FBl = (bf16*)pv;
    cudaGetSymbolAddress(&pv, g_Wru0h); bf16* Wru0h = (bf16*)pv;
    cudaGetSymbolAddress(&pv, g_Wru0l); bf16* Wru0l = (bf16*)pv;
    cudaGetSymbolAddress(&pv, g_Wh0h);  bf16* Wh0h  = (bf16*)pv;
    cudaGetSymbolAddress(&pv, g_Wh0l);  bf16* Wh0l  = (bf16*)pv;
    cudaGetSymbolAddress(&pv, g_Wru1h); bf16* Wru1h = (bf16*)pv;
    cudaGetSymbolAddress(&pv, g_Wru1l); bf16* Wru1l = (bf16*)pv;
    cudaGetSymbolAddress(&pv, g_Wh1h);  bf16* Wh1h  = (bf16*)pv;
    cudaGetSymbolAddress(&pv, g_Wh1l);  bf16* Wh1l  = (bf16*)pv;

    cudaFuncSetAttribute(mmaDiffuseQ, cudaFuncAttributeMaxDynamicSharedMemorySize, QSMEM);
    cudaFuncSetAttribute(mixTC<0>, cudaFuncAttributeMaxDynamicSharedMemorySize, MIX_SMEM);
    cudaFuncSetAttribute(mixTC<1>, cudaFuncAttributeMaxDynamicSharedMemorySize, MIX_SMEM);

    initK<<<(NROWS*HID + 255)/256, 256>>>(enc);
    precomputeM<<<dim3(16,16,2), 256>>>(sup);
    opQuant<<<dim3(NN,4), 256>>>(sup);
    wsplitT<<<(128*352 + 255)/256, 256>>>(Wru0, Wru0h, Wru0l, 66, 128, 352);
    wsplitT<<<(64*352 + 255)/256, 256>>>(Wh0, Wh0h, Wh0l, 66, 64, 352);
    wsplitT<<<(128*640 + 255)/256, 256>>>(Wru1, Wru1h, Wru1l, 128, 128, 640);
    wsplitT<<<(64*640 + 255)/256, 256>>>(Wh1, Wh1h, Wh1l, 128, 64, 640);

    for (int t = 0; t < STEPS; t++) {
        // ---- layer 0 RU: x=[decin|state0], Ct=66, KP=352
        colMaxK<<<32, dim3(128,4)>>>(pDec, 2, pS0, 66);
        tsplitQ<<<dim3(32,3,32), dim3(32,32)>>>(pDec, 2, pS0, 66);
        copyM0<<<(NROWS*66 + 255)/256, 256>>>(pDec, 2, pS0, FAh, FAl, 66, 0, 352);
        mmaDiffuseQ<<<dim3(17,8,4), 512, QSMEM>>>(66, 2112, FAh, FAl, 66, 352, 0);
        mixTC<0><<<dim3(2,256), 256, MIX_SMEM>>>(FAh, FAl, FAh, FAl, 352, 11, Wru0h, Wru0l, bru0, pS0, 0);
        // ---- layer 0 H: x2=[decin|r*state0]
        colMaxK<<<32, dim3(128,4)>>>(pDec, 2, pRst, 66);
        tsplitQ<<<dim3(32,3,32), dim3(32,32)>>>(pDec, 2, pRst, 66);
        copyM0<<<(NROWS*66 + 255)/256, 256>>>(pDec, 2, pRst, FBh, FBl, 66, 0, 352);
        mmaDiffuseQ<<<dim3(17,8,4), 512, QSMEM>>>(66, 2112, FBh, FBl, 66, 352, 0);
        mixTC<1><<<dim3(1,256), 256, MIX_SMEM>>>(FBh, FBl, FBh, FBl, 352, 11, Wh0h, Wh0l, bh0, 0, pS0);

        // ---- layer 1 RU: x=[state0|state1], Ct=128, KP=640
        colMaxK<<<32, dim3(128,4)>>>(pS0, 64, pS1, 128);
        tsplitQ<<<dim3(32,4,32), dim3(32,32)>>>(pS0, 64, pS1, 128);
        copyM0<<<(NROWS*128 + 255)/256, 256>>>(pS0, 64, pS1, FAh, FAl, 128, 0, 640);
        mmaDiffuseQ<<<dim3(32,8,4), 512, QSMEM>>>(128, 4096, FAh, FAl, 128, 640, 0);
        mixTC<0><<<dim3(2,256), 256, MIX_SMEM>>>(FAh, FAl, FAh, FAl, 640, 20, Wru1h, Wru1l, bru1, pS1, 0);
        // ---- layer 1 H: diffuse only r*state1; state0 chunks read from FA
        colMaxK<<<32, dim3(128,4)>>>((const float*)0, 0, pRst, 64);
        tsplitQ<<<dim3(32,2,32), dim3(32,32)>>>((const float*)0, 0, pRst, 64);
        copyM0<<<(NROWS*64 + 255)/256, 256>>>((const float*)0, 0, pRst, FBh, FBl, 64, 64, 640);
        mmaDiffuseQ<<<dim3(16,8,4), 512, QSMEM>>>(64, 2048, FBh, FBl, 128, 640, 64);
        mixTC<1><<<dim3(1,256), 256, MIX_SMEM>>>(FAh, FAl, FBh, FBl, 640, 20, Wh1h, Wh1l, bh1, 0, pS1);

        projK<<<(NROWS + 255)/256, 256>>>(Wp, bp, out + (size_t)t*NROWS*OUTD);
    }
}

// round 8
// speedup vs baseline: 3.4988x; 1.2336x over previous
#include <cuda_runtime.h>
#include <cuda_bf16.h>
#include <math.h>
#include <stdint.h>

#define NN 1024
#define BATCH 32
#define HID 64
#define OUTD 2
#define STEPS 12
#define NROWS (BATCH*NN)
typedef __nv_bfloat16 bf16;

// ---------------- PTX helpers ---------------------------------------------
__device__ __forceinline__ uint32_t smem_u32(const void* p) {
    uint32_t a;
    asm("{ .reg .u64 t; cvta.to.shared.u64 t, %1; cvt.u32.u64 %0, t; }" : "=r"(a) : "l"(p));
    return a;
}
__device__ __forceinline__ void cp16(uint32_t sa, const void* g) {
    asm volatile("cp.async.cg.shared.global [%0], [%1], 16;" :: "r"(sa), "l"(g) : "memory");
}
#define CP_COMMIT() asm volatile("cp.async.commit_group;" ::: "memory")
#define CP_WAIT(n)  asm volatile("cp.async.wait_group %0;" :: "n"(n) : "memory")
#define LDSM4(r, a) asm volatile( \
    "ldmatrix.sync.aligned.m8n8.x4.shared.b16 {%0,%1,%2,%3}, [%4];" \
    : "=r"((r)[0]), "=r"((r)[1]), "=r"((r)[2]), "=r"((r)[3]) : "r"(a))
#define LDSM2(r, a) asm volatile( \
    "ldmatrix.sync.aligned.m8n8.x2.shared.b16 {%0,%1}, [%2];" \
    : "=r"((r)[0]), "=r"((r)[1]) : "r"(a))
#define MMA16816(d, a, b) asm volatile( \
    "mma.sync.aligned.m16n8k16.row.col.f32.bf16.bf16.f32 " \
    "{%0,%1,%2,%3},{%4,%5,%6,%7},{%8,%9},{%0,%1,%2,%3};" \
    : "+f"((d)[0]), "+f"((d)[1]), "+f"((d)[2]), "+f"((d)[3]) \
    : "r"((a)[0]), "r"((a)[1]), "r"((a)[2]), "r"((a)[3]), "r"((b)[0]), "r"((b)[1]))
#define MMAS8(d, a, b) asm volatile( \
    "mma.sync.aligned.m16n8k32.row.col.s32.s8.s8.s32 " \
    "{%0,%1,%2,%3},{%4,%5,%6,%7},{%8,%9},{%0,%1,%2,%3};" \
    : "+r"((d)[0]), "+r"((d)[1]), "+r"((d)[2]), "+r"((d)[3]) \
    : "r"((a)[0]), "r"((a)[1]), "r"((a)[2]), "r"((a)[3]), "r"((b)[0]), "r"((b)[1]))

__device__ __forceinline__ void bsplit(float v, bf16& h, bf16& l) {
    h = __float2bfloat16(v);
    l = __float2bfloat16(v - __bfloat162float(h));
}

// ---------------- scratch -------------------------------------------------
__device__ float g_M[2u*NN*NN];
__device__ float g_state0[NROWS*HID];
__device__ float g_state1[NROWS*HID];
__device__ float g_decin [NROWS*OUTD];
__device__ float g_u     [NROWS*HID];
__device__ float g_rstate[NROWS*HID];
__device__ bf16 g_FAh[(size_t)NROWS*640], g_FAl[(size_t)NROWS*640];
__device__ bf16 g_FBh[(size_t)NROWS*640], g_FBl[(size_t)NROWS*640];
__device__ int8_t g_Aq1[(size_t)4*NN*NN], g_Aq2[(size_t)4*NN*NN];
__device__ int8_t g_Xq1[(size_t)4096*NN], g_Xq2[(size_t)4096*NN];
__device__ float g_sA[4*NN];
__device__ uint32_t g_bits[4][4096];
__device__ bf16 g_Wru0h[128*352], g_Wru0l[128*352];
__device__ bf16 g_Wh0h [64*352],  g_Wh0l [64*352];
__device__ bf16 g_Wru1h[128*640], g_Wru1l[128*640];
__device__ bf16 g_Wh1h [64*640],  g_Wh1l [64*640];

// ---------------- init / precompute ---------------------------------------
__global__ void initK(const float* __restrict__ enc) {
    int i = blockIdx.x*blockDim.x + threadIdx.x;
    const int SZ = NROWS*HID;
    if (i < SZ) { g_state0[i] = enc[i]; g_state1[i] = enc[SZ+i]; }
    if (i < NROWS*OUTD) g_decin[i] = 0.f;
}

__global__ void precomputeM(const float* __restrict__ sup) {
    const int s = blockIdx.z;
    const float* __restrict__ S = sup + (size_t)s*NN*NN;
    float* __restrict__ Mo = g_M + (size_t)s*NN*NN;
    __shared__ float As[16][64], Bs[16][64];
    const int tid = threadIdx.x, tx = tid & 15, ty = tid >> 4;
    const int n0 = blockIdx.y*64, j0 = blockIdx.x*64;
    const int ar = tid >> 2, aq = (tid & 3)*4, br = tid >> 4, bq = (tid & 15)*4;
    float acc[4][4] = {};
    for (int kt = 0; kt < NN; kt += 16) {
        float4 av = *(const float4*)(S + (size_t)(n0+ar)*NN + kt + aq);
        As[aq][ar]=av.x; As[aq+1][ar]=av.y; As[aq+2][ar]=av.z; As[aq+3][ar]=av.w;
        *(float4*)&Bs[br][bq] = *(const float4*)(S + (size_t)(kt+br)*NN + j0 + bq);
        __syncthreads();
        #pragma unroll
        for (int k = 0; k < 16; k++) {
            float4 a = *(float4*)&As[k][ty*4], b = *(float4*)&Bs[k][tx*4];
            float arr[4]={a.x,a.y,a.z,a.w}, brr[4]={b.x,b.y,b.z,b.w};
            #pragma unroll
            for (int i=0;i<4;i++)
                #pragma unroll
                for (int j=0;j<4;j++) acc[i][j] += arr[i]*brr[j];
        }
        __syncthreads();
    }
    #pragma unroll
    for (int i=0;i<4;i++) { int n=n0+ty*4+i;
        #pragma unroll
        for (int j=0;j<4;j++) { int jc=j0+tx*4+j;
            Mo[(size_t)n*NN+jc] = 2.f*acc[i][j] - (n==jc?1.f:0.f); } }
}

// quantize operator rows to 2-limb int8 (limb2 scale 254); zero bits bufs
__global__ void opQuant(const float* __restrict__ sup) {
    const int n = blockIdx.x, f = blockIdx.y, tid = threadIdx.x;
    if (f == 0 && n < 16) {
        for (int j = tid; j < 1024; j += 256) ((uint32_t*)g_bits)[n*1024 + j] = 0;
    }
    const float* src = (f==0) ? sup : (f==1) ? g_M :
                       (f==2) ? sup + (size_t)NN*NN : g_M + (size_t)NN*NN;
    float4 v = *(const float4*)(src + (size_t)n*NN + tid*4);
    float mx = fmaxf(fmaxf(fabsf(v.x),fabsf(v.y)), fmaxf(fabsf(v.z),fabsf(v.w)));
    #pragma unroll
    for (int o = 16; o; o >>= 1) mx = fmaxf(mx, __shfl_xor_sync(0xffffffffu, mx, o));
    __shared__ float w[8]; __shared__ float sInv;
    if ((tid & 31) == 0) w[tid >> 5] = mx;
    __syncthreads();
    if (tid == 0) {
        float m = w[0];
        #pragma unroll
        for (int i = 1; i < 8; i++) m = fmaxf(m, w[i]);
        g_sA[f*NN + n] = (m > 0.f) ? m/127.f : 1.f;
        sInv = (m > 0.f) ? 127.f/m : 0.f;
    }
    __syncthreads();
    float inv = sInv;
    char4 q1, q2;
    float xs[4] = {v.x*inv, v.y*inv, v.z*inv, v.w*inv};
    int a1[4], a2[4];
    #pragma unroll
    for (int i = 0; i < 4; i++) {
        int q = __float2int_rn(xs[i]);
        q = q > 127 ? 127 : (q < -127 ? -127 : q);
        a1[i] = q;
        int r = __float2int_rn((xs[i] - (float)q)*254.f);
        a2[i] = r > 127 ? 127 : (r < -127 ? -127 : r);
    }
    q1.x=a1[0];q1.y=a1[1];q1.z=a1[2];q1.w=a1[3];
    q2.x=a2[0];q2.y=a2[1];q2.z=a2[2];q2.w=a2[3];
    size_t o = ((size_t)f*NN + n)*NN + tid*4;
    *(char4*)(g_Aq1 + o) = q1;
    *(char4*)(g_Aq2 + o) = q2;
}

// atomic column max: bits[buf][b*Ct + c] = max |v|
__global__ void colMaxA(const float* __restrict__ inp, int Cin,
                        const float* __restrict__ st, int Ct, int buf) {
    __shared__ uint32_t sb[128];
    int b = blockIdx.y, chunk = blockIdx.x, tid = threadIdx.x;
    for (int c = tid; c < Ct; c += 256) sb[c] = 0;
    __syncthreads();
    int total = 128*Ct;
    for (int idx = tid; idx < total; idx += 256) {
        int nl = idx / Ct, c = idx - nl*Ct;
        size_t row = (size_t)b*NN + chunk*128 + nl;
        float v = (c < Cin) ? inp[row*Cin + c] : st[row*HID + c - Cin];
        atomicMax(&sb[c], __float_as_uint(fabsf(v)));
    }
    __syncthreads();
    for (int c = tid; c < Ct; c += 256) atomicMax(&g_bits[buf][b*Ct + c], sb[c]);
}

// fused: m0 bf16 slice write + transpose + 2-limb int8 quantize; zeroes next buf
__global__ void prepK(const float* __restrict__ inp, int Cin,
                      const float* __restrict__ st, int Ct,
                      int buf, int nbuf, int m0off, int KP,
                      bf16* __restrict__ Fh, bf16* __restrict__ Fl) {
    __shared__ float t[32][33];
    int b = blockIdx.z, n0 = blockIdx.x*32, c0 = blockIdx.y*32;
    int tx = threadIdx.x, ty = threadIdx.y;
    if (blockIdx.x == 0 && blockIdx.y == 0 && b == 0) {
        int tid = ty*32 + tx;
        for (int j = tid; j < 4096; j += 1024) g_bits[nbuf][j] = 0;
    }
    int c = c0 + tx;
    float v = 0.f;
    size_t row = (size_t)b*NN + n0 + ty;
    if (c < Ct) {
        v = (c < Cin) ? inp[row*Cin + c] : st[row*HID + c - Cin];
        bf16 h, l; bsplit(v, h, l);
        size_t o = row*KP + m0off + c;
        Fh[o] = h; Fl[o] = l;
    }
    t[ty][tx] = v;
    __syncthreads();
    float val = t[tx][ty];
    int n = n0 + tx, cw = c0 + ty;
    if (cw < Ct) {
        float m = __uint_as_float(g_bits[buf][b*Ct + cw]);
        float rB = (m > 0.f) ? 127.f/m : 0.f;
        float x = val * rB;
        int q1 = __float2int_rn(x);
        q1 = q1 > 127 ? 127 : (q1 < -127 ? -127 : q1);
        int q2 = __float2int_rn((x - (float)q1)*254.f);
        q2 = q2 > 127 ? 127 : (q2 < -127 ? -127 : q2);
        size_t o = ((size_t)(b*Ct + cw))*NN + n;
        g_Xq1[o] = (int8_t)q1; g_Xq2[o] = (int8_t)q2;
    }
}

// ---------------- int8 diffusion ------------------------------------------
#define QLDP 80
#define QMATB (128*QLDP)
#define QSTAGE (4*QMATB)
#define QSMEM (2*QSTAGE)

__global__ void __launch_bounds__(512, 1)
mmaDiffuseQ(int Ct, int NC, bf16* __restrict__ Fh, bf16* __restrict__ Fl,
            int Ctot, int KP, int colOff, int buf) {
    extern __shared__ char sm[];
    uint32_t sb = smem_u32(sm);
    const int tid = threadIdx.x, wid = tid >> 5, lane = tid & 31;
    const int f = blockIdx.z, n0 = blockIdx.y*128, j0 = blockIdx.x*128;
    const int8_t* __restrict__ A1 = g_Aq1 + ((size_t)f*NN + n0)*NN;
    const int8_t* __restrict__ A2 = g_Aq2 + ((size_t)f*NN + n0)*NN;
    const int wm = wid >> 2, wn = wid & 3;
    int acch[2][4][4] = {}, accl[2][4][4] = {};

    const int srow = tid >> 2, skq = (tid & 3)*16;
    const uint32_t soff = (uint32_t)(srow*QLDP + skq);
    int jr = j0 + srow; if (jr >= NC) jr = NC - 1;

    #define Q_ISSUE(bufq, kt) do { \
        uint32_t s_ = sb + (bufq)*QSTAGE; \
        size_t ga_ = (size_t)srow*NN + (kt) + skq; \
        cp16(s_ + soff,          A1 + ga_); \
        cp16(s_ + QMATB + soff,  A2 + ga_); \
        size_t gb_ = (size_t)jr*NN + (kt) + skq; \
        cp16(s_ + 2*QMATB + soff, g_Xq1 + gb_); \
        cp16(s_ + 3*QMATB + soff, g_Xq2 + gb_); \
        CP_COMMIT(); \
    } while (0)

    Q_ISSUE(0, 0);
    for (int ch = 0; ch < 16; ch++) {
        if (ch + 1 < 16) { Q_ISSUE((ch+1)&1, (ch+1)*64); CP_WAIT(1); }
        else CP_WAIT(0);
        __syncthreads();
        uint32_t Ab = sb + (ch&1)*QSTAGE;
        uint32_t A2b = Ab + QMATB, B1b = Ab + 2*QMATB, B2b = Ab + 3*QMATB;
        #pragma unroll
        for (int kb = 0; kb < 64; kb += 32) {
            uint32_t a1[2][4], a2[2][4], b1[4][2], b2[4][2];
            #pragma unroll
            for (int im = 0; im < 2; im++) {
                int row = wm*32 + im*16 + (lane & 15);
                uint32_t off = (uint32_t)(row*QLDP + kb + ((lane >> 4) << 4));
                LDSM4(a1[im], Ab + off);
                LDSM4(a2[im], A2b + off);
            }
            #pragma unroll
            for (int in = 0; in < 4; in++) {
                int row = wn*32 + in*8 + (lane & 7);
                uint32_t off = (uint32_t)(row*QLDP + kb + (((lane >> 3) & 1) << 4));
                LDSM2(b1[in], B1b + off);
                LDSM2(b2[in], B2b + off);
            }
            #pragma unroll
            for (int im = 0; im < 2; im++)
                #pragma unroll
                for (int in = 0; in < 4; in++) {
                    MMAS8(acch[im][in], a1[im], b1[in]);
                    MMAS8(accl[im][in], a1[im], b2[in]);
                    MMAS8(accl[im][in], a2[im], b1[in]);
                }
        }
        __syncthreads();
    }
    const int m = f + 1, r = lane >> 2, cp2 = (lane & 3)*2;
    const float INV = 1.f/254.f, IS = 1.f/127.f;
    #pragma unroll
    for (int in = 0; in < 4; in++) {
        int jG = j0 + wn*32 + in*8 + cp2;
        if (jG >= NC) continue;
        int b = jG / Ct, c = jG % Ct;
        float sb0 = __uint_as_float(g_bits[buf][jG])*IS;
        float sb1 = __uint_as_float(g_bits[buf][jG + 1])*IS;
        #pragma unroll
        for (int im = 0; im < 2; im++) {
            #pragma unroll
            for (int hh = 0; hh < 2; hh++) {
                int nG = n0 + wm*32 + im*16 + r + hh*8;
                float sa = g_sA[f*NN + nG];
                float v0 = sa*sb0*((float)acch[im][in][hh*2]   + (float)accl[im][in][hh*2]  *INV);
                float v1 = sa*sb1*((float)acch[im][in][hh*2+1] + (float)accl[im][in][hh*2+1]*INV);
                bf16 h0,l0,h1,l1; bsplit(v0,h0,l0); bsplit(v1,h1,l1);
                __nv_bfloat162 hv; hv.x=h0; hv.y=h1;
                __nv_bfloat162 lv; lv.x=l0; lv.y=l1;
                size_t base = (size_t)(b*NN + nG)*KP + m*Ctot + colOff + c;
                *(__nv_bfloat162*)(Fh + base) = hv;
                *(__nv_bfloat162*)(Fl + base) = lv;
            }
        }
    }
}

// ---------------- weight transpose/split (once) ---------------------------
__global__ void wsplitT(const float* __restrict__ W, bf16* __restrict__ Th,
                        bf16* __restrict__ Tl, int Ct, int O, int KP) {
    int i = blockIdx.x*blockDim.x + threadIdx.x;
    if (i >= O*KP) return;
    int o = i / KP, k = i % KP;
    float v = (k < 5*Ct) ? W[(size_t)k*O + o] : 0.f;
    bf16 h, l; bsplit(v, h, l);
    Th[i] = h; Tl[i] = l;
}

// ---------------- tensor-core mixing + fused GRU --------------------------
#define MLDP 40
#define MA_B (128*MLDP*2)
#define MB_B (64*MLDP*2)
#define MSTAGE (2*MA_B + 2*MB_B)
#define MIX_SMEM (2*MSTAGE)

template<int MODE>
__global__ void __launch_bounds__(256)
mixTC(const bf16* __restrict__ FhA, const bf16* __restrict__ FlA,
      const bf16* __restrict__ FhB, const bf16* __restrict__ FlB,
      int KP, int nCh,
      const bf16* __restrict__ Wh, const bf16* __restrict__ Wl,
      const float* __restrict__ bias, const float* __restrict__ stateIn,
      float* __restrict__ stateOut) {
    extern __shared__ char smc[];
    uint32_t sb = smem_u32(smc);
    const int tid = threadIdx.x, wid = tid >> 5, lane = tid & 31;
    const int r0 = blockIdx.y*128, o0 = blockIdx.x*64;
    const int wm = wid >> 1, wn = wid & 1;
    float acc[2][4][4] = {};

    #define MIX_ISSUE(buf, kt) do { \
        const bf16* Sh_ = (((kt) >> 6) & 1) ? FhB : FhA; \
        const bf16* Sl_ = (((kt) >> 6) & 1) ? FlB : FlA; \
        uint32_t s_ = sb + (buf)*MSTAGE; \
        _Pragma("unroll") \
        for (int it = 0; it < 2; it++) { \
            int v_ = tid + it*256; \
            int row_ = v_ >> 2, kq_ = (v_ & 3)*8; \
            uint32_t off_ = (uint32_t)(row_*(MLDP*2) + kq_*2); \
            size_t g_ = (size_t)(r0+row_)*KP + (kt) + kq_; \
            cp16(s_ + off_, Sh_ + g_); \
            cp16(s_ + MA_B + off_, Sl_ + g_); \
        } \
        { int row_ = tid >> 2, kq_ = (tid & 3)*8; \
          uint32_t off_ = (uint32_t)(row_*(MLDP*2) + kq_*2); \
          size_t g_ = (size_t)(o0+row_)*KP + (kt) + kq_; \
          cp16(s_ + 2*MA_B + off_, Wh + g_); \
          cp16(s_ + 2*MA_B + MB_B + off_, Wl + g_); } \
        CP_COMMIT(); \
    } while (0)

    MIX_ISSUE(0, 0);
    for (int ch = 0; ch < nCh; ch++) {
        if (ch + 1 < nCh) { MIX_ISSUE((ch+1)&1, (ch+1)*32); CP_WAIT(1); }
        else CP_WAIT(0);
        __syncthreads();
        uint32_t Ab = sb + (ch&1)*MSTAGE, Alb = Ab + MA_B, Bb = Ab + 2*MA_B, Blb = Bb + MB_B;
        #pragma unroll
        for (int k16 = 0; k16 < 2; k16++) {
            const int kk = k16*16;
            uint32_t ah[2][4], al[2][4], bh[4][2], bl[4][2];
            #pragma unroll
            for (int im = 0; im < 2; im++) {
                int row = wm*32 + im*16 + (lane & 15);
                int col = kk + ((lane >> 4) << 3);
                uint32_t off = (uint32_t)(row*(MLDP*2) + col*2);
                LDSM4(ah[im], Ab + off);
                LDSM4(al[im], Alb + off);
            }
            #pragma unroll
            for (int in = 0; in < 4; in++) {
                int row = wn*32 + in*8 + (lane & 7);
                int col = kk + (((lane >> 3) & 1) << 3);
                uint32_t off = (uint32_t)(row*(MLDP*2) + col*2);
                LDSM2(bh[in], Bb + off);
                LDSM2(bl[in], Blb + off);
            }
            #pragma unroll
            for (int im = 0; im < 2; im++)
                #pragma unroll
                for (int in = 0; in < 4; in++) {
                    MMA16816(acc[im][in], ah[im], bh[in]);
                    MMA16816(acc[im][in], ah[im], bl[in]);
                    MMA16816(acc[im][in], al[im], bh[in]);
                }
        }
        __syncthreads();
    }
    const int r = lane >> 2, cp2 = (lane & 3)*2;
    #pragma unroll
    for (int im = 0; im < 2; im++) {
        #pragma unroll
        for (int in = 0; in < 4; in++) {
            int o = o0 + wn*32 + in*8 + cp2;
            float b0 = bias[o], b1 = bias[o+1];
            #pragma unroll
            for (int hh = 0; hh < 2; hh++) {
                int row = r0 + wm*32 + im*16 + r + hh*8;
                float v0 = acc[im][in][hh*2], v1 = acc[im][in][hh*2+1];
                if (MODE == 0) {
                    float gg0 = 1.f/(1.f + expf(-(v0 + b0)));
                    float gg1 = 1.f/(1.f + expf(-(v1 + b1)));
                    if (o < HID) {
                        g_rstate[row*HID + o]   = gg0 * stateIn[row*HID + o];
                        g_rstate[row*HID + o+1] = gg1 * stateIn[row*HID + o+1];
                    } else {
                        g_u[row*HID + o - HID]     = gg0;
                        g_u[row*HID + o + 1 - HID] = gg1;
                    }
                } else {
                    float hT0 = tanhf(v0 + b0), hT1 = tanhf(v1 + b1);
                    float u0 = g_u[row*HID + o], u1 = g_u[row*HID + o+1];
                    float s0 = stateOut[row*HID + o], s1 = stateOut[row*HID + o+1];
                    stateOut[row*HID + o]   = u0*s0 + (1.f - u0)*hT0;
                    stateOut[row*HID + o+1] = u1*s1 + (1.f - u1)*hT1;
                }
            }
        }
    }
}

__global__ void projK(const float* __restrict__ Wp, const float* __restrict__ bp,
                      float* __restrict__ out_t) {
    int row = blockIdx.x*blockDim.x + threadIdx.x;
    if (row >= NROWS) return;
    const float* s = g_state1 + (size_t)row*HID;
    float a0 = bp[0], a1 = bp[1];
    #pragma unroll
    for (int h = 0; h < HID; h++) { float v = s[h]; a0 += v*Wp[h*2]; a1 += v*Wp[h*2+1]; }
    out_t[row*2] = a0; out_t[row*2+1] = a1;
    g_decin[row*2] = a0; g_decin[row*2+1] = a1;
}

// -------------------------------------------------------------------------
extern "C" void kernel_launch(void* const* d_in, const int* in_sizes, int n_in,
                              void* d_out, int out_size) {
    const float* enc  = (const float*)d_in[0];
    const float* sup  = (const float*)d_in[1];
    const float* Wru0 = (const float*)d_in[2];
    const float* bru0 = (const float*)d_in[3];
    const float* Wh0  = (const float*)d_in[4];
    const float* bh0  = (const float*)d_in[5];
    const float* Wru1 = (const float*)d_in[6];
    const float* bru1 = (const float*)d_in[7];
    const float* Wh1  = (const float*)d_in[8];
    const float* bh1  = (const float*)d_in[9];
    const float* Wp   = (const float*)d_in[10];
    const float* bp   = (const float*)d_in[11];
    float* out = (float*)d_out;

    void *pv;
    cudaGetSymbolAddress(&pv, g_state0); float* pS0  = (float*)pv;
    cudaGetSymbolAddress(&pv, g_state1); float* pS1  = (float*)pv;
    cudaGetSymbolAddress(&pv, g_decin);  float* pDec = (float*)pv;
    cudaGetSymbolAddress(&pv, g_rstate); float* pRst = (float*)pv;
    cudaGetSymbolAddress(&pv, g_FAh); bf16* FAh = (bf16*)pv;
    cudaGetSymbolAddress(&pv, g_FAl); bf16* FAl = (bf16*)pv;
    cudaGetSymbolAddress(&pv, g_FBh); bf16* FBh = (bf16*)pv;
    cudaGetSymbolAddress(&pv, g_FBl); bf16* FBl = (bf16*)pv;
    cudaGetSymbolAddress(&pv, g_Wru0h); bf16* Wru0h = (bf16*)pv;
    cudaGetSymbolAddress(&pv, g_Wru0l); bf16* Wru0l = (bf16*)pv;
    cudaGetSymbolAddress(&pv, g_Wh0h);  bf16* Wh0h  = (bf16*)pv;
    cudaGetSymbolAddress(&pv, g_Wh0l);  bf16* Wh0l  = (bf16*)pv;
    cudaGetSymbolAddress(&pv, g_Wru1h); bf16* Wru1h = (bf16*)pv;
    cudaGetSymbolAddress(&pv, g_Wru1l); bf16* Wru1l = (bf16*)pv;
    cudaGetSymbolAddress(&pv, g_Wh1h);  bf16* Wh1h  = (bf16*)pv;
    cudaGetSymbolAddress(&pv, g_Wh1l);  bf16* Wh1l  = (bf16*)pv;

    cudaFuncSetAttribute(mmaDiffuseQ, cudaFuncAttributeMaxDynamicSharedMemorySize, QSMEM);
    cudaFuncSetAttribute(mixTC<0>, cudaFuncAttributeMaxDynamicSharedMemorySize, MIX_SMEM);
    cudaFuncSetAttribute(mixTC<1>, cudaFuncAttributeMaxDynamicSharedMemorySize, MIX_SMEM);

    // conv helpers: colMax + prep + diffuse
    auto conv0 = [&]() {  // L0 RU: x=[decin|state0]
        colMaxA<<<dim3(8,32), 256>>>(pDec, 2, pS0, 66, 0);
        prepK<<<dim3(32,3,32), dim3(32,32)>>>(pDec, 2, pS0, 66, 0, 1, 0, 352, FAh, FAl);
        mmaDiffuseQ<<<dim3(17,8,4), 512, QSMEM>>>(66, 2112, FAh, FAl, 66, 352, 0, 0);
    };
    auto conv1 = [&]() {  // L0 H: x2=[decin|r*state0]
        colMaxA<<<dim3(8,32), 256>>>(pDec, 2, pRst, 66, 1);
        prepK<<<dim3(32,3,32), dim3(32,32)>>>(pDec, 2, pRst, 66, 1, 2, 0, 352, FBh, FBl);
        mmaDiffuseQ<<<dim3(17,8,4), 512, QSMEM>>>(66, 2112, FBh, FBl, 66, 352, 0, 1);
    };
    auto conv2 = [&]() {  // L1 RU: x=[state0|state1]
        colMaxA<<<dim3(8,32), 256>>>(pS0, 64, pS1, 128, 2);
        prepK<<<dim3(32,4,32), dim3(32,32)>>>(pS0, 64, pS1, 128, 2, 3, 0, 640, FAh, FAl);
        mmaDiffuseQ<<<dim3(32,8,4), 512, QSMEM>>>(128, 4096, FAh, FAl, 128, 640, 0, 2);
    };
    auto conv3 = [&]() {  // L1 H: diffuse r*state1 only; state0 feats read from FA
        colMaxA<<<dim3(8,32), 256>>>((const float*)0, 0, pRst, 64, 3);
        prepK<<<dim3(32,2,32), dim3(32,32)>>>((const float*)0, 0, pRst, 64, 3, 0, 64, 640, FBh, FBl);
        mmaDiffuseQ<<<dim3(16,8,4), 512, QSMEM>>>(64, 2048, FBh, FBl, 128, 640, 64, 3);
    };
    auto mix0RU = [&]() { mixTC<0><<<dim3(2,256), 256, MIX_SMEM>>>(FAh, FAl, FAh, FAl, 352, 11, Wru0h, Wru0l, bru0, pS0, 0); };
    auto mix0H  = [&]() { mixTC<1><<<dim3(1,256), 256, MIX_SMEM>>>(FBh, FBl, FBh, FBl, 352, 11, Wh0h, Wh0l, bh0, 0, pS0); };
    auto mix1RU = [&]() { mixTC<0><<<dim3(2,256), 256, MIX_SMEM>>>(FAh, FAl, FAh, FAl, 640, 20, Wru1h, Wru1l, bru1, pS1, 0); };
    auto mix1H  = [&]() { mixTC<1><<<dim3(1,256), 256, MIX_SMEM>>>(FAh, FAl, FBh, FBl, 640, 20, Wh1h, Wh1l, bh1, 0, pS1); };

    // setup: 3 launches, then conv0 (launches 4-6; #6 = mmaDiffuseQ for ncu)
    initK<<<(NROWS*HID + 255)/256, 256>>>(enc);
    precomputeM<<<dim3(16,16,2), 256>>>(sup);
    opQuant<<<dim3(NN,4), 256>>>(sup);

    conv0();
    wsplitT<<<(128*352 + 255)/256, 256>>>(Wru0, Wru0h, Wru0l, 66, 128, 352);
    wsplitT<<<(64*352 + 255)/256, 256>>>(Wh0, Wh0h, Wh0l, 66, 64, 352);
    wsplitT<<<(128*640 + 255)/256, 256>>>(Wru1, Wru1h, Wru1l, 128, 128, 640);
    wsplitT<<<(64*640 + 255)/256, 256>>>(Wh1, Wh1h, Wh1l, 128, 64, 640);
    mix0RU();
    conv1(); mix0H();
    conv2(); mix1RU();
    conv3(); mix1H();
    projK<<<(NROWS + 255)/256, 256>>>(Wp, bp, out);

    for (int t = 1; t < STEPS; t++) {
        conv0(); mix0RU();
        conv1(); mix0H();
        conv2(); mix1RU();
        conv3(); mix1H();
        projK<<<(NROWS + 255)/256, 256>>>(Wp, bp, out + (size_t)t*NROWS*OUTD);
    }
}

// round 9
// speedup vs baseline: 4.0015x; 1.1437x over previous
#include <cuda_runtime.h>
#include <cuda_bf16.h>
#include <math.h>
#include <stdint.h>

#define NN 1024
#define BATCH 32
#define HID 64
#define OUTD 2
#define STEPS 12
#define NROWS (BATCH*NN)
typedef __nv_bfloat16 bf16;

// ---------------- PTX helpers ---------------------------------------------
__device__ __forceinline__ uint32_t smem_u32(const void* p) {
    uint32_t a;
    asm("{ .reg .u64 t; cvta.to.shared.u64 t, %1; cvt.u32.u64 %0, t; }" : "=r"(a) : "l"(p));
    return a;
}
__device__ __forceinline__ void cp16(uint32_t sa, const void* g) {
    asm volatile("cp.async.cg.shared.global [%0], [%1], 16;" :: "r"(sa), "l"(g) : "memory");
}
#define CP_COMMIT() asm volatile("cp.async.commit_group;" ::: "memory")
#define CP_WAIT(n)  asm volatile("cp.async.wait_group %0;" :: "n"(n) : "memory")
#define LDSM4(r, a) asm volatile( \
    "ldmatrix.sync.aligned.m8n8.x4.shared.b16 {%0,%1,%2,%3}, [%4];" \
    : "=r"((r)[0]), "=r"((r)[1]), "=r"((r)[2]), "=r"((r)[3]) : "r"(a))
#define LDSM2(r, a) asm volatile( \
    "ldmatrix.sync.aligned.m8n8.x2.shared.b16 {%0,%1}, [%2];" \
    : "=r"((r)[0]), "=r"((r)[1]) : "r"(a))
#define MMA16816(d, a, b) asm volatile( \
    "mma.sync.aligned.m16n8k16.row.col.f32.bf16.bf16.f32 " \
    "{%0,%1,%2,%3},{%4,%5,%6,%7},{%8,%9},{%0,%1,%2,%3};" \
    : "+f"((d)[0]), "+f"((d)[1]), "+f"((d)[2]), "+f"((d)[3]) \
    : "r"((a)[0]), "r"((a)[1]), "r"((a)[2]), "r"((a)[3]), "r"((b)[0]), "r"((b)[1]))
#define MMAS8(d, a, b) asm volatile( \
    "mma.sync.aligned.m16n8k32.row.col.s32.s8.s8.s32 " \
    "{%0,%1,%2,%3},{%4,%5,%6,%7},{%8,%9},{%0,%1,%2,%3};" \
    : "+r"((d)[0]), "+r"((d)[1]), "+r"((d)[2]), "+r"((d)[3]) \
    : "r"((a)[0]), "r"((a)[1]), "r"((a)[2]), "r"((a)[3]), "r"((b)[0]), "r"((b)[1]))

__device__ __forceinline__ void bsplit(float v, bf16& h, bf16& l) {
    h = __float2bfloat16(v);
    l = __float2bfloat16(v - __bfloat162float(h));
}

// ---------------- scratch -------------------------------------------------
__device__ float g_M[2u*NN*NN];
__device__ float g_state0[NROWS*HID];
__device__ float g_state1[NROWS*HID];
__device__ float g_decin [NROWS*OUTD];
__device__ float g_u     [NROWS*HID];
__device__ float g_rstate[NROWS*HID];
__device__ bf16 g_FAh[(size_t)NROWS*640], g_FAl[(size_t)NROWS*640];
__device__ bf16 g_FBh[(size_t)NROWS*640], g_FBl[(size_t)NROWS*640];
__device__ int8_t g_Aq1[(size_t)4*NN*NN], g_Aq2[(size_t)4*NN*NN];
__device__ int8_t g_Xq1[(size_t)4096*NN], g_Xq2[(size_t)4096*NN];
__device__ float g_sA[4*NN];
__device__ uint32_t g_bits[8*4096];   // [conv 0..3][parity][4096]
__device__ bf16 g_Wru0h[128*352], g_Wru0l[128*352];
__device__ bf16 g_Wh0h [64*352],  g_Wh0l [64*352];
__device__ bf16 g_Wru1h[128*640], g_Wru1l[128*640];
__device__ bf16 g_Wh1h [64*640],  g_Wh1l [64*640];

// ---------------- init (+ initial column maxes) ---------------------------
__global__ void initK(const float* __restrict__ enc, uint32_t* __restrict__ bits) {
    __shared__ uint32_t ms0[64], ms1[64];
    int tid = threadIdx.x;
    if (tid < 64) { ms0[tid] = 0; ms1[tid] = 0; }
    __syncthreads();
    int i = blockIdx.x*256 + tid;
    const int SZ = NROWS*HID;
    float s0v = 0.f, s1v = 0.f;
    if (i < SZ) {
        s0v = enc[i]; s1v = enc[SZ+i];
        g_state0[i] = s0v; g_state1[i] = s1v;
        int c = i & 63;
        atomicMax(&ms0[c], __float_as_uint(fabsf(s0v)));
        atomicMax(&ms1[c], __float_as_uint(fabsf(s1v)));
    }
    if (i < NROWS*OUTD) g_decin[i] = 0.f;
    __syncthreads();
    if (tid < 64 && i < SZ) {
        int b = (blockIdx.x*256) >> 16;
        atomicMax(&bits[(0*2+0)*4096 + b*66 + 2 + tid], ms0[tid]);   // conv0 state0
        atomicMax(&bits[(2*2+0)*4096 + b*128 + 64 + tid], ms1[tid]); // conv2 state1
    }
}

__global__ void precomputeM(const float* __restrict__ sup, uint32_t* __restrict__ bits) {
    if (blockIdx.z == 0 && blockIdx.y == 0) {
        int base = (blockIdx.x*256 + threadIdx.x)*8;
        #pragma unroll
        for (int k = 0; k < 8; k++) bits[base + k] = 0;
    }
    const int s = blockIdx.z;
    const float* __restrict__ S = sup + (size_t)s*NN*NN;
    float* __restrict__ Mo = g_M + (size_t)s*NN*NN;
    __shared__ float As[16][64], Bs[16][64];
    const int tid = threadIdx.x, tx = tid & 15, ty = tid >> 4;
    const int n0 = blockIdx.y*64, j0 = blockIdx.x*64;
    const int ar = tid >> 2, aq = (tid & 3)*4, br = tid >> 4, bq = (tid & 15)*4;
    float acc[4][4] = {};
    for (int kt = 0; kt < NN; kt += 16) {
        float4 av = *(const float4*)(S + (size_t)(n0+ar)*NN + kt + aq);
        As[aq][ar]=av.x; As[aq+1][ar]=av.y; As[aq+2][ar]=av.z; As[aq+3][ar]=av.w;
        *(float4*)&Bs[br][bq] = *(const float4*)(S + (size_t)(kt+br)*NN + j0 + bq);
        __syncthreads();
        #pragma unroll
        for (int k = 0; k < 16; k++) {
            float4 a = *(float4*)&As[k][ty*4], b = *(float4*)&Bs[k][tx*4];
            float arr[4]={a.x,a.y,a.z,a.w}, brr[4]={b.x,b.y,b.z,b.w};
            #pragma unroll
            for (int i=0;i<4;i++)
                #pragma unroll
                for (int j=0;j<4;j++) acc[i][j] += arr[i]*brr[j];
        }
        __syncthreads();
    }
    #pragma unroll
    for (int i=0;i<4;i++) { int n=n0+ty*4+i;
        #pragma unroll
        for (int j=0;j<4;j++) { int jc=j0+tx*4+j;
            Mo[(size_t)n*NN+jc] = 2.f*acc[i][j] - (n==jc?1.f:0.f); } }
}

// quantize operator rows to 2-limb int8 (limb2 scale 254)
__global__ void opQuant(const float* __restrict__ sup) {
    const int n = blockIdx.x, f = blockIdx.y, tid = threadIdx.x;
    const float* src = (f==0) ? sup : (f==1) ? g_M :
                       (f==2) ? sup + (size_t)NN*NN : g_M + (size_t)NN*NN;
    float4 v = *(const float4*)(src + (size_t)n*NN + tid*4);
    float mx = fmaxf(fmaxf(fabsf(v.x),fabsf(v.y)), fmaxf(fabsf(v.z),fabsf(v.w)));
    #pragma unroll
    for (int o = 16; o; o >>= 1) mx = fmaxf(mx, __shfl_xor_sync(0xffffffffu, mx, o));
    __shared__ float w[8]; __shared__ float sInv;
    if ((tid & 31) == 0) w[tid >> 5] = mx;
    __syncthreads();
    if (tid == 0) {
        float m = w[0];
        #pragma unroll
        for (int i = 1; i < 8; i++) m = fmaxf(m, w[i]);
        g_sA[f*NN + n] = (m > 0.f) ? m/127.f : 1.f;
        sInv = (m > 0.f) ? 127.f/m : 0.f;
    }
    __syncthreads();
    float inv = sInv;
    char4 q1, q2;
    float xs[4] = {v.x*inv, v.y*inv, v.z*inv, v.w*inv};
    int a1[4], a2[4];
    #pragma unroll
    for (int i = 0; i < 4; i++) {
        int q = __float2int_rn(xs[i]);
        q = q > 127 ? 127 : (q < -127 ? -127 : q);
        a1[i] = q;
        int r = __float2int_rn((xs[i] - (float)q)*254.f);
        a2[i] = r > 127 ? 127 : (r < -127 ? -127 : r);
    }
    q1.x=a1[0];q1.y=a1[1];q1.z=a1[2];q1.w=a1[3];
    q2.x=a2[0];q2.y=a2[1];q2.z=a2[2];q2.w=a2[3];
    size_t o = ((size_t)f*NN + n)*NN + tid*4;
    *(char4*)(g_Aq1 + o) = q1;
    *(char4*)(g_Aq2 + o) = q2;
}

// fused: m0 bf16 slice + transpose + 2-limb int8 quantize; zeroes other parity
__global__ void prepK(const float* __restrict__ inp, int Cin,
                      const float* __restrict__ st, int Ct,
                      const uint32_t* __restrict__ bitsRead,
                      uint32_t* __restrict__ bitsZero,
                      int m0off, int KP,
                      bf16* __restrict__ Fh, bf16* __restrict__ Fl) {
    __shared__ float t[32][33];
    int b = blockIdx.z, n0 = blockIdx.x*32, c0 = blockIdx.y*32;
    int tx = threadIdx.x, ty = threadIdx.y;
    if (blockIdx.x == 0 && blockIdx.y == 0) {
        int tid = ty*32 + tx;
        if (tid < 128) bitsZero[b*128 + tid] = 0;
    }
    int c = c0 + tx;
    float v = 0.f;
    size_t row = (size_t)b*NN + n0 + ty;
    if (c < Ct) {
        v = (c < Cin) ? inp[row*Cin + c] : st[row*HID + c - Cin];
        bf16 h, l; bsplit(v, h, l);
        size_t o = row*KP + m0off + c;
        Fh[o] = h; Fl[o] = l;
    }
    t[ty][tx] = v;
    __syncthreads();
    float val = t[tx][ty];
    int n = n0 + tx, cw = c0 + ty;
    if (cw < Ct) {
        float m = __uint_as_float(bitsRead[b*Ct + cw]);
        float rB = (m > 0.f) ? 127.f/m : 0.f;
        float x = val * rB;
        int q1 = __float2int_rn(x);
        q1 = q1 > 127 ? 127 : (q1 < -127 ? -127 : q1);
        int q2 = __float2int_rn((x - (float)q1)*254.f);
        q2 = q2 > 127 ? 127 : (q2 < -127 ? -127 : q2);
        size_t o = ((size_t)(b*Ct + cw))*NN + n;
        g_Xq1[o] = (int8_t)q1; g_Xq2[o] = (int8_t)q2;
    }
}

// ---------------- int8 diffusion: 256 thr, 128x64 tile, 3-stage -----------
#define QLDP 80
#define QA_B (128*QLDP)          // 10240
#define QB_B (64*QLDP)           // 5120
#define QSTAGE (2*QA_B + 2*QB_B) // 30720
#define QSMEM (3*QSTAGE)         // 92160

__global__ void __launch_bounds__(256, 2)
mmaDiffuseQ(int Ct, int NC, bf16* __restrict__ Fh, bf16* __restrict__ Fl,
            int Ctot, int KP, int colOff, const uint32_t* __restrict__ bitsRead) {
    extern __shared__ char sm[];
    uint32_t sb = smem_u32(sm);
    const int tid = threadIdx.x, wid = tid >> 5, lane = tid & 31;
    const int f = blockIdx.z, n0 = blockIdx.y*128, j0 = blockIdx.x*64;
    const int8_t* __restrict__ A1 = g_Aq1 + ((size_t)f*NN + n0)*NN;
    const int8_t* __restrict__ A2 = g_Aq2 + ((size_t)f*NN + n0)*NN;
    const int wm = wid >> 1, wn = wid & 1;
    int acch[2][4][4] = {}, accl[2][4][4] = {};

    const int brow = tid >> 2, bkq = (tid & 3)*16;
    const uint32_t boff = (uint32_t)(brow*QLDP + bkq);
    int jr = j0 + brow; if (jr >= NC) jr = NC - 1;

    #define Q_ISSUE(bufq, kt) do { \
        uint32_t s_ = sb + (bufq)*QSTAGE; \
        _Pragma("unroll") \
        for (int it = 0; it < 2; it++) { \
            int ai_ = tid + it*256; \
            int arow_ = ai_ >> 2, akq_ = (ai_ & 3)*16; \
            uint32_t ao_ = (uint32_t)(arow_*QLDP + akq_); \
            size_t ga_ = (size_t)arow_*NN + (kt) + akq_; \
            cp16(s_ + ao_,        A1 + ga_); \
            cp16(s_ + QA_B + ao_, A2 + ga_); \
        } \
        size_t gb_ = (size_t)jr*NN + (kt) + bkq; \
        cp16(s_ + 2*QA_B + boff,        g_Xq1 + gb_); \
        cp16(s_ + 2*QA_B + QB_B + boff, g_Xq2 + gb_); \
        CP_COMMIT(); \
    } while (0)

    Q_ISSUE(0, 0);
    Q_ISSUE(1, 64);
    for (int ch = 0; ch < 16; ch++) {
        if (ch < 15) CP_WAIT(1); else CP_WAIT(0);
        __syncthreads();
        if (ch + 2 < 16) Q_ISSUE((ch+2)%3, (ch+2)*64);
        uint32_t Ab = sb + (ch%3)*QSTAGE;
        uint32_t A2b = Ab + QA_B, B1b = Ab + 2*QA_B, B2b = Ab + 2*QA_B + QB_B;
        #pragma unroll
        for (int kb = 0; kb < 64; kb += 32) {
            uint32_t a1[2][4], a2[2][4], b1[4][2], b2[4][2];
            #pragma unroll
            for (int im = 0; im < 2; im++) {
                int row = wm*32 + im*16 + (lane & 15);
                uint32_t off = (uint32_t)(row*QLDP + kb + ((lane >> 4) << 4));
                LDSM4(a1[im], Ab + off);
                LDSM4(a2[im], A2b + off);
            }
            #pragma unroll
            for (int in = 0; in < 4; in++) {
                int row = wn*32 + in*8 + (lane & 7);
                uint32_t off = (uint32_t)(row*QLDP + kb + (((lane >> 3) & 1) << 4));
                LDSM2(b1[in], B1b + off);
                LDSM2(b2[in], B2b + off);
            }
            #pragma unroll
            for (int im = 0; im < 2; im++)
                #pragma unroll
                for (int in = 0; in < 4; in++) {
                    MMAS8(acch[im][in], a1[im], b1[in]);
                    MMAS8(accl[im][in], a1[im], b2[in]);
                    MMAS8(accl[im][in], a2[im], b1[in]);
                }
        }
        __syncthreads();
    }
    const int m = f + 1, r = lane >> 2, cp2 = (lane & 3)*2;
    const float INV = 1.f/254.f, IS = 1.f/127.f;
    #pragma unroll
    for (int in = 0; in < 4; in++) {
        int jG = j0 + wn*32 + in*8 + cp2;
        if (jG >= NC) continue;
        int b = jG / Ct, c = jG % Ct;
        float sb0 = __uint_as_float(bitsRead[jG])*IS;
        float sb1 = __uint_as_float(bitsRead[jG + 1])*IS;
        #pragma unroll
        for (int im = 0; im < 2; im++) {
            #pragma unroll
            for (int hh = 0; hh < 2; hh++) {
                int nG = n0 + wm*32 + im*16 + r + hh*8;
                float sa = g_sA[f*NN + nG];
                float v0 = sa*sb0*((float)acch[im][in][hh*2]   + (float)accl[im][in][hh*2]  *INV);
                float v1 = sa*sb1*((float)acch[im][in][hh*2+1] + (float)accl[im][in][hh*2+1]*INV);
                bf16 h0,l0,h1,l1; bsplit(v0,h0,l0); bsplit(v1,h1,l1);
                __nv_bfloat162 hv; hv.x=h0; hv.y=h1;
                __nv_bfloat162 lv; lv.x=l0; lv.y=l1;
                size_t base = (size_t)(b*NN + nG)*KP + m*Ctot + colOff + c;
                *(__nv_bfloat162*)(Fh + base) = hv;
                *(__nv_bfloat162*)(Fl + base) = lv;
            }
        }
    }
}

// ---------------- weight transpose/split (once) ---------------------------
__global__ void wsplitT(const float* __restrict__ W, bf16* __restrict__ Th,
                        bf16* __restrict__ Tl, int Ct, int O, int KP) {
    int i = blockIdx.x*blockDim.x + threadIdx.x;
    if (i >= O*KP) return;
    int o = i / KP, k = i % KP;
    float v = (k < 5*Ct) ? W[(size_t)k*O + o] : 0.f;
    bf16 h, l; bsplit(v, h, l);
    Th[i] = h; Tl[i] = l;
}

// ---------------- tensor-core mixing + fused GRU + fused column-max -------
#define MLDP 40
#define MA_B (128*MLDP*2)
#define MB_B (64*MLDP*2)
#define MSTAGE (2*MA_B + 2*MB_B)
#define MIX_SMEM (2*MSTAGE)

template<int MODE>
__global__ void __launch_bounds__(256)
mixTC(const bf16* __restrict__ FhA, const bf16* __restrict__ FlA,
      const bf16* __restrict__ FhB, const bf16* __restrict__ FlB,
      int KP, int nCh,
      const bf16* __restrict__ Wh, const bf16* __restrict__ Wl,
      const float* __restrict__ bias, const float* __restrict__ stateIn,
      float* __restrict__ stateOut,
      uint32_t* __restrict__ mx1, int ct1, int off1,
      uint32_t* __restrict__ mx2, int ct2, int off2) {
    extern __shared__ char smc[];
    __shared__ uint32_t mxs[64];
    uint32_t sb = smem_u32(smc);
    const int tid = threadIdx.x, wid = tid >> 5, lane = tid & 31;
    const int r0 = blockIdx.y*128, o0 = blockIdx.x*64;
    const int wm = wid >> 1, wn = wid & 1;
    if (tid < 64) mxs[tid] = 0;
    float acc[2][4][4] = {};

    #define MIX_ISSUE(buf, kt) do { \
        const bf16* Sh_ = (((kt) >> 6) & 1) ? FhB : FhA; \
        const bf16* Sl_ = (((kt) >> 6) & 1) ? FlB : FlA; \
        uint32_t s_ = sb + (buf)*MSTAGE; \
        _Pragma("unroll") \
        for (int it = 0; it < 2; it++) { \
            int v_ = tid + it*256; \
            int row_ = v_ >> 2, kq_ = (v_ & 3)*8; \
            uint32_t off_ = (uint32_t)(row_*(MLDP*2) + kq_*2); \
            size_t g_ = (size_t)(r0+row_)*KP + (kt) + kq_; \
            cp16(s_ + off_, Sh_ + g_); \
            cp16(s_ + MA_B + off_, Sl_ + g_); \
        } \
        { int row_ = tid >> 2, kq_ = (tid & 3)*8; \
          uint32_t off_ = (uint32_t)(row_*(MLDP*2) + kq_*2); \
          size_t g_ = (size_t)(o0+row_)*KP + (kt) + kq_; \
          cp16(s_ + 2*MA_B + off_, Wh + g_); \
          cp16(s_ + 2*MA_B + MB_B + off_, Wl + g_); } \
        CP_COMMIT(); \
    } while (0)

    MIX_ISSUE(0, 0);
    for (int ch = 0; ch < nCh; ch++) {
        if (ch + 1 < nCh) { MIX_ISSUE((ch+1)&1, (ch+1)*32); CP_WAIT(1); }
        else CP_WAIT(0);
        __syncthreads();
        uint32_t Ab = sb + (ch&1)*MSTAGE, Alb = Ab + MA_B, Bb = Ab + 2*MA_B, Blb = Bb + MB_B;
        #pragma unroll
        for (int k16 = 0; k16 < 2; k16++) {
            const int kk = k16*16;
            uint32_t ah[2][4], al[2][4], bh[4][2], bl[4][2];
            #pragma unroll
            for (int im = 0; im < 2; im++) {
                int row = wm*32 + im*16 + (lane & 15);
                int col = kk + ((lane >> 4) << 3);
                uint32_t off = (uint32_t)(row*(MLDP*2) + col*2);
                LDSM4(ah[im], Ab + off);
                LDSM4(al[im], Alb + off);
            }
            #pragma unroll
            for (int in = 0; in < 4; in++) {
                int row = wn*32 + in*8 + (lane & 7);
                int col = kk + (((lane >> 3) & 1) << 3);
                uint32_t off = (uint32_t)(row*(MLDP*2) + col*2);
                LDSM2(bh[in], Bb + off);
                LDSM2(bl[in], Blb + off);
            }
            #pragma unroll
            for (int im = 0; im < 2; im++)
                #pragma unroll
                for (int in = 0; in < 4; in++) {
                    MMA16816(acc[im][in], ah[im], bh[in]);
                    MMA16816(acc[im][in], ah[im], bl[in]);
                    MMA16816(acc[im][in], al[im], bh[in]);
                }
        }
        __syncthreads();
    }
    const int r = lane >> 2, cp2 = (lane & 3)*2;
    const int b = r0 >> 10;
    #pragma unroll
    for (int im = 0; im < 2; im++) {
        #pragma unroll
        for (int in = 0; in < 4; in++) {
            int o = o0 + wn*32 + in*8 + cp2;
            float b0 = bias[o], b1 = bias[o+1];
            #pragma unroll
            for (int hh = 0; hh < 2; hh++) {
                int row = r0 + wm*32 + im*16 + r + hh*8;
                float v0 = acc[im][in][hh*2], v1 = acc[im][in][hh*2+1];
                if (MODE == 0) {
                    float gg0 = 1.f/(1.f + expf(-(v0 + b0)));
                    float gg1 = 1.f/(1.f + expf(-(v1 + b1)));
                    if (o < HID) {
                        float w0 = gg0 * stateIn[row*HID + o];
                        float w1 = gg1 * stateIn[row*HID + o+1];
                        g_rstate[row*HID + o]   = w0;
                        g_rstate[row*HID + o+1] = w1;
                        atomicMax(&mxs[o],   __float_as_uint(fabsf(w0)));
                        atomicMax(&mxs[o+1], __float_as_uint(fabsf(w1)));
                    } else {
                        g_u[row*HID + o - HID]     = gg0;
                        g_u[row*HID + o + 1 - HID] = gg1;
                    }
                } else {
                    float hT0 = tanhf(v0 + b0), hT1 = tanhf(v1 + b1);
                    float u0 = g_u[row*HID + o], u1 = g_u[row*HID + o+1];
                    float s0 = stateOut[row*HID + o], s1 = stateOut[row*HID + o+1];
                    float w0 = u0*s0 + (1.f - u0)*hT0;
                    float w1 = u1*s1 + (1.f - u1)*hT1;
                    stateOut[row*HID + o]   = w0;
                    stateOut[row*HID + o+1] = w1;
                    atomicMax(&mxs[o],   __float_as_uint(fabsf(w0)));
                    atomicMax(&mxs[o+1], __float_as_uint(fabsf(w1)));
                }
            }
        }
    }
    __syncthreads();
    if (tid < 64 && blockIdx.x == 0) {
        if (mx1) atomicMax(&mx1[b*ct1 + off1 + tid], mxs[tid]);
        if (mx2) atomicMax(&mx2[b*ct2 + off2 + tid], mxs[tid]);
    }
}

__global__ void projK(const float* __restrict__ Wp, const float* __restrict__ bp,
                      float* __restrict__ out_t,
                      uint32_t* __restrict__ d0, uint32_t* __restrict__ d1) {
    __shared__ uint32_t m0, m1;
    int tid = threadIdx.x;
    if (tid == 0) { m0 = 0; m1 = 0; }
    __syncthreads();
    int row = blockIdx.x*256 + tid;
    const float* s = g_state1 + (size_t)row*HID;
    float a0 = bp[0], a1 = bp[1];
    #pragma unroll
    for (int h = 0; h < HID; h++) { float v = s[h]; a0 += v*Wp[h*2]; a1 += v*Wp[h*2+1]; }
    out_t[row*2] = a0; out_t[row*2+1] = a1;
    g_decin[row*2] = a0; g_decin[row*2+1] = a1;
    atomicMax(&m0, __float_as_uint(fabsf(a0)));
    atomicMax(&m1, __float_as_uint(fabsf(a1)));
    __syncthreads();
    if (tid == 0) {
        int b = blockIdx.x >> 2;
        atomicMax(&d0[b*66 + 0], m0); atomicMax(&d0[b*66 + 1], m1);
        atomicMax(&d1[b*66 + 0], m0); atomicMax(&d1[b*66 + 1], m1);
    }
}

// -------------------------------------------------------------------------
extern "C" void kernel_launch(void* const* d_in, const int* in_sizes, int n_in,
                              void* d_out, int out_size) {
    const float* enc  = (const float*)d_in[0];
    const float* sup  = (const float*)d_in[1];
    const float* Wru0 = (const float*)d_in[2];
    const float* bru0 = (const float*)d_in[3];
    const float* Wh0  = (const float*)d_in[4];
    const float* bh0  = (const float*)d_in[5];
    const float* Wru1 = (const float*)d_in[6];
    const float* bru1 = (const float*)d_in[7];
    const float* Wh1  = (const float*)d_in[8];
    const float* bh1  = (const float*)d_in[9];
    const float* Wp   = (const float*)d_in[10];
    const float* bp   = (const float*)d_in[11];
    float* out = (float*)d_out;

    void *pv;
    cudaGetSymbolAddress(&pv, g_state0); float* pS0  = (float*)pv;
    cudaGetSymbolAddress(&pv, g_state1); float* pS1  = (float*)pv;
    cudaGetSymbolAddress(&pv, g_decin);  float* pDec = (float*)pv;
    cudaGetSymbolAddress(&pv, g_rstate); float* pRst = (float*)pv;
    cudaGetSymbolAddress(&pv, g_FAh); bf16* FAh = (bf16*)pv;
    cudaGetSymbolAddress(&pv, g_FAl); bf16* FAl = (bf16*)pv;
    cudaGetSymbolAddress(&pv, g_FBh); bf16* FBh = (bf16*)pv;
    cudaGetSymbolAddress(&pv, g_FBl); bf16* FBl = (bf16*)pv;
    cudaGetSymbolAddress(&pv, g_bits); uint32_t* BITS = (uint32_t*)pv;
    cudaGetSymbolAddress(&pv, g_Wru0h); bf16* Wru0h = (bf16*)pv;
    cudaGetSymbolAddress(&pv, g_Wru0l); bf16* Wru0l = (bf16*)pv;
    cudaGetSymbolAddress(&pv, g_Wh0h);  bf16* Wh0h  = (bf16*)pv;
    cudaGetSymbolAddress(&pv, g_Wh0l);  bf16* Wh0l  = (bf16*)pv;
    cudaGetSymbolAddress(&pv, g_Wru1h); bf16* Wru1h = (bf16*)pv;
    cudaGetSymbolAddress(&pv, g_Wru1l); bf16* Wru1l = (bf16*)pv;
    cudaGetSymbolAddress(&pv, g_Wh1h);  bf16* Wh1h  = (bf16*)pv;
    cudaGetSymbolAddress(&pv, g_Wh1l);  bf16* Wh1l  = (bf16*)pv;

    auto BB = [&](int conv, int par) { return BITS + (conv*2 + par)*4096; };

    cudaFuncSetAttribute(mmaDiffuseQ, cudaFuncAttributeMaxDynamicSharedMemorySize, QSMEM);
    cudaFuncSetAttribute(mixTC<0>, cudaFuncAttributeMaxDynamicSharedMemorySize, MIX_SMEM);
    cudaFuncSetAttribute(mixTC<1>, cudaFuncAttributeMaxDynamicSharedMemorySize, MIX_SMEM);

    precomputeM<<<dim3(16,16,2), 256>>>(sup, BITS);
    initK<<<(NROWS*HID + 255)/256, 256>>>(enc, BITS);
    opQuant<<<dim3(NN,4), 256>>>(sup);
    wsplitT<<<(128*352 + 255)/256, 256>>>(Wru0, Wru0h, Wru0l, 66, 128, 352);
    wsplitT<<<(64*352 + 255)/256, 256>>>(Wh0, Wh0h, Wh0l, 66, 64, 352);
    wsplitT<<<(128*640 + 255)/256, 256>>>(Wru1, Wru1h, Wru1l, 128, 128, 640);
    wsplitT<<<(64*640 + 255)/256, 256>>>(Wh1, Wh1h, Wh1l, 128, 64, 640);

    for (int t = 0; t < STEPS; t++) {
        const int p = t & 1, q = p ^ 1;
        // conv0: x=[decin|state0]
        prepK<<<dim3(32,3,32), dim3(32,32)>>>(pDec, 2, pS0, 66, BB(0,p), BB(0,q), 0, 352, FAh, FAl);
        mmaDiffuseQ<<<dim3(33,8,4), 256, QSMEM>>>(66, 2112, FAh, FAl, 66, 352, 0, BB(0,p));
        mixTC<0><<<dim3(2,256), 256, MIX_SMEM>>>(FAh, FAl, FAh, FAl, 352, 11, Wru0h, Wru0l, bru0, pS0, 0,
                                                 BB(1,p), 66, 2, (uint32_t*)0, 0, 0);
        // conv1: x2=[decin|r*state0]
        prepK<<<dim3(32,3,32), dim3(32,32)>>>(pDec, 2, pRst, 66, BB(1,p), BB(1,q), 0, 352, FBh, FBl);
        mmaDiffuseQ<<<dim3(33,8,4), 256, QSMEM>>>(66, 2112, FBh, FBl, 66, 352, 0, BB(1,p));
        mixTC<1><<<dim3(1,256), 256, MIX_SMEM>>>(FBh, FBl, FBh, FBl, 352, 11, Wh0h, Wh0l, bh0, 0, pS0,
                                                 BB(0,q), 66, 2, BB(2,p), 128, 0);
        // conv2: x=[state0|state1]
        prepK<<<dim3(32,4,32), dim3(32,32)>>>(pS0, 64, pS1, 128, BB(2,p), BB(2,q), 0, 640, FAh, FAl);
        mmaDiffuseQ<<<dim3(64,8,4), 256, QSMEM>>>(128, 4096, FAh, FAl, 128, 640, 0, BB(2,p));
        mixTC<0><<<dim3(2,256), 256, MIX_SMEM>>>(FAh, FAl, FAh, FAl, 640, 20, Wru1h, Wru1l, bru1, pS1, 0,
                                                 BB(3,p), 64, 0, (uint32_t*)0, 0, 0);
        // conv3: diffuse r*state1 only; state0 feats read from FA
        prepK<<<dim3(32,2,32), dim3(32,32)>>>((const float*)0, 0, pRst, 64, BB(3,p), BB(3,q), 64, 640, FBh, FBl);
        mmaDiffuseQ<<<dim3(32,8,4), 256, QSMEM>>>(64, 2048, FBh, FBl, 128, 640, 64, BB(3,p));
        mixTC<1><<<dim3(1,256), 256, MIX_SMEM>>>(FAh, FAl, FBh, FBl, 640, 20, Wh1h, Wh1l, bh1, 0, pS1,
                                                 BB(2,q), 128, 64, (uint32_t*)0, 0, 0);
        projK<<<NROWS/256, 256>>>(Wp, bp, out + (size_t)t*NROWS*OUTD, BB(0,q), BB(1,q));
    }
}

// round 10
// speedup vs baseline: 4.2160x; 1.0536x over previous
#include <cuda_runtime.h>
#include <cuda_bf16.h>
#include <math.h>
#include <stdint.h>

#define NN 1024
#define BATCH 32
#define HID 64
#define OUTD 2
#define STEPS 12
#define NROWS (BATCH*NN)
typedef __nv_bfloat16 bf16;

// ---------------- PTX helpers ---------------------------------------------
__device__ __forceinline__ uint32_t smem_u32(const void* p) {
    uint32_t a;
    asm("{ .reg .u64 t; cvta.to.shared.u64 t, %1; cvt.u32.u64 %0, t; }" : "=r"(a) : "l"(p));
    return a;
}
__device__ __forceinline__ void cp16(uint32_t sa, const void* g) {
    asm volatile("cp.async.cg.shared.global [%0], [%1], 16;" :: "r"(sa), "l"(g) : "memory");
}
#define CP_COMMIT() asm volatile("cp.async.commit_group;" ::: "memory")
#define CP_WAIT(n)  asm volatile("cp.async.wait_group %0;" :: "n"(n) : "memory")
#define LDSM4(r, a) asm volatile( \
    "ldmatrix.sync.aligned.m8n8.x4.shared.b16 {%0,%1,%2,%3}, [%4];" \
    : "=r"((r)[0]), "=r"((r)[1]), "=r"((r)[2]), "=r"((r)[3]) : "r"(a))
#define LDSM2(r, a) asm volatile( \
    "ldmatrix.sync.aligned.m8n8.x2.shared.b16 {%0,%1}, [%2];" \
    : "=r"((r)[0]), "=r"((r)[1]) : "r"(a))
#define MMA16816(d, a, b) asm volatile( \
    "mma.sync.aligned.m16n8k16.row.col.f32.bf16.bf16.f32 " \
    "{%0,%1,%2,%3},{%4,%5,%6,%7},{%8,%9},{%0,%1,%2,%3};" \
    : "+f"((d)[0]), "+f"((d)[1]), "+f"((d)[2]), "+f"((d)[3]) \
    : "r"((a)[0]), "r"((a)[1]), "r"((a)[2]), "r"((a)[3]), "r"((b)[0]), "r"((b)[1]))
#define MMAS8(d, a, b) asm volatile( \
    "mma.sync.aligned.m16n8k32.row.col.s32.s8.s8.s32 " \
    "{%0,%1,%2,%3},{%4,%5,%6,%7},{%8,%9},{%0,%1,%2,%3};" \
    : "+r"((d)[0]), "+r"((d)[1]), "+r"((d)[2]), "+r"((d)[3]) \
    : "r"((a)[0]), "r"((a)[1]), "r"((a)[2]), "r"((a)[3]), "r"((b)[0]), "r"((b)[1]))

__device__ __forceinline__ void bsplit(float v, bf16& h, bf16& l) {
    h = __float2bfloat16(v);
    l = __float2bfloat16(v - __bfloat162float(h));
}

// ---------------- scratch -------------------------------------------------
__device__ float g_M[2u*NN*NN];
__device__ float g_state0[NROWS*HID];
__device__ float g_state1[NROWS*HID];
__device__ float g_decin [NROWS*OUTD];
__device__ float g_u     [NROWS*HID];
__device__ float g_rstate[NROWS*HID];
__device__ bf16 g_FAh[(size_t)NROWS*640], g_FAl[(size_t)NROWS*640];
__device__ bf16 g_FBh[(size_t)NROWS*640], g_FBl[(size_t)NROWS*640];
__device__ int8_t g_Aq1[(size_t)4*NN*NN], g_Aq2[(size_t)4*NN*NN];
__device__ int8_t g_Xq1[(size_t)4096*NN], g_Xq2[(size_t)4096*NN];
__device__ float g_sA[4*NN];
__device__ uint32_t g_bits[8*4096];   // [conv 0..3][parity][4096]
__device__ bf16 g_Wru0h[128*352], g_Wru0l[128*352];
__device__ bf16 g_Wh0h [64*352],  g_Wh0l [64*352];
__device__ bf16 g_Wru1h[128*640], g_Wru1l[128*640];
__device__ bf16 g_Wh1h [64*640],  g_Wh1l [64*640];

// ---------------- init (+ initial column maxes) ---------------------------
// layer-0 channel order is [state0 (0..63) | decin (64,65)]
__global__ void initK(const float* __restrict__ enc, uint32_t* __restrict__ bits) {
    __shared__ uint32_t ms0[64], ms1[64];
    int tid = threadIdx.x;
    if (tid < 64) { ms0[tid] = 0; ms1[tid] = 0; }
    __syncthreads();
    int i = blockIdx.x*256 + tid;
    const int SZ = NROWS*HID;
    if (i < SZ) {
        float s0v = enc[i], s1v = enc[SZ+i];
        g_state0[i] = s0v; g_state1[i] = s1v;
        int c = i & 63;
        atomicMax(&ms0[c], __float_as_uint(fabsf(s0v)));
        atomicMax(&ms1[c], __float_as_uint(fabsf(s1v)));
    }
    if (i < NROWS*OUTD) g_decin[i] = 0.f;
    __syncthreads();
    if (tid < 64 && i < SZ) {
        int b = (blockIdx.x*256) >> 16;
        atomicMax(&bits[(0*2+0)*4096 + b*66 + tid], ms0[tid]);        // conv0 state0
        atomicMax(&bits[(2*2+0)*4096 + b*128 + 64 + tid], ms1[tid]);  // conv2 state1
    }
}

__global__ void precomputeM(const float* __restrict__ sup, uint32_t* __restrict__ bits) {
    if (blockIdx.z == 0 && blockIdx.y == 0) {
        int base = (blockIdx.x*256 + threadIdx.x)*8;
        #pragma unroll
        for (int k = 0; k < 8; k++) bits[base + k] = 0;
    }
    const int s = blockIdx.z;
    const float* __restrict__ S = sup + (size_t)s*NN*NN;
    float* __restrict__ Mo = g_M + (size_t)s*NN*NN;
    __shared__ float As[16][64], Bs[16][64];
    const int tid = threadIdx.x, tx = tid & 15, ty = tid >> 4;
    const int n0 = blockIdx.y*64, j0 = blockIdx.x*64;
    const int ar = tid >> 2, aq = (tid & 3)*4, br = tid >> 4, bq = (tid & 15)*4;
    float acc[4][4] = {};
    for (int kt = 0; kt < NN; kt += 16) {
        float4 av = *(const float4*)(S + (size_t)(n0+ar)*NN + kt + aq);
        As[aq][ar]=av.x; As[aq+1][ar]=av.y; As[aq+2][ar]=av.z; As[aq+3][ar]=av.w;
        *(float4*)&Bs[br][bq] = *(const float4*)(S + (size_t)(kt+br)*NN + j0 + bq);
        __syncthreads();
        #pragma unroll
        for (int k = 0; k < 16; k++) {
            float4 a = *(float4*)&As[k][ty*4], b = *(float4*)&Bs[k][tx*4];
            float arr[4]={a.x,a.y,a.z,a.w}, brr[4]={b.x,b.y,b.z,b.w};
            #pragma unroll
            for (int i=0;i<4;i++)
                #pragma unroll
                for (int j=0;j<4;j++) acc[i][j] += arr[i]*brr[j];
        }
        __syncthreads();
    }
    #pragma unroll
    for (int i=0;i<4;i++) { int n=n0+ty*4+i;
        #pragma unroll
        for (int j=0;j<4;j++) { int jc=j0+tx*4+j;
            Mo[(size_t)n*NN+jc] = 2.f*acc[i][j] - (n==jc?1.f:0.f); } }
}

// quantize operator rows to 2-limb int8 (limb2 scale 254)
__global__ void opQuant(const float* __restrict__ sup) {
    const int n = blockIdx.x, f = blockIdx.y, tid = threadIdx.x;
    const float* src = (f==0) ? sup : (f==1) ? g_M :
                       (f==2) ? sup + (size_t)NN*NN : g_M + (size_t)NN*NN;
    float4 v = *(const float4*)(src + (size_t)n*NN + tid*4);
    float mx = fmaxf(fmaxf(fabsf(v.x),fabsf(v.y)), fmaxf(fabsf(v.z),fabsf(v.w)));
    #pragma unroll
    for (int o = 16; o; o >>= 1) mx = fmaxf(mx, __shfl_xor_sync(0xffffffffu, mx, o));
    __shared__ float w[8]; __shared__ float sInv;
    if ((tid & 31) == 0) w[tid >> 5] = mx;
    __syncthreads();
    if (tid == 0) {
        float m = w[0];
        #pragma unroll
        for (int i = 1; i < 8; i++) m = fmaxf(m, w[i]);
        g_sA[f*NN + n] = (m > 0.f) ? m/127.f : 1.f;
        sInv = (m > 0.f) ? 127.f/m : 0.f;
    }
    __syncthreads();
    float inv = sInv;
    char4 q1, q2;
    float xs[4] = {v.x*inv, v.y*inv, v.z*inv, v.w*inv};
    int a1[4], a2[4];
    #pragma unroll
    for (int i = 0; i < 4; i++) {
        int q = __float2int_rn(xs[i]);
        q = q > 127 ? 127 : (q < -127 ? -127 : q);
        a1[i] = q;
        int r = __float2int_rn((xs[i] - (float)q)*254.f);
        a2[i] = r > 127 ? 127 : (r < -127 ? -127 : r);
    }
    q1.x=a1[0];q1.y=a1[1];q1.z=a1[2];q1.w=a1[3];
    q2.x=a2[0];q2.y=a2[1];q2.z=a2[2];q2.w=a2[3];
    size_t o = ((size_t)f*NN + n)*NN + tid*4;
    *(char4*)(g_Aq1 + o) = q1;
    *(char4*)(g_Aq2 + o) = q2;
}

// ------- vectorized prep: 64x64 tile, m0 bf16 write + transposed quant ----
__global__ void __launch_bounds__(256)
prepK(const float* __restrict__ src, int Ct, int cOff,
      const uint32_t* __restrict__ bitsRead, uint32_t* __restrict__ bitsZero,
      int m0col, int KP, bf16* __restrict__ Fh, bf16* __restrict__ Fl) {
    __shared__ float t[64][65];
    __shared__ float scale[64];
    const int b = blockIdx.y, n0 = blockIdx.x*64;
    const int tid = threadIdx.x;
    if (bitsZero && blockIdx.x == 0 && tid < 128) bitsZero[b*128 + tid] = 0;
    if (tid < 64) {
        float m = __uint_as_float(bitsRead[b*Ct + cOff + tid]);
        scale[tid] = (m > 0.f) ? 127.f/m : 0.f;
    }
    #pragma unroll
    for (int i = 0; i < 4; i++) {
        int u = tid + i*256;
        int r = u >> 4, c4 = (u & 15)*4;
        float4 v = *(const float4*)(src + ((size_t)(b*NN + n0 + r))*64 + c4);
        t[r][c4] = v.x; t[r][c4+1] = v.y; t[r][c4+2] = v.z; t[r][c4+3] = v.w;
        bf16 h0,l0,h1,l1,h2,l2,h3,l3;
        bsplit(v.x,h0,l0); bsplit(v.y,h1,l1); bsplit(v.z,h2,l2); bsplit(v.w,h3,l3);
        __nv_bfloat162 ha; ha.x=h0; ha.y=h1;
        __nv_bfloat162 hb; hb.x=h2; hb.y=h3;
        __nv_bfloat162 la; la.x=l0; la.y=l1;
        __nv_bfloat162 lb; lb.x=l2; lb.y=l3;
        size_t o = ((size_t)(b*NN + n0 + r))*KP + m0col + c4;
        *(__nv_bfloat162*)(Fh+o) = ha; *(__nv_bfloat162*)(Fh+o+2) = hb;
        *(__nv_bfloat162*)(Fl+o) = la; *(__nv_bfloat162*)(Fl+o+2) = lb;
    }
    __syncthreads();
    #pragma unroll
    for (int i = 0; i < 4; i++) {
        int u = tid + i*256;
        int cw = u >> 4, ng = (u & 15)*4;
        float rB = scale[cw];
        char q1[4], q2[4];
        #pragma unroll
        for (int j = 0; j < 4; j++) {
            float x = t[ng+j][cw] * rB;
            int a = __float2int_rn(x);
            a = a > 127 ? 127 : (a < -127 ? -127 : a);
            int r2 = __float2int_rn((x - (float)a)*254.f);
            r2 = r2 > 127 ? 127 : (r2 < -127 ? -127 : r2);
            q1[j] = (char)a; q2[j] = (char)r2;
        }
        size_t o = ((size_t)(b*Ct + cOff + cw))*NN + n0 + ng;
        *(char4*)(g_Xq1+o) = make_char4(q1[0],q1[1],q1[2],q1[3]);
        *(char4*)(g_Xq2+o) = make_char4(q2[0],q2[1],q2[2],q2[3]);
    }
}

// decin (2 cols) -> FA/FB m0 cols 64-65 + shared Xq rows b*66+64,65
__global__ void prepDec(bf16* __restrict__ FAh, bf16* __restrict__ FAl,
                        bf16* __restrict__ FBh, bf16* __restrict__ FBl,
                        const uint32_t* __restrict__ bits) {
    int i = blockIdx.x*256 + threadIdx.x;
    if (i >= NROWS) return;
    int b = i >> 10, n = i & 1023;
    float v0 = g_decin[i*2], v1 = g_decin[i*2+1];
    bf16 h0,l0,h1,l1; bsplit(v0,h0,l0); bsplit(v1,h1,l1);
    __nv_bfloat162 hv; hv.x=h0; hv.y=h1;
    __nv_bfloat162 lv; lv.x=l0; lv.y=l1;
    size_t o = (size_t)i*352 + 64;
    *(__nv_bfloat162*)(FAh+o) = hv; *(__nv_bfloat162*)(FAl+o) = lv;
    *(__nv_bfloat162*)(FBh+o) = hv; *(__nv_bfloat162*)(FBl+o) = lv;
    #pragma unroll
    for (int c = 0; c < 2; c++) {
        float m = __uint_as_float(bits[b*66 + 64 + c]);
        float rB = (m > 0.f) ? 127.f/m : 0.f;
        float x = ((c == 0) ? v0 : v1) * rB;
        int a = __float2int_rn(x); a = a > 127 ? 127 : (a < -127 ? -127 : a);
        int r2 = __float2int_rn((x - (float)a)*254.f);
        r2 = r2 > 127 ? 127 : (r2 < -127 ? -127 : r2);
        size_t q = ((size_t)(b*66 + 64 + c))*NN + n;
        g_Xq1[q] = (int8_t)a; g_Xq2[q] = (int8_t)r2;
    }
}

// ---------------- int8 diffusion: 256 thr, 128x64 tile, 3-stage -----------
#define QLDP 80
#define QA_B (128*QLDP)
#define QB_B (64*QLDP)
#define QSTAGE (2*QA_B + 2*QB_B)
#define QSMEM (3*QSTAGE)

__global__ void __launch_bounds__(256, 2)
mmaDiffuseQ(int Ct, int NC, bf16* __restrict__ Fh, bf16* __restrict__ Fl,
            int Ctot, int KP, int colOff, const uint32_t* __restrict__ bitsRead) {
    extern __shared__ char sm[];
    uint32_t sb = smem_u32(sm);
    const int tid = threadIdx.x, wid = tid >> 5, lane = tid & 31;
    const int f = blockIdx.z, n0 = blockIdx.y*128, j0 = blockIdx.x*64;
    const int8_t* __restrict__ A1 = g_Aq1 + ((size_t)f*NN + n0)*NN;
    const int8_t* __restrict__ A2 = g_Aq2 + ((size_t)f*NN + n0)*NN;
    const int wm = wid >> 1, wn = wid & 1;
    int acch[2][4][4] = {}, accl[2][4][4] = {};

    const int brow = tid >> 2, bkq = (tid & 3)*16;
    const uint32_t boff = (uint32_t)(brow*QLDP + bkq);
    int jr = j0 + brow; if (jr >= NC) jr = NC - 1;

    #define Q_ISSUE(bufq, kt) do { \
        uint32_t s_ = sb + (bufq)*QSTAGE; \
        _Pragma("unroll") \
        for (int it = 0; it < 2; it++) { \
            int ai_ = tid + it*256; \
            int arow_ = ai_ >> 2, akq_ = (ai_ & 3)*16; \
            uint32_t ao_ = (uint32_t)(arow_*QLDP + akq_); \
            size_t ga_ = (size_t)arow_*NN + (kt) + akq_; \
            cp16(s_ + ao_,        A1 + ga_); \
            cp16(s_ + QA_B + ao_, A2 + ga_); \
        } \
        size_t gb_ = (size_t)jr*NN + (kt) + bkq; \
        cp16(s_ + 2*QA_B + boff,        g_Xq1 + gb_); \
        cp16(s_ + 2*QA_B + QB_B + boff, g_Xq2 + gb_); \
        CP_COMMIT(); \
    } while (0)

    Q_ISSUE(0, 0);
    Q_ISSUE(1, 64);
    for (int ch = 0; ch < 16; ch++) {
        if (ch < 15) CP_WAIT(1); else CP_WAIT(0);
        __syncthreads();
        if (ch + 2 < 16) Q_ISSUE((ch+2)%3, (ch+2)*64);
        uint32_t Ab = sb + (ch%3)*QSTAGE;
        uint32_t A2b = Ab + QA_B, B1b = Ab + 2*QA_B, B2b = Ab + 2*QA_B + QB_B;
        #pragma unroll
        for (int kb = 0; kb < 64; kb += 32) {
            uint32_t a1[2][4], a2[2][4], b1[4][2], b2[4][2];
            #pragma unroll
            for (int im = 0; im < 2; im++) {
                int row = wm*32 + im*16 + (lane & 15);
                uint32_t off = (uint32_t)(row*QLDP + kb + ((lane >> 4) << 4));
                LDSM4(a1[im], Ab + off);
                LDSM4(a2[im], A2b + off);
            }
            #pragma unroll
            for (int in = 0; in < 4; in++) {
                int row = wn*32 + in*8 + (lane & 7);
                uint32_t off = (uint32_t)(row*QLDP + kb + (((lane >> 3) & 1) << 4));
                LDSM2(b1[in], B1b + off);
                LDSM2(b2[in], B2b + off);
            }
            // separated sweeps: no back-to-back same-accumulator mma
            #pragma unroll
            for (int im = 0; im < 2; im++)
                #pragma unroll
                for (int in = 0; in < 4; in++) MMAS8(acch[im][in], a1[im], b1[in]);
            #pragma unroll
            for (int im = 0; im < 2; im++)
                #pragma unroll
                for (int in = 0; in < 4; in++) MMAS8(accl[im][in], a1[im], b2[in]);
            #pragma unroll
            for (int im = 0; im < 2; im++)
                #pragma unroll
                for (int in = 0; in < 4; in++) MMAS8(accl[im][in], a2[im], b1[in]);
        }
        __syncthreads();
    }
    const int m = f + 1, r = lane >> 2, cp2 = (lane & 3)*2;
    const float INV = 1.f/254.f, IS = 1.f/127.f;
    #pragma unroll
    for (int in = 0; in < 4; in++) {
        int jG = j0 + wn*32 + in*8 + cp2;
        if (jG >= NC) continue;
        int b = jG / Ct, c = jG % Ct;
        float sb0 = __uint_as_float(bitsRead[jG])*IS;
        float sb1 = __uint_as_float(bitsRead[jG + 1])*IS;
        #pragma unroll
        for (int im = 0; im < 2; im++) {
            #pragma unroll
            for (int hh = 0; hh < 2; hh++) {
                int nG = n0 + wm*32 + im*16 + r + hh*8;
                float sa = g_sA[f*NN + nG];
                float v0 = sa*sb0*((float)acch[im][in][hh*2]   + (float)accl[im][in][hh*2]  *INV);
                float v1 = sa*sb1*((float)acch[im][in][hh*2+1] + (float)accl[im][in][hh*2+1]*INV);
                bf16 h0,l0,h1,l1; bsplit(v0,h0,l0); bsplit(v1,h1,l1);
                __nv_bfloat162 hv; hv.x=h0; hv.y=h1;
                __nv_bfloat162 lv; lv.x=l0; lv.y=l1;
                size_t base = (size_t)(b*NN + nG)*KP + m*Ctot + colOff + c;
                *(__nv_bfloat162*)(Fh + base) = hv;
                *(__nv_bfloat162*)(Fl + base) = lv;
            }
        }
    }
}

// ---------------- weight transpose/split (once) ---------------------------
// remap: layer-0 channel order [state0|decin] -> original [decin|state0]
__global__ void wsplitT(const float* __restrict__ W, bf16* __restrict__ Th,
                        bf16* __restrict__ Tl, int Ct, int O, int KP, int remap) {
    int i = blockIdx.x*blockDim.x + threadIdx.x;
    if (i >= O*KP) return;
    int o = i / KP, k = i % KP;
    float v = 0.f;
    if (k < 5*Ct) {
        int m = k / Ct, c = k % Ct;
        int oc = remap ? ((c < 64) ? c + 2 : c - 64) : c;
        v = W[((size_t)m*Ct + oc)*O + o];
    }
    bf16 h, l; bsplit(v, h, l);
    Th[i] = h; Tl[i] = l;
}

// ---------------- tensor-core mixing + fused GRU + fused column-max -------
#define MLDP 40
#define MA_B (128*MLDP*2)
#define MB_B (64*MLDP*2)
#define MSTAGE (2*MA_B + 2*MB_B)
#define MIX_SMEM (2*MSTAGE)

template<int MODE>
__global__ void __launch_bounds__(256)
mixTC(const bf16* __restrict__ FhA, const bf16* __restrict__ FlA,
      const bf16* __restrict__ FhB, const bf16* __restrict__ FlB,
      int KP, int nCh,
      const bf16* __restrict__ Wh, const bf16* __restrict__ Wl,
      const float* __restrict__ bias, const float* __restrict__ stateIn,
      float* __restrict__ stateOut,
      uint32_t* __restrict__ mx1, int ct1, int off1,
      uint32_t* __restrict__ mx2, int ct2, int off2) {
    extern __shared__ char smc[];
    __shared__ uint32_t mxs[64];
    uint32_t sb = smem_u32(smc);
    const int tid = threadIdx.x, wid = tid >> 5, lane = tid & 31;
    const int r0 = blockIdx.y*128, o0 = blockIdx.x*64;
    const int wm = wid >> 1, wn = wid & 1;
    if (tid < 64) mxs[tid] = 0;
    float acc[2][4][4] = {};

    #define MIX_ISSUE(buf, kt) do { \
        const bf16* Sh_ = (((kt) >> 6) & 1) ? FhB : FhA; \
        const bf16* Sl_ = (((kt) >> 6) & 1) ? FlB : FlA; \
        uint32_t s_ = sb + (buf)*MSTAGE; \
        _Pragma("unroll") \
        for (int it = 0; it < 2; it++) { \
            int v_ = tid + it*256; \
            int row_ = v_ >> 2, kq_ = (v_ & 3)*8; \
            uint32_t off_ = (uint32_t)(row_*(MLDP*2) + kq_*2); \
            size_t g_ = (size_t)(r0+row_)*KP + (kt) + kq_; \
            cp16(s_ + off_, Sh_ + g_); \
            cp16(s_ + MA_B + off_, Sl_ + g_); \
        } \
        { int row_ = tid >> 2, kq_ = (tid & 3)*8; \
          uint32_t off_ = (uint32_t)(row_*(MLDP*2) + kq_*2); \
          size_t g_ = (size_t)(o0+row_)*KP + (kt) + kq_; \
          cp16(s_ + 2*MA_B + off_, Wh + g_); \
          cp16(s_ + 2*MA_B + MB_B + off_, Wl + g_); } \
        CP_COMMIT(); \
    } while (0)

    MIX_ISSUE(0, 0);
    for (int ch = 0; ch < nCh; ch++) {
        if (ch + 1 < nCh) { MIX_ISSUE((ch+1)&1, (ch+1)*32); CP_WAIT(1); }
        else CP_WAIT(0);
        __syncthreads();
        uint32_t Ab = sb + (ch&1)*MSTAGE, Alb = Ab + MA_B, Bb = Ab + 2*MA_B, Blb = Bb + MB_B;
        #pragma unroll
        for (int k16 = 0; k16 < 2; k16++) {
            const int kk = k16*16;
            uint32_t ah[2][4], al[2][4], bh[4][2], bl[4][2];
            #pragma unroll
            for (int im = 0; im < 2; im++) {
                int row = wm*32 + im*16 + (lane & 15);
                int col = kk + ((lane >> 4) << 3);
                uint32_t off = (uint32_t)(row*(MLDP*2) + col*2);
                LDSM4(ah[im], Ab + off);
                LDSM4(al[im], Alb + off);
            }
            #pragma unroll
            for (int in = 0; in < 4; in++) {
                int row = wn*32 + in*8 + (lane & 7);
                int col = kk + (((lane >> 3) & 1) << 3);
                uint32_t off = (uint32_t)(row*(MLDP*2) + col*2);
                LDSM2(bh[in], Bb + off);
                LDSM2(bl[in], Blb + off);
            }
            #pragma unroll
            for (int im = 0; im < 2; im++)
                #pragma unroll
                for (int in = 0; in < 4; in++) MMA16816(acc[im][in], ah[im], bh[in]);
            #pragma unroll
            for (int im = 0; im < 2; im++)
                #pragma unroll
                for (int in = 0; in < 4; in++) MMA16816(acc[im][in], ah[im], bl[in]);
            #pragma unroll
            for (int im = 0; im < 2; im++)
                #pragma unroll
                for (int in = 0; in < 4; in++) MMA16816(acc[im][in], al[im], bh[in]);
        }
        __syncthreads();
    }
    const int r = lane >> 2, cp2 = (lane & 3)*2;
    const int b = r0 >> 10;
    #pragma unroll
    for (int im = 0; im < 2; im++) {
        #pragma unroll
        for (int in = 0; in < 4; in++) {
            int o = o0 + wn*32 + in*8 + cp2;
            float b0 = bias[o], b1 = bias[o+1];
            #pragma unroll
            for (int hh = 0; hh < 2; hh++) {
                int row = r0 + wm*32 + im*16 + r + hh*8;
                float v0 = acc[im][in][hh*2], v1 = acc[im][in][hh*2+1];
                if (MODE == 0) {
                    float gg0 = 1.f/(1.f + expf(-(v0 + b0)));
                    float gg1 = 1.f/(1.f + expf(-(v1 + b1)));
                    if (o < HID) {
                        float w0 = gg0 * stateIn[row*HID + o];
                        float w1 = gg1 * stateIn[row*HID + o+1];
                        g_rstate[row*HID + o]   = w0;
                        g_rstate[row*HID + o+1] = w1;
                        atomicMax(&mxs[o],   __float_as_uint(fabsf(w0)));
                        atomicMax(&mxs[o+1], __float_as_uint(fabsf(w1)));
                    } else {
                        g_u[row*HID + o - HID]     = gg0;
                        g_u[row*HID + o + 1 - HID] = gg1;
                    }
                } else {
                    float hT0 = tanhf(v0 + b0), hT1 = tanhf(v1 + b1);
                    float u0 = g_u[row*HID + o], u1 = g_u[row*HID + o+1];
                    float s0 = stateOut[row*HID + o], s1 = stateOut[row*HID + o+1];
                    float w0 = u0*s0 + (1.f - u0)*hT0;
                    float w1 = u1*s1 + (1.f - u1)*hT1;
                    stateOut[row*HID + o]   = w0;
                    stateOut[row*HID + o+1] = w1;
                    atomicMax(&mxs[o],   __float_as_uint(fabsf(w0)));
                    atomicMax(&mxs[o+1], __float_as_uint(fabsf(w1)));
                }
            }
        }
    }
    __syncthreads();
    if (tid < 64 && blockIdx.x == 0) {
        if (mx1) atomicMax(&mx1[b*ct1 + off1 + tid], mxs[tid]);
        if (mx2) atomicMax(&mx2[b*ct2 + off2 + tid], mxs[tid]);
    }
}

__global__ void projK(const float* __restrict__ Wp, const float* __restrict__ bp,
                      float* __restrict__ out_t,
                      uint32_t* __restrict__ d0, uint32_t* __restrict__ d1) {
    __shared__ uint32_t m0, m1;
    int tid = threadIdx.x;
    if (tid == 0) { m0 = 0; m1 = 0; }
    __syncthreads();
    int row = blockIdx.x*256 + tid;
    const float* s = g_state1 + (size_t)row*HID;
    float a0 = bp[0], a1 = bp[1];
    #pragma unroll
    for (int h = 0; h < HID; h++) { float v = s[h]; a0 += v*Wp[h*2]; a1 += v*Wp[h*2+1]; }
    out_t[row*2] = a0; out_t[row*2+1] = a1;
    g_decin[row*2] = a0; g_decin[row*2+1] = a1;
    atomicMax(&m0, __float_as_uint(fabsf(a0)));
    atomicMax(&m1, __float_as_uint(fabsf(a1)));
    __syncthreads();
    if (tid == 0) {
        int b = blockIdx.x >> 2;
        atomicMax(&d0[b*66 + 64], m0); atomicMax(&d0[b*66 + 65], m1);
        atomicMax(&d1[b*66 + 64], m0); atomicMax(&d1[b*66 + 65], m1);
    }
}

// -------------------------------------------------------------------------
extern "C" void kernel_launch(void* const* d_in, const int* in_sizes, int n_in,
                              void* d_out, int out_size) {
    const float* enc  = (const float*)d_in[0];
    const float* sup  = (const float*)d_in[1];
    const float* Wru0 = (const float*)d_in[2];
    const float* bru0 = (const float*)d_in[3];
    const float* Wh0  = (const float*)d_in[4];
    const float* bh0  = (const float*)d_in[5];
    const float* Wru1 = (const float*)d_in[6];
    const float* bru1 = (const float*)d_in[7];
    const float* Wh1  = (const float*)d_in[8];
    const float* bh1  = (const float*)d_in[9];
    const float* Wp   = (const float*)d_in[10];
    const float* bp   = (const float*)d_in[11];
    float* out = (float*)d_out;

    void *pv;
    cudaGetSymbolAddress(&pv, g_state0); float* pS0  = (float*)pv;
    cudaGetSymbolAddress(&pv, g_state1); float* pS1  = (float*)pv;
    cudaGetSymbolAddress(&pv, g_rstate); float* pRst = (float*)pv;
    cudaGetSymbolAddress(&pv, g_FAh); bf16* FAh = (bf16*)pv;
    cudaGetSymbolAddress(&pv, g_FAl); bf16* FAl = (bf16*)pv;
    cudaGetSymbolAddress(&pv, g_FBh); bf16* FBh = (bf16*)pv;
    cudaGetSymbolAddress(&pv, g_FBl); bf16* FBl = (bf16*)pv;
    cudaGetSymbolAddress(&pv, g_bits); uint32_t* BITS = (uint32_t*)pv;
    cudaGetSymbolAddress(&pv, g_Wru0h); bf16* Wru0h = (bf16*)pv;
    cudaGetSymbolAddress(&pv, g_Wru0l); bf16* Wru0l = (bf16*)pv;
    cudaGetSymbolAddress(&pv, g_Wh0h);  bf16* Wh0h  = (bf16*)pv;
    cudaGetSymbolAddress(&pv, g_Wh0l);  bf16* Wh0l  = (bf16*)pv;
    cudaGetSymbolAddress(&pv, g_Wru1h); bf16* Wru1h = (bf16*)pv;
    cudaGetSymbolAddress(&pv, g_Wru1l); bf16* Wru1l = (bf16*)pv;
    cudaGetSymbolAddress(&pv, g_Wh1h);  bf16* Wh1h  = (bf16*)pv;
    cudaGetSymbolAddress(&pv, g_Wh1l);  bf16* Wh1l  = (bf16*)pv;

    auto BB = [&](int conv, int par) { return BITS + (conv*2 + par)*4096; };

    cudaFuncSetAttribute(mmaDiffuseQ, cudaFuncAttributeMaxDynamicSharedMemorySize, QSMEM);
    cudaFuncSetAttribute(mixTC<0>, cudaFuncAttributeMaxDynamicSharedMemorySize, MIX_SMEM);
    cudaFuncSetAttribute(mixTC<1>, cudaFuncAttributeMaxDynamicSharedMemorySize, MIX_SMEM);

    precomputeM<<<dim3(16,16,2), 256>>>(sup, BITS);
    initK<<<(NROWS*HID + 255)/256, 256>>>(enc, BITS);
    opQuant<<<dim3(NN,4), 256>>>(sup);
    wsplitT<<<(128*352 + 255)/256, 256>>>(Wru0, Wru0h, Wru0l, 66, 128, 352, 1);
    wsplitT<<<(64*352 + 255)/256, 256>>>(Wh0, Wh0h, Wh0l, 66, 64, 352, 1);
    wsplitT<<<(128*640 + 255)/256, 256>>>(Wru1, Wru1h, Wru1l, 128, 128, 640, 0);
    wsplitT<<<(64*640 + 255)/256, 256>>>(Wh1, Wh1h, Wh1l, 128, 64, 640, 0);

    for (int t = 0; t < STEPS; t++) {
        const int p = t & 1, q = p ^ 1;
        // conv0: x=[state0|decin]
        prepDec<<<NROWS/256, 256>>>(FAh, FAl, FBh, FBl, BB(0,p));
        prepK<<<dim3(16,32), 256>>>(pS0, 66, 0, BB(0,p), BB(0,q), 0, 352, FAh, FAl);
        mmaDiffuseQ<<<dim3(33,8,4), 256, QSMEM>>>(66, 2112, FAh, FAl, 66, 352, 0, BB(0,p));
        mixTC<0><<<dim3(2,256), 256, MIX_SMEM>>>(FAh, FAl, FAh, FAl, 352, 11, Wru0h, Wru0l, bru0, pS0, 0,
                                                 BB(1,p), 66, 0, (uint32_t*)0, 0, 0);
        // conv1: x2=[r*state0|decin]
        prepK<<<dim3(16,32), 256>>>(pRst, 66, 0, BB(1,p), BB(1,q), 0, 352, FBh, FBl);
        mmaDiffuseQ<<<dim3(33,8,4), 256, QSMEM>>>(66, 2112, FBh, FBl, 66, 352, 0, BB(1,p));
        mixTC<1><<<dim3(1,256), 256, MIX_SMEM>>>(FBh, FBl, FBh, FBl, 352, 11, Wh0h, Wh0l, bh0, 0, pS0,
                                                 BB(0,q), 66, 0, BB(2,p), 128, 0);
        // conv2: x=[state0|state1]
        prepK<<<dim3(16,32), 256>>>(pS0, 128, 0,  BB(2,p), BB(2,q), 0,  640, FAh, FAl);
        prepK<<<dim3(16,32), 256>>>(pS1, 128, 64, BB(2,p), (uint32_t*)0, 64, 640, FAh, FAl);
        mmaDiffuseQ<<<dim3(64,8,4), 256, QSMEM>>>(128, 4096, FAh, FAl, 128, 640, 0, BB(2,p));
        mixTC<0><<<dim3(2,256), 256, MIX_SMEM>>>(FAh, FAl, FAh, FAl, 640, 20, Wru1h, Wru1l, bru1, pS1, 0,
                                                 BB(3,p), 64, 0, (uint32_t*)0, 0, 0);
        // conv3: diffuse r*state1 only; state0 feats read from FA
        prepK<<<dim3(16,32), 256>>>(pRst, 64, 0, BB(3,p), BB(3,q), 64, 640, FBh, FBl);
        mmaDiffuseQ<<<dim3(32,8,4), 256, QSMEM>>>(64, 2048, FBh, FBl, 128, 640, 64, BB(3,p));
        mixTC<1><<<dim3(1,256), 256, MIX_SMEM>>>(FAh, FAl, FBh, FBl, 640, 20, Wh1h, Wh1l, bh1, 0, pS1,
                                                 BB(2,q), 128, 64, (uint32_t*)0, 0, 0);
        projK<<<NROWS/256, 256>>>(Wp, bp, out + (size_t)t*NROWS*OUTD, BB(0,q), BB(1,q));
    }
}

// round 11
// speedup vs baseline: 4.4869x; 1.0643x over previous
#include <cuda_runtime.h>
#include <cuda_bf16.h>
#include <math.h>
#include <stdint.h>

#define NN 1024
#define BATCH 32
#define HID 64
#define OUTD 2
#define STEPS 12
#define NROWS (BATCH*NN)
typedef __nv_bfloat16 bf16;

// ---------------- PTX helpers ---------------------------------------------
__device__ __forceinline__ uint32_t smem_u32(const void* p) {
    uint32_t a;
    asm("{ .reg .u64 t; cvta.to.shared.u64 t, %1; cvt.u32.u64 %0, t; }" : "=r"(a) : "l"(p));
    return a;
}
__device__ __forceinline__ void cp16(uint32_t sa, const void* g) {
    asm volatile("cp.async.cg.shared.global [%0], [%1], 16;" :: "r"(sa), "l"(g) : "memory");
}
#define CP_COMMIT() asm volatile("cp.async.commit_group;" ::: "memory")
#define CP_WAIT(n)  asm volatile("cp.async.wait_group %0;" :: "n"(n) : "memory")
#define LDSM4(r, a) asm volatile( \
    "ldmatrix.sync.aligned.m8n8.x4.shared.b16 {%0,%1,%2,%3}, [%4];" \
    : "=r"((r)[0]), "=r"((r)[1]), "=r"((r)[2]), "=r"((r)[3]) : "r"(a))
#define MMA16816(d, a, b) asm volatile( \
    "mma.sync.aligned.m16n8k16.row.col.f32.bf16.bf16.f32 " \
    "{%0,%1,%2,%3},{%4,%5,%6,%7},{%8,%9},{%0,%1,%2,%3};" \
    : "+f"((d)[0]), "+f"((d)[1]), "+f"((d)[2]), "+f"((d)[3]) \
    : "r"((a)[0]), "r"((a)[1]), "r"((a)[2]), "r"((a)[3]), "r"((b)[0]), "r"((b)[1]))
#define MMAS8(d, a, b) asm volatile( \
    "mma.sync.aligned.m16n8k32.row.col.s32.s8.s8.s32 " \
    "{%0,%1,%2,%3},{%4,%5,%6,%7},{%8,%9},{%0,%1,%2,%3};" \
    : "+r"((d)[0]), "+r"((d)[1]), "+r"((d)[2]), "+r"((d)[3]) \
    : "r"((a)[0]), "r"((a)[1]), "r"((a)[2]), "r"((a)[3]), "r"((b)[0]), "r"((b)[1]))

__device__ __forceinline__ void bsplit(float v, bf16& h, bf16& l) {
    h = __float2bfloat16(v);
    l = __float2bfloat16(v - __bfloat162float(h));
}
__device__ __forceinline__ uint32_t packbf(bf16 a, bf16 b) {
    __nv_bfloat162 t; t.x = a; t.y = b;
    return *(uint32_t*)&t;
}

// ---------------- scratch -------------------------------------------------
__device__ float g_M[2u*NN*NN];
__device__ float g_state0[NROWS*HID];
__device__ float g_state1[NROWS*HID];
__device__ float g_decin [NROWS*OUTD];
__device__ float g_u     [NROWS*HID];
__device__ float g_rstate[NROWS*HID];
__device__ bf16 g_FAh[(size_t)NROWS*640], g_FAl[(size_t)NROWS*640];
__device__ bf16 g_FBh[(size_t)NROWS*640], g_FBl[(size_t)NROWS*640];
__device__ int8_t g_Aq1[(size_t)4*NN*NN], g_Aq2[(size_t)4*NN*NN];
__device__ int8_t g_Xq1[(size_t)4096*NN], g_Xq2[(size_t)4096*NN];
__device__ float g_sA[4*NN];
__device__ uint32_t g_bits[8*4096];   // [conv 0..3][parity][4096]
__device__ bf16 g_Wru0h[128*352], g_Wru0l[128*352];
__device__ bf16 g_Wh0h [64*352],  g_Wh0l [64*352];
__device__ bf16 g_Wru1h[128*640], g_Wru1l[128*640];
__device__ bf16 g_Wh1h [64*640],  g_Wh1l [64*640];

// ---------------- init (+ initial column maxes) ---------------------------
__global__ void initK(const float* __restrict__ enc, uint32_t* __restrict__ bits) {
    __shared__ uint32_t ms0[64], ms1[64];
    int tid = threadIdx.x;
    if (tid < 64) { ms0[tid] = 0; ms1[tid] = 0; }
    __syncthreads();
    int i = blockIdx.x*256 + tid;
    const int SZ = NROWS*HID;
    if (i < SZ) {
        float s0v = enc[i], s1v = enc[SZ+i];
        g_state0[i] = s0v; g_state1[i] = s1v;
        int c = i & 63;
        atomicMax(&ms0[c], __float_as_uint(fabsf(s0v)));
        atomicMax(&ms1[c], __float_as_uint(fabsf(s1v)));
    }
    if (i < NROWS*OUTD) g_decin[i] = 0.f;
    __syncthreads();
    if (tid < 64 && i < SZ) {
        int b = (blockIdx.x*256) >> 16;
        atomicMax(&bits[(0*2+0)*4096 + b*66 + tid], ms0[tid]);
        atomicMax(&bits[(2*2+0)*4096 + b*128 + 64 + tid], ms1[tid]);
    }
}

__global__ void precomputeM(const float* __restrict__ sup, uint32_t* __restrict__ bits) {
    if (blockIdx.z == 0 && blockIdx.y == 0) {
        int base = (blockIdx.x*256 + threadIdx.x)*8;
        #pragma unroll
        for (int k = 0; k < 8; k++) bits[base + k] = 0;
    }
    const int s = blockIdx.z;
    const float* __restrict__ S = sup + (size_t)s*NN*NN;
    float* __restrict__ Mo = g_M + (size_t)s*NN*NN;
    __shared__ float As[16][64], Bs[16][64];
    const int tid = threadIdx.x, tx = tid & 15, ty = tid >> 4;
    const int n0 = blockIdx.y*64, j0 = blockIdx.x*64;
    const int ar = tid >> 2, aq = (tid & 3)*4, br = tid >> 4, bq = (tid & 15)*4;
    float acc[4][4] = {};
    for (int kt = 0; kt < NN; kt += 16) {
        float4 av = *(const float4*)(S + (size_t)(n0+ar)*NN + kt + aq);
        As[aq][ar]=av.x; As[aq+1][ar]=av.y; As[aq+2][ar]=av.z; As[aq+3][ar]=av.w;
        *(float4*)&Bs[br][bq] = *(const float4*)(S + (size_t)(kt+br)*NN + j0 + bq);
        __syncthreads();
        #pragma unroll
        for (int k = 0; k < 16; k++) {
            float4 a = *(float4*)&As[k][ty*4], b = *(float4*)&Bs[k][tx*4];
            float arr[4]={a.x,a.y,a.z,a.w}, brr[4]={b.x,b.y,b.z,b.w};
            #pragma unroll
            for (int i=0;i<4;i++)
                #pragma unroll
                for (int j=0;j<4;j++) acc[i][j] += arr[i]*brr[j];
        }
        __syncthreads();
    }
    #pragma unroll
    for (int i=0;i<4;i++) { int n=n0+ty*4+i;
        #pragma unroll
        for (int j=0;j<4;j++) { int jc=j0+tx*4+j;
            Mo[(size_t)n*NN+jc] = 2.f*acc[i][j] - (n==jc?1.f:0.f); } }
}

__global__ void opQuant(const float* __restrict__ sup) {
    const int n = blockIdx.x, f = blockIdx.y, tid = threadIdx.x;
    const float* src = (f==0) ? sup : (f==1) ? g_M :
                       (f==2) ? sup + (size_t)NN*NN : g_M + (size_t)NN*NN;
    float4 v = *(const float4*)(src + (size_t)n*NN + tid*4);
    float mx = fmaxf(fmaxf(fabsf(v.x),fabsf(v.y)), fmaxf(fabsf(v.z),fabsf(v.w)));
    #pragma unroll
    for (int o = 16; o; o >>= 1) mx = fmaxf(mx, __shfl_xor_sync(0xffffffffu, mx, o));
    __shared__ float w[8]; __shared__ float sInv;
    if ((tid & 31) == 0) w[tid >> 5] = mx;
    __syncthreads();
    if (tid == 0) {
        float m = w[0];
        #pragma unroll
        for (int i = 1; i < 8; i++) m = fmaxf(m, w[i]);
        g_sA[f*NN + n] = (m > 0.f) ? m/127.f : 1.f;
        sInv = (m > 0.f) ? 127.f/m : 0.f;
    }
    __syncthreads();
    float inv = sInv;
    char4 q1, q2;
    float xs[4] = {v.x*inv, v.y*inv, v.z*inv, v.w*inv};
    int a1[4], a2[4];
    #pragma unroll
    for (int i = 0; i < 4; i++) {
        int q = __float2int_rn(xs[i]);
        q = q > 127 ? 127 : (q < -127 ? -127 : q);
        a1[i] = q;
        int r = __float2int_rn((xs[i] - (float)q)*254.f);
        a2[i] = r > 127 ? 127 : (r < -127 ? -127 : r);
    }
    q1.x=a1[0];q1.y=a1[1];q1.z=a1[2];q1.w=a1[3];
    q2.x=a2[0];q2.y=a2[1];q2.z=a2[2];q2.w=a2[3];
    size_t o = ((size_t)f*NN + n)*NN + tid*4;
    *(char4*)(g_Aq1 + o) = q1;
    *(char4*)(g_Aq2 + o) = q2;
}

// ------- vectorized prep (+ optional fused decin block at x==16) ----------
__global__ void __launch_bounds__(256)
prepK(const float* __restrict__ src, int Ct, int cOff,
      const uint32_t* __restrict__ bitsRead, uint32_t* __restrict__ bitsZero,
      int m0col, int KP, bf16* __restrict__ Fh, bf16* __restrict__ Fl,
      const float* __restrict__ dec, bf16* __restrict__ F2h, bf16* __restrict__ F2l) {
    const int b = blockIdx.y;
    const int tid = threadIdx.x;
    if (dec && blockIdx.x == 16) {
        float m0v = __uint_as_float(bitsRead[b*66 + 64]);
        float m1v = __uint_as_float(bitsRead[b*66 + 65]);
        float rB0 = (m0v > 0.f) ? 127.f/m0v : 0.f;
        float rB1 = (m1v > 0.f) ? 127.f/m1v : 0.f;
        for (int n = tid; n < NN; n += 256) {
            size_t row = (size_t)b*NN + n;
            float v0 = dec[row*2], v1 = dec[row*2+1];
            bf16 h0,l0,h1,l1; bsplit(v0,h0,l0); bsplit(v1,h1,l1);
            uint32_t hv = packbf(h0,h1), lv = packbf(l0,l1);
            size_t o = row*KP + 64;
            *(uint32_t*)(Fh+o) = hv; *(uint32_t*)(Fl+o) = lv;
            *(uint32_t*)(F2h+o) = hv; *(uint32_t*)(F2l+o) = lv;
            #pragma unroll
            for (int c = 0; c < 2; c++) {
                float x = ((c == 0) ? v0 : v1) * ((c == 0) ? rB0 : rB1);
                int a = __float2int_rn(x); a = a > 127 ? 127 : (a < -127 ? -127 : a);
                int r2 = __float2int_rn((x - (float)a)*254.f);
                r2 = r2 > 127 ? 127 : (r2 < -127 ? -127 : r2);
                size_t q = ((size_t)(b*66 + 64 + c))*NN + n;
                g_Xq1[q] = (int8_t)a; g_Xq2[q] = (int8_t)r2;
            }
        }
        return;
    }
    __shared__ float t[64][65];
    __shared__ float scale[64];
    const int n0 = blockIdx.x*64;
    if (bitsZero && blockIdx.x == 0 && tid < 128) bitsZero[b*128 + tid] = 0;
    if (tid < 64) {
        float m = __uint_as_float(bitsRead[b*Ct + cOff + tid]);
        scale[tid] = (m > 0.f) ? 127.f/m : 0.f;
    }
    #pragma unroll
    for (int i = 0; i < 4; i++) {
        int u = tid + i*256;
        int r = u >> 4, c4 = (u & 15)*4;
        float4 v = *(const float4*)(src + ((size_t)(b*NN + n0 + r))*64 + c4);
        t[r][c4] = v.x; t[r][c4+1] = v.y; t[r][c4+2] = v.z; t[r][c4+3] = v.w;
        bf16 h0,l0,h1,l1,h2,l2,h3,l3;
        bsplit(v.x,h0,l0); bsplit(v.y,h1,l1); bsplit(v.z,h2,l2); bsplit(v.w,h3,l3);
        size_t o = ((size_t)(b*NN + n0 + r))*KP + m0col + c4;
        *(uint32_t*)(Fh+o) = packbf(h0,h1); *(uint32_t*)(Fh+o+2) = packbf(h2,h3);
        *(uint32_t*)(Fl+o) = packbf(l0,l1); *(uint32_t*)(Fl+o+2) = packbf(l2,l3);
    }
    __syncthreads();
    #pragma unroll
    for (int i = 0; i < 4; i++) {
        int u = tid + i*256;
        int cw = u >> 4, ng = (u & 15)*4;
        float rB = scale[cw];
        char q1[4], q2[4];
        #pragma unroll
        for (int j = 0; j < 4; j++) {
            float x = t[ng+j][cw] * rB;
            int a = __float2int_rn(x);
            a = a > 127 ? 127 : (a < -127 ? -127 : a);
            int r2 = __float2int_rn((x - (float)a)*254.f);
            r2 = r2 > 127 ? 127 : (r2 < -127 ? -127 : r2);
            q1[j] = (char)a; q2[j] = (char)r2;
        }
        size_t o = ((size_t)(b*Ct + cOff + cw))*NN + n0 + ng;
        *(char4*)(g_Xq1+o) = make_char4(q1[0],q1[1],q1[2],q1[3]);
        *(char4*)(g_Xq2+o) = make_char4(q2[0],q2[1],q2[2],q2[3]);
    }
}

// ---------------- int8 diffusion: merged B ldmatrix, staged epilogue ------
#define QLDP 80
#define QA_B (128*QLDP)
#define QB_B (64*QLDP)
#define QSTAGE (2*QA_B + 2*QB_B)
#define QSMEM (3*QSTAGE)

__global__ void __launch_bounds__(256, 2)
mmaDiffuseQ(int Ct, bf16* __restrict__ Fh, bf16* __restrict__ Fl,
            int Ctot, int KP, int colOff, const uint32_t* __restrict__ bitsRead) {
    extern __shared__ char sm[];
    uint32_t sb = smem_u32(sm);
    const int tid = threadIdx.x, wid = tid >> 5, lane = tid & 31;
    const int f = blockIdx.z, n0 = blockIdx.y*128, j0 = blockIdx.x*64;
    const int8_t* __restrict__ A1 = g_Aq1 + ((size_t)f*NN + n0)*NN;
    const int8_t* __restrict__ A2 = g_Aq2 + ((size_t)f*NN + n0)*NN;
    const int wm = wid >> 1, wn = wid & 1;
    int acch[2][4][4] = {}, accl[2][4][4] = {};

    const int brow = tid >> 2, bkq = (tid & 3)*16;
    const uint32_t boff = (uint32_t)(brow*QLDP + bkq);
    const int jr = j0 + brow;

    #define Q_ISSUE(bufq, kt) do { \
        uint32_t s_ = sb + (bufq)*QSTAGE; \
        _Pragma("unroll") \
        for (int it = 0; it < 2; it++) { \
            int ai_ = tid + it*256; \
            int arow_ = ai_ >> 2, akq_ = (ai_ & 3)*16; \
            uint32_t ao_ = (uint32_t)(arow_*QLDP + akq_); \
            size_t ga_ = (size_t)arow_*NN + (kt) + akq_; \
            cp16(s_ + ao_,        A1 + ga_); \
            cp16(s_ + QA_B + ao_, A2 + ga_); \
        } \
        size_t gb_ = (size_t)jr*NN + (kt) + bkq; \
        cp16(s_ + 2*QA_B + boff,        g_Xq1 + gb_); \
        cp16(s_ + 2*QA_B + QB_B + boff, g_Xq2 + gb_); \
        CP_COMMIT(); \
    } while (0)

    const int bg = lane >> 3;           // fragment group for merged B LDSM4
    const int bkhalf = (bg & 1) << 4;
    const int br8 = lane & 7;

    Q_ISSUE(0, 0);
    Q_ISSUE(1, 64);
    for (int ch = 0; ch < 16; ch++) {
        if (ch < 15) CP_WAIT(1); else CP_WAIT(0);
        __syncthreads();
        if (ch + 2 < 16) Q_ISSUE((ch+2)%3, (ch+2)*64);
        uint32_t Ab = sb + (ch%3)*QSTAGE;
        uint32_t A2b = Ab + QA_B, B1b = Ab + 2*QA_B, B2b = Ab + 2*QA_B + QB_B;
        uint32_t bBaseSel = (bg < 2) ? B1b : B2b;
        #pragma unroll
        for (int kb = 0; kb < 64; kb += 32) {
            uint32_t a1[2][4], a2[2][4], b1[4][2], b2[4][2];
            #pragma unroll
            for (int im = 0; im < 2; im++) {
                int row = wm*32 + im*16 + (lane & 15);
                uint32_t off = (uint32_t)(row*QLDP + kb + ((lane >> 4) << 4));
                LDSM4(a1[im], Ab + off);
                LDSM4(a2[im], A2b + off);
            }
            #pragma unroll
            for (int in = 0; in < 4; in++) {
                int row = wn*32 + in*8 + br8;
                uint32_t rr[4];
                LDSM4(rr, bBaseSel + (uint32_t)(row*QLDP + kb + bkhalf));
                b1[in][0]=rr[0]; b1[in][1]=rr[1]; b2[in][0]=rr[2]; b2[in][1]=rr[3];
            }
            #pragma unroll
            for (int im = 0; im < 2; im++)
                #pragma unroll
                for (int in = 0; in < 4; in++) MMAS8(acch[im][in], a1[im], b1[in]);
            #pragma unroll
            for (int im = 0; im < 2; im++)
                #pragma unroll
                for (int in = 0; in < 4; in++) MMAS8(accl[im][in], a1[im], b2[in]);
            #pragma unroll
            for (int im = 0; im < 2; im++)
                #pragma unroll
                for (int in = 0; in < 4; in++) MMAS8(accl[im][in], a2[im], b1[in]);
        }
        __syncthreads();
    }
    // staged epilogue: scale -> smem tiles -> coalesced global writes
    const int m = f + 1, r = lane >> 2, cp2 = (lane & 3)*2;
    const float INV = 1.f/254.f, IS = 1.f/127.f;
    uint32_t* hT = (uint32_t*)sm;
    uint32_t* lT = hT + 128*33;
    #pragma unroll
    for (int in = 0; in < 4; in++) {
        int jl = wn*32 + in*8 + cp2;
        int jG = j0 + jl;
        float sb0 = __uint_as_float(bitsRead[jG])*IS;
        float sb1 = __uint_as_float(bitsRead[jG + 1])*IS;
        #pragma unroll
        for (int im = 0; im < 2; im++) {
            #pragma unroll
            for (int hh = 0; hh < 2; hh++) {
                int nl = wm*32 + im*16 + r + hh*8;
                float sa = g_sA[f*NN + n0 + nl];
                float v0 = sa*sb0*((float)acch[im][in][hh*2]   + (float)accl[im][in][hh*2]  *INV);
                float v1 = sa*sb1*((float)acch[im][in][hh*2+1] + (float)accl[im][in][hh*2+1]*INV);
                bf16 h0,l0,h1,l1; bsplit(v0,h0,l0); bsplit(v1,h1,l1);
                hT[nl*33 + (jl>>1)] = packbf(h0,h1);
                lT[nl*33 + (jl>>1)] = packbf(l0,l1);
            }
        }
    }
    __syncthreads();
    {
        int jG2 = j0 + lane*2;
        int bL = jG2 / Ct, cL = jG2 - bL*Ct;
        size_t colbase = (size_t)bL*NN*KP + (size_t)m*Ctot + colOff + cL;
        for (int rr2 = wid; rr2 < 128; rr2 += 8) {
            size_t o = colbase + (size_t)(n0 + rr2)*KP;
            *(uint32_t*)(Fh + o) = hT[rr2*33 + lane];
            *(uint32_t*)(Fl + o) = lT[rr2*33 + lane];
        }
    }
}

// ---------------- weight transpose/split (once) ---------------------------
__global__ void wsplitT(const float* __restrict__ W, bf16* __restrict__ Th,
                        bf16* __restrict__ Tl, int Ct, int O, int KP, int remap) {
    int i = blockIdx.x*blockDim.x + threadIdx.x;
    if (i >= O*KP) return;
    int o = i / KP, k = i % KP;
    float v = 0.f;
    if (k < 5*Ct) {
        int m = k / Ct, c = k % Ct;
        int oc = remap ? ((c < 64) ? c + 2 : c - 64) : c;
        v = W[((size_t)m*Ct + oc)*O + o];
    }
    bf16 h, l; bsplit(v, h, l);
    Th[i] = h; Tl[i] = l;
}

// ---------------- mixing + fused GRU + col-max (+ optional fused proj) ----
#define MLDP 40
#define MA_B (128*MLDP*2)
#define MB_B (64*MLDP*2)
#define MSTAGE (2*MA_B + 2*MB_B)
#define MIX_SMEM (2*MSTAGE)

template<int MODE, int PROJ>
__global__ void __launch_bounds__(256)
mixTC(const bf16* __restrict__ FhA, const bf16* __restrict__ FlA,
      const bf16* __restrict__ FhB, const bf16* __restrict__ FlB,
      int KP, int nCh,
      const bf16* __restrict__ Wh, const bf16* __restrict__ Wl,
      const float* __restrict__ bias, const float* __restrict__ stateIn,
      float* __restrict__ stateOut,
      uint32_t* __restrict__ mx1, int ct1, int off1,
      uint32_t* __restrict__ mx2, int ct2, int off2,
      const float* __restrict__ Wp, const float* __restrict__ bp2,
      float* __restrict__ outp, uint32_t* __restrict__ d0, uint32_t* __restrict__ d1) {
    extern __shared__ char smc[];
    __shared__ uint32_t mxs[64];
    __shared__ uint32_t pm[2];
    uint32_t sb = smem_u32(smc);
    const int tid = threadIdx.x, wid = tid >> 5, lane = tid & 31;
    const int r0 = blockIdx.y*128, o0 = blockIdx.x*64;
    const int wm = wid >> 1, wn = wid & 1;
    if (tid < 64) mxs[tid] = 0;
    if (PROJ && tid < 2) pm[tid] = 0;
    float acc[2][4][4] = {};

    #define MIX_ISSUE(buf, kt) do { \
        const bf16* Sh_ = (((kt) >> 6) & 1) ? FhB : FhA; \
        const bf16* Sl_ = (((kt) >> 6) & 1) ? FlB : FlA; \
        uint32_t s_ = sb + (buf)*MSTAGE; \
        _Pragma("unroll") \
        for (int it = 0; it < 2; it++) { \
            int v_ = tid + it*256; \
            int row_ = v_ >> 2, kq_ = (v_ & 3)*8; \
            uint32_t off_ = (uint32_t)(row_*(MLDP*2) + kq_*2); \
            size_t g_ = (size_t)(r0+row_)*KP + (kt) + kq_; \
            cp16(s_ + off_, Sh_ + g_); \
            cp16(s_ + MA_B + off_, Sl_ + g_); \
        } \
        { int row_ = tid >> 2, kq_ = (tid & 3)*8; \
          uint32_t off_ = (uint32_t)(row_*(MLDP*2) + kq_*2); \
          size_t g_ = (size_t)(o0+row_)*KP + (kt) + kq_; \
          cp16(s_ + 2*MA_B + off_, Wh + g_); \
          cp16(s_ + 2*MA_B + MB_B + off_, Wl + g_); } \
        CP_COMMIT(); \
    } while (0)

    const int bg = lane >> 3;
    const int bkh = (bg & 1) << 3;
    const int br8 = lane & 7;

    MIX_ISSUE(0, 0);
    for (int ch = 0; ch < nCh; ch++) {
        if (ch + 1 < nCh) { MIX_ISSUE((ch+1)&1, (ch+1)*32); CP_WAIT(1); }
        else CP_WAIT(0);
        __syncthreads();
        uint32_t Ab = sb + (ch&1)*MSTAGE, Alb = Ab + MA_B, Bb = Ab + 2*MA_B, Blb = Bb + MB_B;
        uint32_t bBaseSel = (bg < 2) ? Bb : Blb;
        #pragma unroll
        for (int k16 = 0; k16 < 2; k16++) {
            const int kk = k16*16;
            uint32_t ah[2][4], al[2][4], bh[4][2], bl[4][2];
            #pragma unroll
            for (int im = 0; im < 2; im++) {
                int row = wm*32 + im*16 + (lane & 15);
                int col = kk + ((lane >> 4) << 3);
                uint32_t off = (uint32_t)(row*(MLDP*2) + col*2);
                LDSM4(ah[im], Ab + off);
                LDSM4(al[im], Alb + off);
            }
            #pragma unroll
            for (int in = 0; in < 4; in++) {
                int row = wn*32 + in*8 + br8;
                uint32_t rr[4];
                LDSM4(rr, bBaseSel + (uint32_t)(row*(MLDP*2) + (kk + bkh)*2));
                bh[in][0]=rr[0]; bh[in][1]=rr[1]; bl[in][0]=rr[2]; bl[in][1]=rr[3];
            }
            #pragma unroll
            for (int im = 0; im < 2; im++)
                #pragma unroll
                for (int in = 0; in < 4; in++) MMA16816(acc[im][in], ah[im], bh[in]);
            #pragma unroll
            for (int im = 0; im < 2; im++)
                #pragma unroll
                for (int in = 0; in < 4; in++) MMA16816(acc[im][in], ah[im], bl[in]);
            #pragma unroll
            for (int im = 0; im < 2; im++)
                #pragma unroll
                for (int in = 0; in < 4; in++) MMA16816(acc[im][in], al[im], bh[in]);
        }
        __syncthreads();
    }
    const int r = lane >> 2, cp2 = (lane & 3)*2;
    const int b = r0 >> 10;
    float* stT = (float*)smc;    // reused pipeline smem for PROJ state tile
    #pragma unroll
    for (int im = 0; im < 2; im++) {
        #pragma unroll
        for (int in = 0; in < 4; in++) {
            int o = o0 + wn*32 + in*8 + cp2;
            float b0 = bias[o], b1 = bias[o+1];
            #pragma unroll
            for (int hh = 0; hh < 2; hh++) {
                int rowL = wm*32 + im*16 + r + hh*8;
                int row = r0 + rowL;
                float v0 = acc[im][in][hh*2], v1 = acc[im][in][hh*2+1];
                if (MODE == 0) {
                    float gg0 = 1.f/(1.f + expf(-(v0 + b0)));
                    float gg1 = 1.f/(1.f + expf(-(v1 + b1)));
                    if (o < HID) {
                        float w0 = gg0 * stateIn[row*HID + o];
                        float w1 = gg1 * stateIn[row*HID + o+1];
                        g_rstate[row*HID + o]   = w0;
                        g_rstate[row*HID + o+1] = w1;
                        atomicMax(&mxs[o],   __float_as_uint(fabsf(w0)));
                        atomicMax(&mxs[o+1], __float_as_uint(fabsf(w1)));
                    } else {
                        g_u[row*HID + o - HID]     = gg0;
                        g_u[row*HID + o + 1 - HID] = gg1;
                    }
                } else {
                    float hT0 = tanhf(v0 + b0), hT1 = tanhf(v1 + b1);
                    float u0 = g_u[row*HID + o], u1 = g_u[row*HID + o+1];
                    float s0 = stateOut[row*HID + o], s1 = stateOut[row*HID + o+1];
                    float w0 = u0*s0 + (1.f - u0)*hT0;
                    float w1 = u1*s1 + (1.f - u1)*hT1;
                    stateOut[row*HID + o]   = w0;
                    stateOut[row*HID + o+1] = w1;
                    atomicMax(&mxs[o],   __float_as_uint(fabsf(w0)));
                    atomicMax(&mxs[o+1], __float_as_uint(fabsf(w1)));
                    if (PROJ) { stT[rowL*65 + o] = w0; stT[rowL*65 + o+1] = w1; }
                }
            }
        }
    }
    __syncthreads();
    if (tid < 64 && blockIdx.x == 0) {
        if (mx1) atomicMax(&mx1[b*ct1 + off1 + tid], mxs[tid]);
        if (mx2) atomicMax(&mx2[b*ct2 + off2 + tid], mxs[tid]);
    }
    if (PROJ) {
        int trow = tid >> 1, od = tid & 1;
        float a = bp2[od];
        #pragma unroll 8
        for (int o = 0; o < 64; o++) a += stT[trow*65 + o]*Wp[o*2 + od];
        int grow = r0 + trow;
        outp[grow*2 + od] = a;
        g_decin[grow*2 + od] = a;
        atomicMax(&pm[od], __float_as_uint(fabsf(a)));
        __syncthreads();
        if (tid < 2) {
            atomicMax(&d0[b*66 + 64 + tid], pm[tid]);
            atomicMax(&d1[b*66 + 64 + tid], pm[tid]);
        }
    }
}

// -------------------------------------------------------------------------
extern "C" void kernel_launch(void* const* d_in, const int* in_sizes, int n_in,
                              void* d_out, int out_size) {
    const float* enc  = (const float*)d_in[0];
    const float* sup  = (const float*)d_in[1];
    const float* Wru0 = (const float*)d_in[2];
    const float* bru0 = (const float*)d_in[3];
    const float* Wh0  = (const float*)d_in[4];
    const float* bh0  = (const float*)d_in[5];
    const float* Wru1 = (const float*)d_in[6];
    const float* bru1 = (const float*)d_in[7];
    const float* Wh1  = (const float*)d_in[8];
    const float* bh1  = (const float*)d_in[9];
    const float* Wp   = (const float*)d_in[10];
    const float* bp   = (const float*)d_in[11];
    float* out = (float*)d_out;

    void *pv;
    cudaGetSymbolAddress(&pv, g_state0); float* pS0  = (float*)pv;
    cudaGetSymbolAddress(&pv, g_state1); float* pS1  = (float*)pv;
    cudaGetSymbolAddress(&pv, g_decin);  float* pDec = (float*)pv;
    cudaGetSymbolAddress(&pv, g_rstate); float* pRst = (float*)pv;
    cudaGetSymbolAddress(&pv, g_FAh); bf16* FAh = (bf16*)pv;
    cudaGetSymbolAddress(&pv, g_FAl); bf16* FAl = (bf16*)pv;
    cudaGetSymbolAddress(&pv, g_FBh); bf16* FBh = (bf16*)pv;
    cudaGetSymbolAddress(&pv, g_FBl); bf16* FBl = (bf16*)pv;
    cudaGetSymbolAddress(&pv, g_bits); uint32_t* BITS = (uint32_t*)pv;
    cudaGetSymbolAddress(&pv, g_Wru0h); bf16* Wru0h = (bf16*)pv;
    cudaGetSymbolAddress(&pv, g_Wru0l); bf16* Wru0l = (bf16*)pv;
    cudaGetSymbolAddress(&pv, g_Wh0h);  bf16* Wh0h  = (bf16*)pv;
    cudaGetSymbolAddress(&pv, g_Wh0l);  bf16* Wh0l  = (bf16*)pv;
    cudaGetSymbolAddress(&pv, g_Wru1h); bf16* Wru1h = (bf16*)pv;
    cudaGetSymbolAddress(&pv, g_Wru1l); bf16* Wru1l = (bf16*)pv;
    cudaGetSymbolAddress(&pv, g_Wh1h);  bf16* Wh1h  = (bf16*)pv;
    cudaGetSymbolAddress(&pv, g_Wh1l);  bf16* Wh1l  = (bf16*)pv;

    auto BB = [&](int conv, int par) { return BITS + (conv*2 + par)*4096; };

    cudaFuncSetAttribute(mmaDiffuseQ, cudaFuncAttributeMaxDynamicSharedMemorySize, QSMEM);
    cudaFuncSetAttribute(mixTC<0,0>, cudaFuncAttributeMaxDynamicSharedMemorySize, MIX_SMEM);
    cudaFuncSetAttribute(mixTC<1,0>, cudaFuncAttributeMaxDynamicSharedMemorySize, MIX_SMEM);
    cudaFuncSetAttribute(mixTC<1,1>, cudaFuncAttributeMaxDynamicSharedMemorySize, MIX_SMEM);

    precomputeM<<<dim3(16,16,2), 256>>>(sup, BITS);
    initK<<<(NROWS*HID + 255)/256, 256>>>(enc, BITS);
    opQuant<<<dim3(NN,4), 256>>>(sup);
    wsplitT<<<(128*352 + 255)/256, 256>>>(Wru0, Wru0h, Wru0l, 66, 128, 352, 1);
    wsplitT<<<(64*352 + 255)/256, 256>>>(Wh0, Wh0h, Wh0l, 66, 64, 352, 1);
    wsplitT<<<(128*640 + 255)/256, 256>>>(Wru1, Wru1h, Wru1l, 128, 128, 640, 0);
    wsplitT<<<(64*640 + 255)/256, 256>>>(Wh1, Wh1h, Wh1l, 128, 64, 640, 0);

    for (int t = 0; t < STEPS; t++) {
        const int p = t & 1, q = p ^ 1;
        // conv0: x=[state0|decin] (decin fused as 17th block column)
        prepK<<<dim3(17,32), 256>>>(pS0, 66, 0, BB(0,p), BB(0,q), 0, 352, FAh, FAl,
                                    pDec, FBh, FBl);
        mmaDiffuseQ<<<dim3(33,8,4), 256, QSMEM>>>(66, FAh, FAl, 66, 352, 0, BB(0,p));
        mixTC<0,0><<<dim3(2,256), 256, MIX_SMEM>>>(FAh, FAl, FAh, FAl, 352, 11,
            Wru0h, Wru0l, bru0, pS0, 0, BB(1,p), 66, 0, (uint32_t*)0, 0, 0,
            0, 0, 0, 0, 0);
        // conv1: x2=[r*state0|decin]
        prepK<<<dim3(16,32), 256>>>(pRst, 66, 0, BB(1,p), BB(1,q), 0, 352, FBh, FBl,
                                    0, 0, 0);
        mmaDiffuseQ<<<dim3(33,8,4), 256, QSMEM>>>(66, FBh, FBl, 66, 352, 0, BB(1,p));
        mixTC<1,0><<<dim3(1,256), 256, MIX_SMEM>>>(FBh, FBl, FBh, FBl, 352, 11,
            Wh0h, Wh0l, bh0, 0, pS0, BB(0,q), 66, 0, BB(2,p), 128, 0,
            0, 0, 0, 0, 0);
        // conv2: x=[state0|state1]
        prepK<<<dim3(16,32), 256>>>(pS0, 128, 0,  BB(2,p), BB(2,q), 0,  640, FAh, FAl, 0,0,0);
        prepK<<<dim3(16,32), 256>>>(pS1, 128, 64, BB(2,p), (uint32_t*)0, 64, 640, FAh, FAl, 0,0,0);
        mmaDiffuseQ<<<dim3(64,8,4), 256, QSMEM>>>(128, FAh, FAl, 128, 640, 0, BB(2,p));
        mixTC<0,0><<<dim3(2,256), 256, MIX_SMEM>>>(FAh, FAl, FAh, FAl, 640, 20,
            Wru1h, Wru1l, bru1, pS1, 0, BB(3,p), 64, 0, (uint32_t*)0, 0, 0,
            0, 0, 0, 0, 0);
        // conv3: diffuse r*state1 only; state0 feats read from FA; proj fused
        prepK<<<dim3(16,32), 256>>>(pRst, 64, 0, BB(3,p), BB(3,q), 64, 640, FBh, FBl, 0,0,0);
        mmaDiffuseQ<<<dim3(32,8,4), 256, QSMEM>>>(64, FBh, FBl, 128, 640, 64, BB(3,p));
        mixTC<1,1><<<dim3(1,256), 256, MIX_SMEM>>>(FAh, FAl, FBh, FBl, 640, 20,
            Wh1h, Wh1l, bh1, 0, pS1, BB(2,q), 128, 64, (uint32_t*)0, 0, 0,
            Wp, bp, out + (size_t)t*NROWS*OUTD, BB(0,q), BB(1,q));
    }
}